// round 10
// baseline (speedup 1.0000x reference)
#include <cuda_runtime.h>
#include <cuda_bf16.h>
#include <math.h>

#define NN   20000        // nodes
#define NE   320000       // edges (without self loops)
#define ETOT (NE + NN)    // edges + self loops
#define NGR  256          // graphs
#define FD   11           // node feature dim
#define FT   30           // tda feature dim
#define DH   128          // hidden
#define NH   4            // heads
#define NL   3            // layers
#define NT   6            // tasks

#define APAD 40           // A smem row length (32 k + 8 pad) in bf16
#define BPAD 136          // B smem row length (128 n + 8 pad) in bf16

// ---------------- device scratch (static, no allocations) ----------------
// Referenced ONLY inside kernels — never passed as kernel arguments.
__device__ float         g_h[NN * DH];            // node features (in-place updated)
__device__ __nv_bfloat16 g_agg_hi[NN * 512];      // aggregated features bf16 hi [N, 4*128]
__device__ __nv_bfloat16 g_agg_lo[NN * 512];      // aggregated features bf16 lo
__device__ __nv_bfloat16 g_wstk_hi[NL * 512 * DH];// stacked (W_h/4) bf16 hi [l][h*128+kd][d]
__device__ __nv_bfloat16 g_wstk_lo[NL * 512 * DH];
__device__ float         g_vs[NL * NH * DH];      // projected a_src vectors [l][h][k]
__device__ float         g_vd[NL * NH * DH];      // projected a_dst vectors
__device__ float         g_as[NN * NH];           // alpha_src per node/head
__device__ float         g_ad[NN * NH];           // alpha_dst per node/head
__device__ int           g_rowptr[NN + 1];
__device__ int           g_cnt[NN];               // counts, then scatter cursor
__device__ int           g_esrc[ETOT];            // src ids sorted by dst
__device__ int           g_gstart[NGR + 1];

// ---------------- bf16 mma helpers ----------------
__device__ __forceinline__ void mma_bf16(float c[4], const unsigned a[4], const unsigned* b) {
    asm volatile(
        "mma.sync.aligned.m16n8k16.row.col.f32.bf16.bf16.f32 "
        "{%0,%1,%2,%3}, {%4,%5,%6,%7}, {%8,%9}, {%0,%1,%2,%3};\n"
        : "+f"(c[0]), "+f"(c[1]), "+f"(c[2]), "+f"(c[3])
        : "r"(a[0]), "r"(a[1]), "r"(a[2]), "r"(a[3]), "r"(b[0]), "r"(b[1]));
}

__device__ __forceinline__ void ldsm_x4(unsigned r[4], unsigned saddr) {
    asm volatile("ldmatrix.sync.aligned.m8n8.x4.shared.b16 {%0,%1,%2,%3}, [%4];"
        : "=r"(r[0]), "=r"(r[1]), "=r"(r[2]), "=r"(r[3]) : "r"(saddr));
}

__device__ __forceinline__ void ldsm_x4_t(unsigned r[4], unsigned saddr) {
    asm volatile("ldmatrix.sync.aligned.m8n8.x4.trans.shared.b16 {%0,%1,%2,%3}, [%4];"
        : "=r"(r[0]), "=r"(r[1]), "=r"(r[2]), "=r"(r[3]) : "r"(saddr));
}

// ---------------- fused pre-pass ----------------
// segments: inproj (2 nodes/block) | Wstack split | alpha-projection vectors | CSR prep
#define PRE_INPROJ_BLOCKS (NN / 2)                        // 10000
#define PRE_WSTK_BLOCKS   ((NL * 512 * DH + 255) / 256)   // 768
#define PRE_V_BLOCKS      ((NL * NH * DH * 2 + 255) / 256)// 12
#define PRE_PREP_BLOCKS   ((NN + 256) / 256)              // 79
#define PRE_TOTAL_BLOCKS  (PRE_INPROJ_BLOCKS + PRE_WSTK_BLOCKS + PRE_V_BLOCKS + PRE_PREP_BLOCKS)

__global__ __launch_bounds__(256) void k_pre(const float* __restrict__ x,
                                             const float* __restrict__ w,
                                             const float* __restrict__ b,
                                             const float* __restrict__ wg,
                                             const float* __restrict__ a_src,
                                             const float* __restrict__ a_dst,
                                             const int* __restrict__ batch) {
    int bid = blockIdx.x;
    if (bid < PRE_INPROJ_BLOCKS) {
        int local = threadIdx.x >> 7;     // 0/1
        int d = threadIdx.x & 127;
        int n = bid * 2 + local;
        __shared__ float xs[2][FD];
        if (d < FD) xs[local][d] = x[n * FD + d];
        __syncthreads();
        float a = b[d];
#pragma unroll
        for (int k = 0; k < FD; k++) a += xs[local][k] * w[k * DH + d];
        g_h[n * DH + d] = fmaxf(a, 0.f);
    } else if (bid < PRE_INPROJ_BLOCKS + PRE_WSTK_BLOCKS) {
        int i = (bid - PRE_INPROJ_BLOCKS) * 256 + threadIdx.x;
        if (i < NL * 512 * DH) {
            int l = i >> 16;             // 512*128 = 65536
            int r = (i >> 7) & 511;      // stacked row = h*128 + kd
            int d = i & 127;
            int h = r >> 7, kd = r & 127;
            float v = 0.25f * wg[l * 65536 + kd * 512 + h * 128 + d];
            __nv_bfloat16 hi = __float2bfloat16_rn(v);
            g_wstk_hi[i] = hi;
            g_wstk_lo[i] = __float2bfloat16_rn(v - __bfloat162float(hi));
        }
    } else if (bid < PRE_INPROJ_BLOCKS + PRE_WSTK_BLOCKS + PRE_V_BLOCKS) {
        int i = (bid - PRE_INPROJ_BLOCKS - PRE_WSTK_BLOCKS) * 256 + threadIdx.x;
        int half = (i >= NL * NH * DH);
        int j = half ? i - NL * NH * DH : i;
        if (j < NL * NH * DH) {
            int l = j >> 9;              // NH*DH = 512
            int rem = j & 511;
            int h = rem >> 7, k = rem & 127;
            const float* av = half ? a_dst : a_src;
            float s = 0.f;
#pragma unroll 4
            for (int d = 0; d < 128; d++)
                s += wg[l * 65536 + k * 512 + h * 128 + d] * av[l * 512 + h * 128 + d];
            if (half) g_vd[j] = s; else g_vs[j] = s;
        }
    } else {
        int i = (bid - PRE_INPROJ_BLOCKS - PRE_WSTK_BLOCKS - PRE_V_BLOCKS) * 256 + threadIdx.x;
        if (i < NN) g_cnt[i] = 0;
        if (i <= NN) {
            int bb = (i < NN) ? batch[i] : NGR;
            int bp = (i > 0) ? batch[i - 1] : -1;
            for (int g = bp + 1; g <= bb && g <= NGR; g++) g_gstart[g] = i;
        }
    }
}

// ---------------- CSR build ----------------
__global__ void k_count(const int* __restrict__ ei) {
    int i = blockIdx.x * blockDim.x + threadIdx.x;
    if (i >= ETOT) return;
    int dst = (i < NE) ? ei[NE + i] : (i - NE);
    atomicAdd(&g_cnt[dst], 1);
}

__global__ void k_scan() {   // single block, 1024 threads, chunk=20; also writes cursor
    __shared__ int ssum[1024];
    const int CH = 20;
    int tid = threadIdx.x;
    int base = tid * CH;
    int s = 0;
    for (int j = 0; j < CH; j++) {
        int idx = base + j;
        if (idx < NN) s += g_cnt[idx];
    }
    ssum[tid] = s;
    __syncthreads();
    for (int off = 1; off < 1024; off <<= 1) {
        int v = 0;
        if (tid >= off) v = ssum[tid - off];
        __syncthreads();
        ssum[tid] += v;
        __syncthreads();
    }
    int run = tid ? ssum[tid - 1] : 0;
    for (int j = 0; j < CH; j++) {
        int idx = base + j;
        if (idx < NN) {
            int c = g_cnt[idx];
            g_rowptr[idx] = run;
            g_cnt[idx]    = run;   // scatter cursor
            run += c;
        }
    }
    if (tid == 1023) g_rowptr[NN] = ssum[1023];
}

__global__ void k_scatter(const int* __restrict__ ei) {
    int i = blockIdx.x * blockDim.x + threadIdx.x;
    if (i >= ETOT) return;
    int src, dst;
    if (i < NE) { src = ei[i]; dst = ei[NE + i]; }
    else        { src = i - NE; dst = i - NE; }
    int pos = atomicAdd(&g_cnt[dst], 1);
    g_esrc[pos] = src;
}

// ---------------- alpha logits: g_as/g_ad[n,h] = h[n] . v_{s,d}[layer,h] ----------------
// grid 157 x 256 threads: 128 rows/block, 2 threads/row (64 dims each)
__global__ __launch_bounds__(256) void k_alpha(int layer) {
    __shared__ float svs[512], svd[512];
    int tid = threadIdx.x;
    // stage v vectors
    for (int i = tid; i < 512; i += 256) {
        svs[i] = g_vs[layer * 512 + i];
        svd[i] = g_vd[layer * 512 + i];
    }
    __syncthreads();
    int n = blockIdx.x * 128 + (tid >> 1);
    if (n >= NN) return;
    int half = tid & 1;
    const float* hr = &g_h[n * DH + half * 64];
    float p[8] = {0.f, 0.f, 0.f, 0.f, 0.f, 0.f, 0.f, 0.f};
    for (int j = 0; j < 64; j++) {
        float hv = hr[j];
        int d = half * 64 + j;
#pragma unroll
        for (int h = 0; h < 4; h++) {
            p[h]     += hv * svs[h * 128 + d];
            p[4 + h] += hv * svd[h * 128 + d];
        }
    }
#pragma unroll
    for (int i = 0; i < 8; i++) p[i] += __shfl_xor_sync(0xffffffffu, p[i], 1);
    if (half == 0) {
#pragma unroll
        for (int h = 0; h < 4; h++) {
            g_as[n * 4 + h] = p[h];
            g_ad[n * 4 + h] = p[4 + h];
        }
    }
}

// ---------------- GAT aggregation in input space ----------------
// block per node, 128 threads; thread = dim; 4 head accumulators over h[src].
__global__ __launch_bounds__(128) void k_agg() {
    int node = blockIdx.x, tid = threadIdx.x;
    int h = tid >> 5, lane = tid & 31;
    __shared__ float sm[4], ss[4], sad[4];
    __shared__ int   ssrc[32];
    __shared__ alignas(16) float swt[32][4];
    if (tid < 4) sad[tid] = g_ad[node * 4 + tid];
    int beg = g_rowptr[node], end = g_rowptr[node + 1];
    __syncthreads();

    // pass 1: per-head online softmax stats (warp per head)
    float adh = sad[h];
    float m = -1e30f, s = 0.f;
    for (int e = beg + lane; e < end; e += 32) {
        int src = g_esrc[e];
        float x = g_as[src * 4 + h] + adh;
        x = x > 0.f ? x : 0.2f * x;
        float nm = fmaxf(m, x);
        s = s * __expf(m - nm) + __expf(x - nm);
        m = nm;
    }
#pragma unroll
    for (int off = 16; off > 0; off >>= 1) {
        float mo = __shfl_xor_sync(0xffffffffu, m, off);
        float so = __shfl_xor_sync(0xffffffffu, s, off);
        float nm = fmaxf(m, mo);
        s = s * __expf(m - nm) + so * __expf(mo - nm);
        m = nm;
    }
    if (lane == 0) { sm[h] = m; ss[h] = 1.f / s; }
    __syncthreads();

    // pass 2: gather h[src] once per edge, 4 head-weighted accumulators
    float a0 = 0.f, a1 = 0.f, a2 = 0.f, a3 = 0.f;
    for (int base = beg; base < end; base += 32) {
        int cnt = end - base; if (cnt > 32) cnt = 32;
        if (tid < cnt * 4) {
            int e  = base + (tid >> 2);
            int hd = tid & 3;
            int src = g_esrc[e];
            float x = g_as[src * 4 + hd] + sad[hd];
            x = x > 0.f ? x : 0.2f * x;
            swt[tid >> 2][hd] = __expf(x - sm[hd]) * ss[hd];
            if (hd == 0) ssrc[tid >> 2] = src;
        }
        __syncthreads();
        for (int j = 0; j < cnt; j++) {
            float4 wv = *(const float4*)swt[j];
            float hv = g_h[ssrc[j] * DH + tid];
            a0 += wv.x * hv;
            a1 += wv.y * hv;
            a2 += wv.z * hv;
            a3 += wv.w * hv;
        }
        __syncthreads();
    }

    // store bf16 split of agg [node][h*128 + d]
    int ob = node * 512 + tid;
#pragma unroll
    for (int hh = 0; hh < 4; hh++) {
        float v = (hh == 0) ? a0 : (hh == 1) ? a1 : (hh == 2) ? a2 : a3;
        __nv_bfloat16 hi = __float2bfloat16_rn(v);
        g_agg_hi[ob + hh * 128] = hi;
        g_agg_lo[ob + hh * 128] = __float2bfloat16_rn(v - __bfloat162float(hi));
    }
}

// ---------------- post-GEMM: h_new = relu(LN(agg @ Wstack + bias)) + h_old ----------------
// grid 157, 256 threads = 8 warps (4m x 2n). A=[N,512] agg bf16 split, B=[512,128] Wstack.
__global__ __launch_bounds__(256, 2) void k_gemm2(int layer,
                                                  const float* __restrict__ bg,
                                                  const float* __restrict__ lnw,
                                                  const float* __restrict__ lnb) {
    __shared__ alignas(16) __nv_bfloat16 As_h[128][APAD], As_l[128][APAD];   // [m][k]
    __shared__ alignas(16) __nv_bfloat16 Bs_h[32][BPAD],  Bs_l[32][BPAD];    // [k][n]
    __shared__ float rsum[2][128], rsq[2][128];
    __shared__ float s_bg[128], s_lnw[128], s_lnb[128];

    int tid = threadIdx.x;
    int wid = tid >> 5, lane = tid & 31;
    int warp_m = wid & 3, warp_n = wid >> 2;
    int m0 = blockIdx.x * 128;
    int g  = lane >> 2, t = lane & 3;
    const __nv_bfloat16* Bh = g_wstk_hi + layer * 512 * DH;
    const __nv_bfloat16* Bl = g_wstk_lo + layer * 512 * DH;

    if (tid < 128) { s_bg[tid] = bg[tid]; s_lnw[tid] = lnw[tid]; s_lnb[tid] = lnb[tid]; }

    float c[2][8][4];
#pragma unroll
    for (int mt = 0; mt < 2; mt++)
#pragma unroll
        for (int nt = 0; nt < 8; nt++)
#pragma unroll
            for (int i = 0; i < 4; i++) c[mt][nt][i] = 0.f;

    int ar  = tid >> 1, akg = (tid & 1) * 16;    // A: 32 k per row, 16 per thread
    int bkr = tid >> 3, bcg = (tid & 7) * 16;    // B: 128 n per row, 16 per thread

    int lrow = (lane & 7) + ((lane >> 3) & 1) * 8;
    int lcol = (lane >> 4) * 8;
    unsigned sAh = (unsigned)__cvta_generic_to_shared(As_h);
    unsigned sAl = (unsigned)__cvta_generic_to_shared(As_l);
    unsigned sBh = (unsigned)__cvta_generic_to_shared(Bs_h);
    unsigned sBl = (unsigned)__cvta_generic_to_shared(Bs_l);

    for (int kc = 0; kc < 512; kc += 32) {
        __syncthreads();
        {
            bool ok = (m0 + ar < NN);
            uint4 z = make_uint4(0u, 0u, 0u, 0u);
            const uint4* ph = (const uint4*)&g_agg_hi[(m0 + ar) * 512 + kc + akg];
            const uint4* pl = (const uint4*)&g_agg_lo[(m0 + ar) * 512 + kc + akg];
            uint4 h0 = ok ? ph[0] : z, h1 = ok ? ph[1] : z;
            uint4 l0 = ok ? pl[0] : z, l1 = ok ? pl[1] : z;
            *(uint4*)&As_h[ar][akg]     = h0;
            *(uint4*)&As_h[ar][akg + 8] = h1;
            *(uint4*)&As_l[ar][akg]     = l0;
            *(uint4*)&As_l[ar][akg + 8] = l1;
        }
        {
            const uint4* ph = (const uint4*)&Bh[(kc + bkr) * 128 + bcg];
            const uint4* pl = (const uint4*)&Bl[(kc + bkr) * 128 + bcg];
            uint4 h0 = ph[0], h1 = ph[1];
            uint4 l0 = pl[0], l1 = pl[1];
            *(uint4*)&Bs_h[bkr][bcg]     = h0;
            *(uint4*)&Bs_h[bkr][bcg + 8] = h1;
            *(uint4*)&Bs_l[bkr][bcg]     = l0;
            *(uint4*)&Bs_l[bkr][bcg + 8] = l1;
        }
        __syncthreads();

#pragma unroll
        for (int kk = 0; kk < 32; kk += 16) {
            unsigned ah[2][4], al[2][4];
#pragma unroll
            for (int mt = 0; mt < 2; mt++) {
                unsigned off = (unsigned)(((warp_m * 32 + mt * 16 + lrow) * APAD + kk + lcol) * 2);
                ldsm_x4(ah[mt], sAh + off);
                ldsm_x4(al[mt], sAl + off);
            }
#pragma unroll
            for (int p = 0; p < 4; p++) {
                unsigned boff = (unsigned)(((kk + lrow) * BPAD + warp_n * 64 + p * 16 + lcol) * 2);
                unsigned bh[4], bl[4];
                ldsm_x4_t(bh, sBh + boff);
                ldsm_x4_t(bl, sBl + boff);
#pragma unroll
                for (int q = 0; q < 2; q++) {
#pragma unroll
                    for (int mt = 0; mt < 2; mt++) {
                        float* cc = c[mt][p * 2 + q];
                        mma_bf16(cc, ah[mt], &bh[q * 2]);
                        mma_bf16(cc, ah[mt], &bl[q * 2]);
                        mma_bf16(cc, al[mt], &bh[q * 2]);
                    }
                }
            }
        }
    }
    __syncthreads();

    // epilogue: add bias, per-row LN stats, normalize, relu, residual, write g_h
#pragma unroll
    for (int mt = 0; mt < 2; mt++)
#pragma unroll
        for (int nt = 0; nt < 8; nt++) {
            int col = warp_n * 64 + nt * 8 + t * 2;
            c[mt][nt][0] += s_bg[col];
            c[mt][nt][1] += s_bg[col + 1];
            c[mt][nt][2] += s_bg[col];
            c[mt][nt][3] += s_bg[col + 1];
        }

    float sum[4] = {0.f, 0.f, 0.f, 0.f}, sq[4] = {0.f, 0.f, 0.f, 0.f};
#pragma unroll
    for (int mt = 0; mt < 2; mt++)
#pragma unroll
        for (int nt = 0; nt < 8; nt++) {
            float c0 = c[mt][nt][0], c1 = c[mt][nt][1];
            float c2 = c[mt][nt][2], c3 = c[mt][nt][3];
            sum[mt * 2 + 0] += c0 + c1;  sq[mt * 2 + 0] += c0 * c0 + c1 * c1;
            sum[mt * 2 + 1] += c2 + c3;  sq[mt * 2 + 1] += c2 * c2 + c3 * c3;
        }
#pragma unroll
    for (int off = 1; off <= 2; off <<= 1)
#pragma unroll
        for (int i = 0; i < 4; i++) {
            sum[i] += __shfl_xor_sync(0xffffffffu, sum[i], off);
            sq[i]  += __shfl_xor_sync(0xffffffffu, sq[i],  off);
        }
    if (t == 0) {
#pragma unroll
        for (int mt = 0; mt < 2; mt++)
#pragma unroll
            for (int hf = 0; hf < 2; hf++) {
                int row = warp_m * 32 + mt * 16 + hf * 8 + g;
                rsum[warp_n][row] = sum[mt * 2 + hf];
                rsq[warp_n][row]  = sq[mt * 2 + hf];
            }
    }
    __syncthreads();

#pragma unroll
    for (int mt = 0; mt < 2; mt++) {
        int row0 = warp_m * 32 + mt * 16 + g;
#pragma unroll
        for (int hf = 0; hf < 2; hf++) {
            int row = row0 + hf * 8;
            int grow = m0 + row;
            if (grow >= NN) continue;
            float S = rsum[0][row] + rsum[1][row];
            float Q = rsq[0][row] + rsq[1][row];
            float mu  = S * (1.f / 128.f);
            float var = Q * (1.f / 128.f) - mu * mu;
            float rstd = rsqrtf(var + 1e-5f);
#pragma unroll
            for (int nt = 0; nt < 8; nt++) {
                int col = warp_n * 64 + nt * 8 + t * 2;
                float c0 = c[mt][nt][hf * 2 + 0];
                float c1 = c[mt][nt][hf * 2 + 1];
                float2 hold = *(const float2*)&g_h[grow * DH + col];
                float v0 = (c0 - mu) * rstd * s_lnw[col]     + s_lnb[col];
                float v1 = (c1 - mu) * rstd * s_lnw[col + 1] + s_lnb[col + 1];
                float2 nv = make_float2(fmaxf(v0, 0.f) + hold.x, fmaxf(v1, 0.f) + hold.y);
                *(float2*)&g_h[grow * DH + col] = nv;
            }
        }
    }
}

// ---------------- pooling + TDA + trunk + task heads (fully fused) ----------------
__global__ __launch_bounds__(256) void k_head(const float* __restrict__ tda,
                                              const float* __restrict__ wt1, const float* __restrict__ bt1,
                                              const float* __restrict__ wt2, const float* __restrict__ bt2,
                                              const float* __restrict__ wsh1, const float* __restrict__ bsh1,
                                              const float* __restrict__ wsh2, const float* __restrict__ bsh2,
                                              const float* __restrict__ wh1,  const float* __restrict__ bh1,
                                              const float* __restrict__ wh2,  const float* __restrict__ bh2,
                                              float* __restrict__ out) {
    int g = blockIdx.x, tid = threadIdx.x;
    __shared__ float comb[320], s1[256], s2[128], hh1[NT * 64], th1[64];

    int beg = g_gstart[g], end = g_gstart[g + 1];
    int cntn = end - beg;
    {
        int d = tid & 127;
        if (tid < 128) {
            float s = 0.f;
            for (int i = beg; i < end; i++) s += g_h[i * DH + d];
            comb[d] = s / (float)(cntn > 0 ? cntn : 1);
        } else {
            float mx = -1e30f;
            for (int i = beg; i < end; i++) mx = fmaxf(mx, g_h[i * DH + d]);
            comb[128 + d] = (cntn > 0) ? mx : 0.f;
        }
    }
    __syncthreads();
    if (tid < 64) {
        float a = bt1[tid];
#pragma unroll
        for (int k = 0; k < FT; k++) a += tda[g * FT + k] * wt1[k * 64 + tid];
        th1[tid] = fmaxf(a, 0.f);
    }
    __syncthreads();
    if (tid < 64) {
        float c = bt2[tid];
#pragma unroll
        for (int k = 0; k < 64; k++) c += th1[k] * wt2[k * 64 + tid];
        comb[256 + tid] = fmaxf(c, 0.f);
    }
    __syncthreads();
    float a = bsh1[tid];
    for (int k = 0; k < 320; k++) a += comb[k] * wsh1[k * 256 + tid];
    s1[tid] = fmaxf(a, 0.f);
    __syncthreads();
    if (tid < 128) {
        float c = bsh2[tid];
        for (int k = 0; k < 256; k++) c += s1[k] * wsh2[k * 128 + tid];
        s2[tid] = fmaxf(c, 0.f);
    }
    __syncthreads();
    for (int idx = tid; idx < NT * 64; idx += 256) {
        int t = idx >> 6, kk = idx & 63;
        float c = bh1[t * 64 + kk];
        for (int k = 0; k < 128; k++) c += s2[k] * wh1[t * 8192 + k * 64 + kk];
        hh1[idx] = fmaxf(c, 0.f);
    }
    __syncthreads();
    if (tid < NT) {
        float c = bh2[tid];
        for (int k = 0; k < 64; k++) c += hh1[tid * 64 + k] * wh2[tid * 64 + k];
        out[tid * NGR + g] = c;
    }
}

// ---------------- launch ----------------
extern "C" void kernel_launch(void* const* d_in, const int* in_sizes, int n_in,
                              void* d_out, int out_size) {
    const float* x       = (const float*)d_in[0];
    const int*   ei      = (const int*)d_in[1];
    const int*   batch   = (const int*)d_in[2];
    const float* tda     = (const float*)d_in[3];
    const float* w_in    = (const float*)d_in[4];
    const float* b_in    = (const float*)d_in[5];
    const float* w_gat   = (const float*)d_in[6];
    const float* a_src   = (const float*)d_in[7];
    const float* a_dst   = (const float*)d_in[8];
    const float* b_gat   = (const float*)d_in[9];
    const float* ln_w    = (const float*)d_in[10];
    const float* ln_b    = (const float*)d_in[11];
    const float* w_tda1  = (const float*)d_in[12];
    const float* b_tda1  = (const float*)d_in[13];
    const float* w_tda2  = (const float*)d_in[14];
    const float* b_tda2  = (const float*)d_in[15];
    const float* w_sh1   = (const float*)d_in[16];
    const float* b_sh1   = (const float*)d_in[17];
    const float* w_sh2   = (const float*)d_in[18];
    const float* b_sh2   = (const float*)d_in[19];
    const float* w_h1    = (const float*)d_in[20];
    const float* b_h1    = (const float*)d_in[21];
    const float* w_h2    = (const float*)d_in[22];
    const float* b_h2    = (const float*)d_in[23];
    float* out = (float*)d_out;

    const int GEMM_GRID = (NN + 127) / 128;   // 157

    k_pre<<<PRE_TOTAL_BLOCKS, 256>>>(x, w_in, b_in, w_gat, a_src, a_dst, batch);  // 0
    k_count<<<(ETOT + 255) / 256, 256>>>(ei);                                     // 1
    k_scan<<<1, 1024>>>();                                                        // 2
    k_alpha<<<GEMM_GRID, 256>>>(0);                                               // 3
    k_scatter<<<(ETOT + 255) / 256, 256>>>(ei);                                   // 4

    for (int l = 0; l < NL; l++) {
        k_agg<<<NN, 128>>>();
        k_gemm2<<<GEMM_GRID, 256>>>(l, b_gat + l * 128, ln_w + l * 128, ln_b + l * 128);
        if (l + 1 < NL) k_alpha<<<GEMM_GRID, 256>>>(l + 1);
    }

    k_head<<<NGR, 256>>>(tda, w_tda1, b_tda1, w_tda2, b_tda2,
                         w_sh1, b_sh1, w_sh2, b_sh2, w_h1, b_h1, w_h2, b_h2, out);
}

// round 11
// speedup vs baseline: 1.0570x; 1.0570x over previous
#include <cuda_runtime.h>
#include <cuda_bf16.h>
#include <math.h>

#define NN   20000        // nodes
#define NE   320000       // edges (without self loops)
#define ETOT (NE + NN)    // edges + self loops
#define NGR  256          // graphs
#define FD   11           // node feature dim
#define FT   30           // tda feature dim
#define DH   128          // hidden
#define NH   4            // heads
#define NL   3            // layers
#define NT   6            // tasks

#define APAD 40           // A smem row length (32 k + 8 pad) in bf16
#define BPAD 136          // B smem row length (128 n + 8 pad) in bf16

// ---------------- device scratch (static, no allocations) ----------------
// Referenced ONLY inside kernels — never passed as kernel arguments.
__device__ float         g_h[NN * DH];            // node features (in-place updated)
__device__ __nv_bfloat16 g_agg_hi[NN * 512];      // aggregated features bf16 hi [N, 4*128]
__device__ __nv_bfloat16 g_agg_lo[NN * 512];      // aggregated features bf16 lo
__device__ __nv_bfloat16 g_wstk_hi[NL * 512 * DH];// stacked (W_h/4) bf16 hi [l][h*128+kd][d]
__device__ __nv_bfloat16 g_wstk_lo[NL * 512 * DH];
__device__ float         g_vs[NL * NH * DH];      // projected a_src vectors [l][h][k]
__device__ float         g_vd[NL * NH * DH];      // projected a_dst vectors
__device__ float         g_as[NN * NH];           // alpha_src per node/head
__device__ float         g_ad[NN * NH];           // alpha_dst per node/head
__device__ int           g_rowptr[NN + 1];
__device__ int           g_cnt[NN];               // counts, then scatter cursor
__device__ int           g_esrc[ETOT];            // src ids sorted by dst
__device__ int           g_gstart[NGR + 1];

// ---------------- bf16 mma helpers ----------------
__device__ __forceinline__ void mma_bf16(float c[4], const unsigned a[4], const unsigned* b) {
    asm volatile(
        "mma.sync.aligned.m16n8k16.row.col.f32.bf16.bf16.f32 "
        "{%0,%1,%2,%3}, {%4,%5,%6,%7}, {%8,%9}, {%0,%1,%2,%3};\n"
        : "+f"(c[0]), "+f"(c[1]), "+f"(c[2]), "+f"(c[3])
        : "r"(a[0]), "r"(a[1]), "r"(a[2]), "r"(a[3]), "r"(b[0]), "r"(b[1]));
}

__device__ __forceinline__ void ldsm_x4(unsigned r[4], unsigned saddr) {
    asm volatile("ldmatrix.sync.aligned.m8n8.x4.shared.b16 {%0,%1,%2,%3}, [%4];"
        : "=r"(r[0]), "=r"(r[1]), "=r"(r[2]), "=r"(r[3]) : "r"(saddr));
}

__device__ __forceinline__ void ldsm_x4_t(unsigned r[4], unsigned saddr) {
    asm volatile("ldmatrix.sync.aligned.m8n8.x4.trans.shared.b16 {%0,%1,%2,%3}, [%4];"
        : "=r"(r[0]), "=r"(r[1]), "=r"(r[2]), "=r"(r[3]) : "r"(saddr));
}

// ---------------- fused pre-pass ----------------
// segments: inproj (2 nodes/block) | Wstack split | alpha-projection vectors | CSR prep
#define PRE_INPROJ_BLOCKS (NN / 2)                        // 10000
#define PRE_WSTK_BLOCKS   ((NL * 512 * DH + 255) / 256)   // 768
#define PRE_V_BLOCKS      ((NL * NH * DH * 2 + 255) / 256)// 12
#define PRE_PREP_BLOCKS   ((NN + 256) / 256)              // 79
#define PRE_TOTAL_BLOCKS  (PRE_INPROJ_BLOCKS + PRE_WSTK_BLOCKS + PRE_V_BLOCKS + PRE_PREP_BLOCKS)

__global__ __launch_bounds__(256) void k_pre(const float* __restrict__ x,
                                             const float* __restrict__ w,
                                             const float* __restrict__ b,
                                             const float* __restrict__ wg,
                                             const float* __restrict__ a_src,
                                             const float* __restrict__ a_dst,
                                             const int* __restrict__ batch) {
    int bid = blockIdx.x;
    if (bid < PRE_INPROJ_BLOCKS) {
        int local = threadIdx.x >> 7;     // 0/1
        int d = threadIdx.x & 127;
        int n = bid * 2 + local;
        __shared__ float xs[2][FD];
        if (d < FD) xs[local][d] = x[n * FD + d];
        __syncthreads();
        float a = b[d];
#pragma unroll
        for (int k = 0; k < FD; k++) a += xs[local][k] * w[k * DH + d];
        g_h[n * DH + d] = fmaxf(a, 0.f);
    } else if (bid < PRE_INPROJ_BLOCKS + PRE_WSTK_BLOCKS) {
        int i = (bid - PRE_INPROJ_BLOCKS) * 256 + threadIdx.x;
        if (i < NL * 512 * DH) {
            int l = i >> 16;             // 512*128 = 65536
            int r = (i >> 7) & 511;      // stacked row = h*128 + kd
            int d = i & 127;
            int h = r >> 7, kd = r & 127;
            float v = 0.25f * wg[l * 65536 + kd * 512 + h * 128 + d];
            __nv_bfloat16 hi = __float2bfloat16_rn(v);
            g_wstk_hi[i] = hi;
            g_wstk_lo[i] = __float2bfloat16_rn(v - __bfloat162float(hi));
        }
    } else if (bid < PRE_INPROJ_BLOCKS + PRE_WSTK_BLOCKS + PRE_V_BLOCKS) {
        int i = (bid - PRE_INPROJ_BLOCKS - PRE_WSTK_BLOCKS) * 256 + threadIdx.x;
        int half = (i >= NL * NH * DH);
        int j = half ? i - NL * NH * DH : i;
        if (j < NL * NH * DH) {
            int l = j >> 9;              // NH*DH = 512
            int rem = j & 511;
            int h = rem >> 7, k = rem & 127;
            const float* av = half ? a_dst : a_src;
            float s = 0.f;
#pragma unroll 4
            for (int d = 0; d < 128; d++)
                s += wg[l * 65536 + k * 512 + h * 128 + d] * av[l * 512 + h * 128 + d];
            if (half) g_vd[j] = s; else g_vs[j] = s;
        }
    } else {
        int i = (bid - PRE_INPROJ_BLOCKS - PRE_WSTK_BLOCKS - PRE_V_BLOCKS) * 256 + threadIdx.x;
        if (i < NN) g_cnt[i] = 0;
        if (i <= NN) {
            int bb = (i < NN) ? batch[i] : NGR;
            int bp = (i > 0) ? batch[i - 1] : -1;
            for (int g = bp + 1; g <= bb && g <= NGR; g++) g_gstart[g] = i;
        }
    }
}

// ---------------- CSR build ----------------
__global__ void k_count(const int* __restrict__ ei) {
    int i = blockIdx.x * blockDim.x + threadIdx.x;
    if (i >= ETOT) return;
    int dst = (i < NE) ? ei[NE + i] : (i - NE);
    atomicAdd(&g_cnt[dst], 1);
}

__global__ void k_scan() {   // single block, 1024 threads, chunk=20; also writes cursor
    __shared__ int ssum[1024];
    const int CH = 20;
    int tid = threadIdx.x;
    int base = tid * CH;
    int s = 0;
    for (int j = 0; j < CH; j++) {
        int idx = base + j;
        if (idx < NN) s += g_cnt[idx];
    }
    ssum[tid] = s;
    __syncthreads();
    for (int off = 1; off < 1024; off <<= 1) {
        int v = 0;
        if (tid >= off) v = ssum[tid - off];
        __syncthreads();
        ssum[tid] += v;
        __syncthreads();
    }
    int run = tid ? ssum[tid - 1] : 0;
    for (int j = 0; j < CH; j++) {
        int idx = base + j;
        if (idx < NN) {
            int c = g_cnt[idx];
            g_rowptr[idx] = run;
            g_cnt[idx]    = run;   // scatter cursor
            run += c;
        }
    }
    if (tid == 1023) g_rowptr[NN] = ssum[1023];
}

__global__ void k_scatter(const int* __restrict__ ei) {
    int i = blockIdx.x * blockDim.x + threadIdx.x;
    if (i >= ETOT) return;
    int src, dst;
    if (i < NE) { src = ei[i]; dst = ei[NE + i]; }
    else        { src = i - NE; dst = i - NE; }
    int pos = atomicAdd(&g_cnt[dst], 1);
    g_esrc[pos] = src;
}

// ---------------- alpha logits: g_as/g_ad[n,h] = h[n] . v_{s,d}[layer,h] ----------------
// grid 313 x 256: 64 rows/block, 4 threads/row (32 dims each), 8 independent LDG.128 per thread
__global__ __launch_bounds__(256) void k_alpha(int layer) {
    __shared__ float svs[512], svd[512];
    int tid = threadIdx.x;
    for (int i = tid; i < 512; i += 256) {
        svs[i] = g_vs[layer * 512 + i];
        svd[i] = g_vd[layer * 512 + i];
    }
    __syncthreads();
    int n = blockIdx.x * 64 + (tid >> 2);
    int q = tid & 3;
    bool ok = (n < NN);
    float p[8] = {0.f, 0.f, 0.f, 0.f, 0.f, 0.f, 0.f, 0.f};
    if (ok) {
        const float4* hr = (const float4*)&g_h[n * DH + q * 32];
        float4 hv[8];
#pragma unroll
        for (int j = 0; j < 8; j++) hv[j] = hr[j];
#pragma unroll
        for (int j = 0; j < 8; j++) {
            int d = q * 32 + j * 4;
#pragma unroll
            for (int h = 0; h < 4; h++) {
                float4 vs4 = *(const float4*)&svs[h * 128 + d];
                float4 vd4 = *(const float4*)&svd[h * 128 + d];
                p[h]     += hv[j].x * vs4.x + hv[j].y * vs4.y + hv[j].z * vs4.z + hv[j].w * vs4.w;
                p[4 + h] += hv[j].x * vd4.x + hv[j].y * vd4.y + hv[j].z * vd4.z + hv[j].w * vd4.w;
            }
        }
    }
#pragma unroll
    for (int i = 0; i < 8; i++) {
        p[i] += __shfl_xor_sync(0xffffffffu, p[i], 1);
        p[i] += __shfl_xor_sync(0xffffffffu, p[i], 2);
    }
    if (ok && q == 0) {
#pragma unroll
        for (int h = 0; h < 4; h++) {
            g_as[n * 4 + h] = p[h];
            g_ad[n * 4 + h] = p[4 + h];
        }
    }
}

// ---------------- GAT aggregation in input space ----------------
// block per node, 128 threads; thread = dim; 4 head accumulators over h[src].
__global__ __launch_bounds__(128) void k_agg() {
    int node = blockIdx.x, tid = threadIdx.x;
    int h = tid >> 5, lane = tid & 31;
    __shared__ float sm[4], ss[4], sad[4];
    __shared__ int   ssrc[32];
    __shared__ alignas(16) float swt[32][4];
    if (tid < 4) sad[tid] = g_ad[node * 4 + tid];
    int beg = g_rowptr[node], end = g_rowptr[node + 1];
    __syncthreads();

    // pass 1: per-head online softmax stats (warp per head)
    float adh = sad[h];
    float m = -1e30f, s = 0.f;
    for (int e = beg + lane; e < end; e += 32) {
        int src = g_esrc[e];
        float x = g_as[src * 4 + h] + adh;
        x = x > 0.f ? x : 0.2f * x;
        float nm = fmaxf(m, x);
        s = s * __expf(m - nm) + __expf(x - nm);
        m = nm;
    }
#pragma unroll
    for (int off = 16; off > 0; off >>= 1) {
        float mo = __shfl_xor_sync(0xffffffffu, m, off);
        float so = __shfl_xor_sync(0xffffffffu, s, off);
        float nm = fmaxf(m, mo);
        s = s * __expf(m - nm) + so * __expf(mo - nm);
        m = nm;
    }
    if (lane == 0) { sm[h] = m; ss[h] = 1.f / s; }
    __syncthreads();

    // pass 2: gather h[src] once per edge, 4 head-weighted accumulators
    float a0 = 0.f, a1 = 0.f, a2 = 0.f, a3 = 0.f;
    for (int base = beg; base < end; base += 32) {
        int cnt = end - base; if (cnt > 32) cnt = 32;
        if (tid < cnt * 4) {
            int e  = base + (tid >> 2);
            int hd = tid & 3;
            int src = g_esrc[e];
            float x = g_as[src * 4 + hd] + sad[hd];
            x = x > 0.f ? x : 0.2f * x;
            swt[tid >> 2][hd] = __expf(x - sm[hd]) * ss[hd];
            if (hd == 0) ssrc[tid >> 2] = src;
        }
        __syncthreads();
        for (int j = 0; j < cnt; j++) {
            float4 wv = *(const float4*)swt[j];
            float hv = g_h[ssrc[j] * DH + tid];
            a0 += wv.x * hv;
            a1 += wv.y * hv;
            a2 += wv.z * hv;
            a3 += wv.w * hv;
        }
        __syncthreads();
    }

    // store bf16 split of agg [node][h*128 + d]
    int ob = node * 512 + tid;
#pragma unroll
    for (int hh = 0; hh < 4; hh++) {
        float v = (hh == 0) ? a0 : (hh == 1) ? a1 : (hh == 2) ? a2 : a3;
        __nv_bfloat16 hi = __float2bfloat16_rn(v);
        g_agg_hi[ob + hh * 128] = hi;
        g_agg_lo[ob + hh * 128] = __float2bfloat16_rn(v - __bfloat162float(hi));
    }
}

// ---------------- post-GEMM: h_new = relu(LN(agg @ Wstack + bias)) + h_old ----------------
// M-tile 64, grid 313, 256 threads = 8 warps (4 warp_m x 16 rows, 2 warp_n x 64 cols).
__global__ __launch_bounds__(256, 3) void k_gemm2(int layer,
                                                  const float* __restrict__ bg,
                                                  const float* __restrict__ lnw,
                                                  const float* __restrict__ lnb) {
    __shared__ alignas(16) __nv_bfloat16 As_h[64][APAD], As_l[64][APAD];     // [m][k]
    __shared__ alignas(16) __nv_bfloat16 Bs_h[32][BPAD],  Bs_l[32][BPAD];    // [k][n]
    __shared__ float rsum[2][64], rsq[2][64];
    __shared__ float s_bg[128], s_lnw[128], s_lnb[128];

    int tid = threadIdx.x;
    int wid = tid >> 5, lane = tid & 31;
    int warp_m = wid & 3, warp_n = wid >> 2;
    int m0 = blockIdx.x * 64;
    int g  = lane >> 2, t = lane & 3;
    const __nv_bfloat16* Bh = g_wstk_hi + layer * 512 * DH;
    const __nv_bfloat16* Bl = g_wstk_lo + layer * 512 * DH;

    if (tid < 128) { s_bg[tid] = bg[tid]; s_lnw[tid] = lnw[tid]; s_lnb[tid] = lnb[tid]; }

    float c[8][4];
#pragma unroll
    for (int nt = 0; nt < 8; nt++)
#pragma unroll
        for (int i = 0; i < 4; i++) c[nt][i] = 0.f;

    int ar  = tid >> 2, akg = (tid & 3) * 8;     // A: 64 rows, 8 bf16 (1 uint4) per thread
    int bkr = tid >> 3, bcg = (tid & 7) * 16;    // B: 32 rows, 16 bf16 (2 uint4) per thread

    int lrow = (lane & 7) + ((lane >> 3) & 1) * 8;
    int lcol = (lane >> 4) * 8;
    unsigned sAh = (unsigned)__cvta_generic_to_shared(As_h);
    unsigned sAl = (unsigned)__cvta_generic_to_shared(As_l);
    unsigned sBh = (unsigned)__cvta_generic_to_shared(Bs_h);
    unsigned sBl = (unsigned)__cvta_generic_to_shared(Bs_l);

    for (int kc = 0; kc < 512; kc += 32) {
        __syncthreads();
        {
            bool ok = (m0 + ar < NN);
            uint4 z = make_uint4(0u, 0u, 0u, 0u);
            const uint4* ph = (const uint4*)&g_agg_hi[(m0 + ar) * 512 + kc + akg];
            const uint4* pl = (const uint4*)&g_agg_lo[(m0 + ar) * 512 + kc + akg];
            *(uint4*)&As_h[ar][akg] = ok ? ph[0] : z;
            *(uint4*)&As_l[ar][akg] = ok ? pl[0] : z;
        }
        {
            const uint4* ph = (const uint4*)&Bh[(kc + bkr) * 128 + bcg];
            const uint4* pl = (const uint4*)&Bl[(kc + bkr) * 128 + bcg];
            uint4 h0 = ph[0], h1 = ph[1];
            uint4 l0 = pl[0], l1 = pl[1];
            *(uint4*)&Bs_h[bkr][bcg]     = h0;
            *(uint4*)&Bs_h[bkr][bcg + 8] = h1;
            *(uint4*)&Bs_l[bkr][bcg]     = l0;
            *(uint4*)&Bs_l[bkr][bcg + 8] = l1;
        }
        __syncthreads();

#pragma unroll
        for (int kk = 0; kk < 32; kk += 16) {
            unsigned ah[4], al[4];
            unsigned off = (unsigned)(((warp_m * 16 + lrow) * APAD + kk + lcol) * 2);
            ldsm_x4(ah, sAh + off);
            ldsm_x4(al, sAl + off);
#pragma unroll
            for (int p = 0; p < 4; p++) {
                unsigned boff = (unsigned)(((kk + lrow) * BPAD + warp_n * 64 + p * 16 + lcol) * 2);
                unsigned bh[4], bl[4];
                ldsm_x4_t(bh, sBh + boff);
                ldsm_x4_t(bl, sBl + boff);
#pragma unroll
                for (int q = 0; q < 2; q++) {
                    float* cc = c[p * 2 + q];
                    mma_bf16(cc, ah, &bh[q * 2]);
                    mma_bf16(cc, ah, &bl[q * 2]);
                    mma_bf16(cc, al, &bh[q * 2]);
                }
            }
        }
    }
    __syncthreads();

    // epilogue: bias, per-row LN stats, normalize, relu, residual, write g_h
#pragma unroll
    for (int nt = 0; nt < 8; nt++) {
        int col = warp_n * 64 + nt * 8 + t * 2;
        c[nt][0] += s_bg[col];
        c[nt][1] += s_bg[col + 1];
        c[nt][2] += s_bg[col];
        c[nt][3] += s_bg[col + 1];
    }
    float sum[2] = {0.f, 0.f}, sq[2] = {0.f, 0.f};
#pragma unroll
    for (int nt = 0; nt < 8; nt++) {
        float c0 = c[nt][0], c1 = c[nt][1], c2 = c[nt][2], c3 = c[nt][3];
        sum[0] += c0 + c1;  sq[0] += c0 * c0 + c1 * c1;
        sum[1] += c2 + c3;  sq[1] += c2 * c2 + c3 * c3;
    }
#pragma unroll
    for (int off = 1; off <= 2; off <<= 1)
#pragma unroll
        for (int i = 0; i < 2; i++) {
            sum[i] += __shfl_xor_sync(0xffffffffu, sum[i], off);
            sq[i]  += __shfl_xor_sync(0xffffffffu, sq[i],  off);
        }
    if (t == 0) {
#pragma unroll
        for (int hf = 0; hf < 2; hf++) {
            int row = warp_m * 16 + hf * 8 + g;
            rsum[warp_n][row] = sum[hf];
            rsq[warp_n][row]  = sq[hf];
        }
    }
    __syncthreads();

#pragma unroll
    for (int hf = 0; hf < 2; hf++) {
        int row = warp_m * 16 + hf * 8 + g;
        int grow = m0 + row;
        if (grow >= NN) continue;
        float S = rsum[0][row] + rsum[1][row];
        float Q = rsq[0][row] + rsq[1][row];
        float mu  = S * (1.f / 128.f);
        float var = Q * (1.f / 128.f) - mu * mu;
        float rstd = rsqrtf(var + 1e-5f);
#pragma unroll
        for (int nt = 0; nt < 8; nt++) {
            int col = warp_n * 64 + nt * 8 + t * 2;
            float c0 = c[nt][hf * 2 + 0];
            float c1 = c[nt][hf * 2 + 1];
            float2 hold = *(const float2*)&g_h[grow * DH + col];
            float v0 = (c0 - mu) * rstd * s_lnw[col]     + s_lnb[col];
            float v1 = (c1 - mu) * rstd * s_lnw[col + 1] + s_lnb[col + 1];
            float2 nv = make_float2(fmaxf(v0, 0.f) + hold.x, fmaxf(v1, 0.f) + hold.y);
            *(float2*)&g_h[grow * DH + col] = nv;
        }
    }
}

// ---------------- pooling + TDA + trunk + task heads (fully fused) ----------------
__global__ __launch_bounds__(256) void k_head(const float* __restrict__ tda,
                                              const float* __restrict__ wt1, const float* __restrict__ bt1,
                                              const float* __restrict__ wt2, const float* __restrict__ bt2,
                                              const float* __restrict__ wsh1, const float* __restrict__ bsh1,
                                              const float* __restrict__ wsh2, const float* __restrict__ bsh2,
                                              const float* __restrict__ wh1,  const float* __restrict__ bh1,
                                              const float* __restrict__ wh2,  const float* __restrict__ bh2,
                                              float* __restrict__ out) {
    int g = blockIdx.x, tid = threadIdx.x;
    __shared__ float comb[320], s1[256], s2[128], hh1[NT * 64], th1[64];

    int beg = g_gstart[g], end = g_gstart[g + 1];
    int cntn = end - beg;
    {
        int d = tid & 127;
        if (tid < 128) {
            float s = 0.f;
            for (int i = beg; i < end; i++) s += g_h[i * DH + d];
            comb[d] = s / (float)(cntn > 0 ? cntn : 1);
        } else {
            float mx = -1e30f;
            for (int i = beg; i < end; i++) mx = fmaxf(mx, g_h[i * DH + d]);
            comb[128 + d] = (cntn > 0) ? mx : 0.f;
        }
    }
    __syncthreads();
    if (tid < 64) {
        float a = bt1[tid];
#pragma unroll
        for (int k = 0; k < FT; k++) a += tda[g * FT + k] * wt1[k * 64 + tid];
        th1[tid] = fmaxf(a, 0.f);
    }
    __syncthreads();
    if (tid < 64) {
        float c = bt2[tid];
#pragma unroll
        for (int k = 0; k < 64; k++) c += th1[k] * wt2[k * 64 + tid];
        comb[256 + tid] = fmaxf(c, 0.f);
    }
    __syncthreads();
    float a = bsh1[tid];
    for (int k = 0; k < 320; k++) a += comb[k] * wsh1[k * 256 + tid];
    s1[tid] = fmaxf(a, 0.f);
    __syncthreads();
    if (tid < 128) {
        float c = bsh2[tid];
        for (int k = 0; k < 256; k++) c += s1[k] * wsh2[k * 128 + tid];
        s2[tid] = fmaxf(c, 0.f);
    }
    __syncthreads();
    for (int idx = tid; idx < NT * 64; idx += 256) {
        int t = idx >> 6, kk = idx & 63;
        float c = bh1[t * 64 + kk];
        for (int k = 0; k < 128; k++) c += s2[k] * wh1[t * 8192 + k * 64 + kk];
        hh1[idx] = fmaxf(c, 0.f);
    }
    __syncthreads();
    if (tid < NT) {
        float c = bh2[tid];
        for (int k = 0; k < 64; k++) c += hh1[tid * 64 + k] * wh2[tid * 64 + k];
        out[tid * NGR + g] = c;
    }
}

// ---------------- launch ----------------
extern "C" void kernel_launch(void* const* d_in, const int* in_sizes, int n_in,
                              void* d_out, int out_size) {
    const float* x       = (const float*)d_in[0];
    const int*   ei      = (const int*)d_in[1];
    const int*   batch   = (const int*)d_in[2];
    const float* tda     = (const float*)d_in[3];
    const float* w_in    = (const float*)d_in[4];
    const float* b_in    = (const float*)d_in[5];
    const float* w_gat   = (const float*)d_in[6];
    const float* a_src   = (const float*)d_in[7];
    const float* a_dst   = (const float*)d_in[8];
    const float* b_gat   = (const float*)d_in[9];
    const float* ln_w    = (const float*)d_in[10];
    const float* ln_b    = (const float*)d_in[11];
    const float* w_tda1  = (const float*)d_in[12];
    const float* b_tda1  = (const float*)d_in[13];
    const float* w_tda2  = (const float*)d_in[14];
    const float* b_tda2  = (const float*)d_in[15];
    const float* w_sh1   = (const float*)d_in[16];
    const float* b_sh1   = (const float*)d_in[17];
    const float* w_sh2   = (const float*)d_in[18];
    const float* b_sh2   = (const float*)d_in[19];
    const float* w_h1    = (const float*)d_in[20];
    const float* b_h1    = (const float*)d_in[21];
    const float* w_h2    = (const float*)d_in[22];
    const float* b_h2    = (const float*)d_in[23];
    float* out = (float*)d_out;

    const int ROWS64_GRID = (NN + 63) / 64;   // 313

    k_pre<<<PRE_TOTAL_BLOCKS, 256>>>(x, w_in, b_in, w_gat, a_src, a_dst, batch);  // 0
    k_count<<<(ETOT + 255) / 256, 256>>>(ei);                                     // 1
    k_scan<<<1, 1024>>>();                                                        // 2
    k_alpha<<<ROWS64_GRID, 256>>>(0);                                             // 3 (profiled)
    k_scatter<<<(ETOT + 255) / 256, 256>>>(ei);                                   // 4

    for (int l = 0; l < NL; l++) {
        k_agg<<<NN, 128>>>();
        k_gemm2<<<ROWS64_GRID, 256>>>(l, b_gat + l * 128, ln_w + l * 128, ln_b + l * 128);
        if (l + 1 < NL) k_alpha<<<ROWS64_GRID, 256>>>(l + 1);
    }

    k_head<<<NGR, 256>>>(tda, w_tda1, b_tda1, w_tda2, b_tda2,
                         w_sh1, b_sh1, w_sh2, b_sh2, w_h1, b_h1, w_h2, b_h2, out);
}

// round 12
// speedup vs baseline: 1.0850x; 1.0265x over previous
#include <cuda_runtime.h>
#include <cuda_bf16.h>
#include <math.h>

#define NN   20000        // nodes
#define NE   320000       // edges (without self loops)
#define ETOT (NE + NN)    // edges + self loops
#define NGR  256          // graphs
#define FD   11           // node feature dim
#define FT   30           // tda feature dim
#define DH   128          // hidden
#define NH   4            // heads
#define NL   3            // layers
#define NT   6            // tasks

#define APAD 40           // A smem row length (32 k + 8 pad) in bf16
#define BPAD 136          // B smem row length (128 n + 8 pad) in bf16

// ---------------- device scratch (static, no allocations) ----------------
// Referenced ONLY inside kernels — never passed as kernel arguments.
__device__ float         g_h[NN * DH];            // node features (in-place updated)
__device__ __nv_bfloat16 g_agg_hi[NN * 512];      // aggregated features bf16 hi [N, 4*128]
__device__ __nv_bfloat16 g_agg_lo[NN * 512];      // aggregated features bf16 lo
__device__ __nv_bfloat16 g_wstk_hi[NL * 512 * DH];// stacked (W_h/4) bf16 hi [l][h*128+kd][d]
__device__ __nv_bfloat16 g_wstk_lo[NL * 512 * DH];
__device__ float         g_vs[NL * NH * DH];      // projected a_src vectors [l][h][k]
__device__ float         g_vd[NL * NH * DH];      // projected a_dst vectors
__device__ float         g_as[NN * NH];           // alpha_src per node/head
__device__ float         g_ad[NN * NH];           // alpha_dst per node/head
__device__ int           g_rowptr[NN + 1];
__device__ int           g_cnt[NN];               // counts, then scatter cursor
__device__ int           g_esrc[ETOT];            // src ids sorted by dst
__device__ int           g_gstart[NGR + 1];

// ---------------- bf16 mma helpers ----------------
__device__ __forceinline__ void mma_bf16(float c[4], const unsigned a[4], const unsigned* b) {
    asm volatile(
        "mma.sync.aligned.m16n8k16.row.col.f32.bf16.bf16.f32 "
        "{%0,%1,%2,%3}, {%4,%5,%6,%7}, {%8,%9}, {%0,%1,%2,%3};\n"
        : "+f"(c[0]), "+f"(c[1]), "+f"(c[2]), "+f"(c[3])
        : "r"(a[0]), "r"(a[1]), "r"(a[2]), "r"(a[3]), "r"(b[0]), "r"(b[1]));
}

__device__ __forceinline__ void ldsm_x4(unsigned r[4], unsigned saddr) {
    asm volatile("ldmatrix.sync.aligned.m8n8.x4.shared.b16 {%0,%1,%2,%3}, [%4];"
        : "=r"(r[0]), "=r"(r[1]), "=r"(r[2]), "=r"(r[3]) : "r"(saddr));
}

__device__ __forceinline__ void ldsm_x4_t(unsigned r[4], unsigned saddr) {
    asm volatile("ldmatrix.sync.aligned.m8n8.x4.trans.shared.b16 {%0,%1,%2,%3}, [%4];"
        : "=r"(r[0]), "=r"(r[1]), "=r"(r[2]), "=r"(r[3]) : "r"(saddr));
}

// ---------------- fused pre-pass ----------------
// segments: inproj (2 nodes/block) | Wstack split | v-projection (warp per output) | CSR prep
#define PRE_INPROJ_BLOCKS (NN / 2)                        // 10000
#define PRE_WSTK_BLOCKS   ((NL * 512 * DH + 255) / 256)   // 768
#define PRE_V_BLOCKS      ((NL * 2 * NH * DH) / 8)        // 384 (8 warps/block, warp per output)
#define PRE_PREP_BLOCKS   ((NN + 256) / 256)              // 79
#define PRE_TOTAL_BLOCKS  (PRE_INPROJ_BLOCKS + PRE_WSTK_BLOCKS + PRE_V_BLOCKS + PRE_PREP_BLOCKS)

__global__ __launch_bounds__(256) void k_pre(const float* __restrict__ x,
                                             const float* __restrict__ w,
                                             const float* __restrict__ b,
                                             const float* __restrict__ wg,
                                             const float* __restrict__ a_src,
                                             const float* __restrict__ a_dst,
                                             const int* __restrict__ batch) {
    int bid = blockIdx.x;
    if (bid < PRE_INPROJ_BLOCKS) {
        int local = threadIdx.x >> 7;     // 0/1
        int d = threadIdx.x & 127;
        int n = bid * 2 + local;
        __shared__ float xs[2][FD];
        if (d < FD) xs[local][d] = x[n * FD + d];
        __syncthreads();
        float a = b[d];
#pragma unroll
        for (int k = 0; k < FD; k++) a += xs[local][k] * w[k * DH + d];
        g_h[n * DH + d] = fmaxf(a, 0.f);
    } else if (bid < PRE_INPROJ_BLOCKS + PRE_WSTK_BLOCKS) {
        int i = (bid - PRE_INPROJ_BLOCKS) * 256 + threadIdx.x;
        if (i < NL * 512 * DH) {
            int l = i >> 16;             // 512*128 = 65536
            int r = (i >> 7) & 511;      // stacked row = h*128 + kd
            int d = i & 127;
            int h = r >> 7, kd = r & 127;
            float v = 0.25f * wg[l * 65536 + kd * 512 + h * 128 + d];
            __nv_bfloat16 hi = __float2bfloat16_rn(v);
            g_wstk_hi[i] = hi;
            g_wstk_lo[i] = __float2bfloat16_rn(v - __bfloat162float(hi));
        }
    } else if (bid < PRE_INPROJ_BLOCKS + PRE_WSTK_BLOCKS + PRE_V_BLOCKS) {
        // warp per output: j over NL*2*NH*DH = 3072; lane = one float4 of the 128-dot
        int bl = bid - PRE_INPROJ_BLOCKS - PRE_WSTK_BLOCKS;
        int wid = threadIdx.x >> 5, lane = threadIdx.x & 31;
        int j = bl * 8 + wid;            // [0, 3072)
        int l    = j >> 10;              // 1024 outputs per layer (2 halves x 512)
        int rem  = j & 1023;
        int half = rem >> 9;
        int hk   = rem & 511;
        int h = hk >> 7, k = hk & 127;
        const float* av = half ? a_dst : a_src;
        float4 w4 = *(const float4*)&wg[l * 65536 + k * 512 + h * 128 + lane * 4];
        float4 a4 = *(const float4*)&av[l * 512 + h * 128 + lane * 4];
        float s = w4.x * a4.x + w4.y * a4.y + w4.z * a4.z + w4.w * a4.w;
#pragma unroll
        for (int off = 16; off > 0; off >>= 1) s += __shfl_xor_sync(0xffffffffu, s, off);
        if (lane == 0) {
            if (half) g_vd[l * 512 + hk] = s;
            else      g_vs[l * 512 + hk] = s;
        }
    } else {
        int i = (bid - PRE_INPROJ_BLOCKS - PRE_WSTK_BLOCKS - PRE_V_BLOCKS) * 256 + threadIdx.x;
        if (i < NN) g_cnt[i] = 0;
        if (i <= NN) {
            int bb = (i < NN) ? batch[i] : NGR;
            int bp = (i > 0) ? batch[i - 1] : -1;
            for (int g = bp + 1; g <= bb && g <= NGR; g++) g_gstart[g] = i;
        }
    }
}

// ---------------- CSR build ----------------
__global__ void k_count(const int* __restrict__ ei) {
    int i = blockIdx.x * blockDim.x + threadIdx.x;
    if (i >= ETOT) return;
    int dst = (i < NE) ? ei[NE + i] : (i - NE);
    atomicAdd(&g_cnt[dst], 1);
}

__global__ void k_scan() {   // single block, 1024 threads, chunk=20; also writes cursor
    __shared__ int ssum[1024];
    const int CH = 20;
    int tid = threadIdx.x;
    int base = tid * CH;
    int s = 0;
    for (int j = 0; j < CH; j++) {
        int idx = base + j;
        if (idx < NN) s += g_cnt[idx];
    }
    ssum[tid] = s;
    __syncthreads();
    for (int off = 1; off < 1024; off <<= 1) {
        int v = 0;
        if (tid >= off) v = ssum[tid - off];
        __syncthreads();
        ssum[tid] += v;
        __syncthreads();
    }
    int run = tid ? ssum[tid - 1] : 0;
    for (int j = 0; j < CH; j++) {
        int idx = base + j;
        if (idx < NN) {
            int c = g_cnt[idx];
            g_rowptr[idx] = run;
            g_cnt[idx]    = run;   // scatter cursor
            run += c;
        }
    }
    if (tid == 1023) g_rowptr[NN] = ssum[1023];
}

__global__ void k_scatter(const int* __restrict__ ei) {
    int i = blockIdx.x * blockDim.x + threadIdx.x;
    if (i >= ETOT) return;
    int src, dst;
    if (i < NE) { src = ei[i]; dst = ei[NE + i]; }
    else        { src = i - NE; dst = i - NE; }
    int pos = atomicAdd(&g_cnt[dst], 1);
    g_esrc[pos] = src;
}

// ---------------- alpha logits: g_as/g_ad[n,h] = h[n] . v_{s,d}[layer,h] ----------------
// grid 10000 x 256: 2 nodes/block, thread = (node, dim). 1 LDG + 8 broadcast LDS + reduce.
__global__ __launch_bounds__(256) void k_alpha(int layer) {
    __shared__ float sv[1024];        // [0:512) = vs, [512:1024) = vd
    __shared__ float red[8][8];       // [warp][p-index]
    int tid = threadIdx.x;
    {   // stage both v vectors: 256 float4 = one per thread
        float4 v4;
        if (tid < 128) v4 = *(const float4*)&g_vs[layer * 512 + tid * 4];
        else           v4 = *(const float4*)&g_vd[layer * 512 + (tid - 128) * 4];
        *(float4*)&sv[tid * 4] = v4;
    }
    __syncthreads();
    int local = tid >> 7;             // 0/1
    int d = tid & 127;
    int n = blockIdx.x * 2 + local;
    float hv = (n < NN) ? g_h[n * DH + d] : 0.f;
    float p[8];
#pragma unroll
    for (int h = 0; h < 4; h++) {
        p[h]     = hv * sv[h * 128 + d];
        p[4 + h] = hv * sv[512 + h * 128 + d];
    }
#pragma unroll
    for (int off = 16; off > 0; off >>= 1)
#pragma unroll
        for (int i = 0; i < 8; i++) p[i] += __shfl_xor_sync(0xffffffffu, p[i], off);
    int wid = tid >> 5, lane = tid & 31;
    if (lane == 0) {
#pragma unroll
        for (int i = 0; i < 8; i++) red[wid][i] = p[i];
    }
    __syncthreads();
    if (tid < 16) {
        int ln = tid >> 3, i = tid & 7;
        float s = red[ln * 4 + 0][i] + red[ln * 4 + 1][i] + red[ln * 4 + 2][i] + red[ln * 4 + 3][i];
        int nn = blockIdx.x * 2 + ln;
        if (nn < NN) {
            if (i < 4) g_as[nn * 4 + i] = s;
            else       g_ad[nn * 4 + (i - 4)] = s;
        }
    }
}

// ---------------- GAT aggregation in input space ----------------
// block per node, 128 threads; thread = dim; 4 head accumulators over h[src].
__global__ __launch_bounds__(128) void k_agg() {
    int node = blockIdx.x, tid = threadIdx.x;
    int h = tid >> 5, lane = tid & 31;
    __shared__ float sm[4], ss[4], sad[4];
    __shared__ int   ssrc[32];
    __shared__ alignas(16) float swt[32][4];
    if (tid < 4) sad[tid] = g_ad[node * 4 + tid];
    int beg = g_rowptr[node], end = g_rowptr[node + 1];
    __syncthreads();

    // pass 1: per-head online softmax stats (warp per head)
    float adh = sad[h];
    float m = -1e30f, s = 0.f;
    for (int e = beg + lane; e < end; e += 32) {
        int src = g_esrc[e];
        float x = g_as[src * 4 + h] + adh;
        x = x > 0.f ? x : 0.2f * x;
        float nm = fmaxf(m, x);
        s = s * __expf(m - nm) + __expf(x - nm);
        m = nm;
    }
#pragma unroll
    for (int off = 16; off > 0; off >>= 1) {
        float mo = __shfl_xor_sync(0xffffffffu, m, off);
        float so = __shfl_xor_sync(0xffffffffu, s, off);
        float nm = fmaxf(m, mo);
        s = s * __expf(m - nm) + so * __expf(mo - nm);
        m = nm;
    }
    if (lane == 0) { sm[h] = m; ss[h] = 1.f / s; }
    __syncthreads();

    // pass 2: gather h[src] once per edge, 4 head-weighted accumulators
    float a0 = 0.f, a1 = 0.f, a2 = 0.f, a3 = 0.f;
    for (int base = beg; base < end; base += 32) {
        int cnt = end - base; if (cnt > 32) cnt = 32;
        if (tid < cnt * 4) {
            int e  = base + (tid >> 2);
            int hd = tid & 3;
            int src = g_esrc[e];
            float x = g_as[src * 4 + hd] + sad[hd];
            x = x > 0.f ? x : 0.2f * x;
            swt[tid >> 2][hd] = __expf(x - sm[hd]) * ss[hd];
            if (hd == 0) ssrc[tid >> 2] = src;
        }
        __syncthreads();
        for (int j = 0; j < cnt; j++) {
            float4 wv = *(const float4*)swt[j];
            float hv = g_h[ssrc[j] * DH + tid];
            a0 += wv.x * hv;
            a1 += wv.y * hv;
            a2 += wv.z * hv;
            a3 += wv.w * hv;
        }
        __syncthreads();
    }

    // store bf16 split of agg [node][h*128 + d]
    int ob = node * 512 + tid;
#pragma unroll
    for (int hh = 0; hh < 4; hh++) {
        float v = (hh == 0) ? a0 : (hh == 1) ? a1 : (hh == 2) ? a2 : a3;
        __nv_bfloat16 hi = __float2bfloat16_rn(v);
        g_agg_hi[ob + hh * 128] = hi;
        g_agg_lo[ob + hh * 128] = __float2bfloat16_rn(v - __bfloat162float(hi));
    }
}

// ---------------- post-GEMM: h_new = relu(LN(agg @ Wstack + bias)) + h_old ----------------
// M-tile 64, grid 313, 256 threads = 8 warps (4 warp_m x 16 rows, 2 warp_n x 64 cols).
__global__ __launch_bounds__(256, 3) void k_gemm2(int layer,
                                                  const float* __restrict__ bg,
                                                  const float* __restrict__ lnw,
                                                  const float* __restrict__ lnb) {
    __shared__ alignas(16) __nv_bfloat16 As_h[64][APAD], As_l[64][APAD];     // [m][k]
    __shared__ alignas(16) __nv_bfloat16 Bs_h[32][BPAD],  Bs_l[32][BPAD];    // [k][n]
    __shared__ float rsum[2][64], rsq[2][64];
    __shared__ float s_bg[128], s_lnw[128], s_lnb[128];

    int tid = threadIdx.x;
    int wid = tid >> 5, lane = tid & 31;
    int warp_m = wid & 3, warp_n = wid >> 2;
    int m0 = blockIdx.x * 64;
    int g  = lane >> 2, t = lane & 3;
    const __nv_bfloat16* Bh = g_wstk_hi + layer * 512 * DH;
    const __nv_bfloat16* Bl = g_wstk_lo + layer * 512 * DH;

    if (tid < 128) { s_bg[tid] = bg[tid]; s_lnw[tid] = lnw[tid]; s_lnb[tid] = lnb[tid]; }

    float c[8][4];
#pragma unroll
    for (int nt = 0; nt < 8; nt++)
#pragma unroll
        for (int i = 0; i < 4; i++) c[nt][i] = 0.f;

    int ar  = tid >> 2, akg = (tid & 3) * 8;     // A: 64 rows, 8 bf16 (1 uint4) per thread
    int bkr = tid >> 3, bcg = (tid & 7) * 16;    // B: 32 rows, 16 bf16 (2 uint4) per thread

    int lrow = (lane & 7) + ((lane >> 3) & 1) * 8;
    int lcol = (lane >> 4) * 8;
    unsigned sAh = (unsigned)__cvta_generic_to_shared(As_h);
    unsigned sAl = (unsigned)__cvta_generic_to_shared(As_l);
    unsigned sBh = (unsigned)__cvta_generic_to_shared(Bs_h);
    unsigned sBl = (unsigned)__cvta_generic_to_shared(Bs_l);

    for (int kc = 0; kc < 512; kc += 32) {
        __syncthreads();
        {
            bool ok = (m0 + ar < NN);
            uint4 z = make_uint4(0u, 0u, 0u, 0u);
            const uint4* ph = (const uint4*)&g_agg_hi[(m0 + ar) * 512 + kc + akg];
            const uint4* pl = (const uint4*)&g_agg_lo[(m0 + ar) * 512 + kc + akg];
            *(uint4*)&As_h[ar][akg] = ok ? ph[0] : z;
            *(uint4*)&As_l[ar][akg] = ok ? pl[0] : z;
        }
        {
            const uint4* ph = (const uint4*)&Bh[(kc + bkr) * 128 + bcg];
            const uint4* pl = (const uint4*)&Bl[(kc + bkr) * 128 + bcg];
            uint4 h0 = ph[0], h1 = ph[1];
            uint4 l0 = pl[0], l1 = pl[1];
            *(uint4*)&Bs_h[bkr][bcg]     = h0;
            *(uint4*)&Bs_h[bkr][bcg + 8] = h1;
            *(uint4*)&Bs_l[bkr][bcg]     = l0;
            *(uint4*)&Bs_l[bkr][bcg + 8] = l1;
        }
        __syncthreads();

#pragma unroll
        for (int kk = 0; kk < 32; kk += 16) {
            unsigned ah[4], al[4];
            unsigned off = (unsigned)(((warp_m * 16 + lrow) * APAD + kk + lcol) * 2);
            ldsm_x4(ah, sAh + off);
            ldsm_x4(al, sAl + off);
#pragma unroll
            for (int p = 0; p < 4; p++) {
                unsigned boff = (unsigned)(((kk + lrow) * BPAD + warp_n * 64 + p * 16 + lcol) * 2);
                unsigned bh[4], bl[4];
                ldsm_x4_t(bh, sBh + boff);
                ldsm_x4_t(bl, sBl + boff);
#pragma unroll
                for (int q = 0; q < 2; q++) {
                    float* cc = c[p * 2 + q];
                    mma_bf16(cc, ah, &bh[q * 2]);
                    mma_bf16(cc, ah, &bl[q * 2]);
                    mma_bf16(cc, al, &bh[q * 2]);
                }
            }
        }
    }
    __syncthreads();

    // epilogue: bias, per-row LN stats, normalize, relu, residual, write g_h
#pragma unroll
    for (int nt = 0; nt < 8; nt++) {
        int col = warp_n * 64 + nt * 8 + t * 2;
        c[nt][0] += s_bg[col];
        c[nt][1] += s_bg[col + 1];
        c[nt][2] += s_bg[col];
        c[nt][3] += s_bg[col + 1];
    }
    float sum[2] = {0.f, 0.f}, sq[2] = {0.f, 0.f};
#pragma unroll
    for (int nt = 0; nt < 8; nt++) {
        float c0 = c[nt][0], c1 = c[nt][1], c2 = c[nt][2], c3 = c[nt][3];
        sum[0] += c0 + c1;  sq[0] += c0 * c0 + c1 * c1;
        sum[1] += c2 + c3;  sq[1] += c2 * c2 + c3 * c3;
    }
#pragma unroll
    for (int off = 1; off <= 2; off <<= 1)
#pragma unroll
        for (int i = 0; i < 2; i++) {
            sum[i] += __shfl_xor_sync(0xffffffffu, sum[i], off);
            sq[i]  += __shfl_xor_sync(0xffffffffu, sq[i],  off);
        }
    if (t == 0) {
#pragma unroll
        for (int hf = 0; hf < 2; hf++) {
            int row = warp_m * 16 + hf * 8 + g;
            rsum[warp_n][row] = sum[hf];
            rsq[warp_n][row]  = sq[hf];
        }
    }
    __syncthreads();

#pragma unroll
    for (int hf = 0; hf < 2; hf++) {
        int row = warp_m * 16 + hf * 8 + g;
        int grow = m0 + row;
        if (grow >= NN) continue;
        float S = rsum[0][row] + rsum[1][row];
        float Q = rsq[0][row] + rsq[1][row];
        float mu  = S * (1.f / 128.f);
        float var = Q * (1.f / 128.f) - mu * mu;
        float rstd = rsqrtf(var + 1e-5f);
#pragma unroll
        for (int nt = 0; nt < 8; nt++) {
            int col = warp_n * 64 + nt * 8 + t * 2;
            float c0 = c[nt][hf * 2 + 0];
            float c1 = c[nt][hf * 2 + 1];
            float2 hold = *(const float2*)&g_h[grow * DH + col];
            float v0 = (c0 - mu) * rstd * s_lnw[col]     + s_lnb[col];
            float v1 = (c1 - mu) * rstd * s_lnw[col + 1] + s_lnb[col + 1];
            float2 nv = make_float2(fmaxf(v0, 0.f) + hold.x, fmaxf(v1, 0.f) + hold.y);
            *(float2*)&g_h[grow * DH + col] = nv;
        }
    }
}

// ---------------- pooling + TDA + trunk + task heads (fully fused) ----------------
__global__ __launch_bounds__(256) void k_head(const float* __restrict__ tda,
                                              const float* __restrict__ wt1, const float* __restrict__ bt1,
                                              const float* __restrict__ wt2, const float* __restrict__ bt2,
                                              const float* __restrict__ wsh1, const float* __restrict__ bsh1,
                                              const float* __restrict__ wsh2, const float* __restrict__ bsh2,
                                              const float* __restrict__ wh1,  const float* __restrict__ bh1,
                                              const float* __restrict__ wh2,  const float* __restrict__ bh2,
                                              float* __restrict__ out) {
    int g = blockIdx.x, tid = threadIdx.x;
    __shared__ float comb[320], s1[256], s2[128], hh1[NT * 64], th1[64];

    int beg = g_gstart[g], end = g_gstart[g + 1];
    int cntn = end - beg;
    {
        int d = tid & 127;
        if (tid < 128) {
            float s = 0.f;
            for (int i = beg; i < end; i++) s += g_h[i * DH + d];
            comb[d] = s / (float)(cntn > 0 ? cntn : 1);
        } else {
            float mx = -1e30f;
            for (int i = beg; i < end; i++) mx = fmaxf(mx, g_h[i * DH + d]);
            comb[128 + d] = (cntn > 0) ? mx : 0.f;
        }
    }
    __syncthreads();
    if (tid < 64) {
        float a = bt1[tid];
#pragma unroll
        for (int k = 0; k < FT; k++) a += tda[g * FT + k] * wt1[k * 64 + tid];
        th1[tid] = fmaxf(a, 0.f);
    }
    __syncthreads();
    if (tid < 64) {
        float c = bt2[tid];
#pragma unroll
        for (int k = 0; k < 64; k++) c += th1[k] * wt2[k * 64 + tid];
        comb[256 + tid] = fmaxf(c, 0.f);
    }
    __syncthreads();
    float a = bsh1[tid];
    for (int k = 0; k < 320; k++) a += comb[k] * wsh1[k * 256 + tid];
    s1[tid] = fmaxf(a, 0.f);
    __syncthreads();
    if (tid < 128) {
        float c = bsh2[tid];
        for (int k = 0; k < 256; k++) c += s1[k] * wsh2[k * 128 + tid];
        s2[tid] = fmaxf(c, 0.f);
    }
    __syncthreads();
    for (int idx = tid; idx < NT * 64; idx += 256) {
        int t = idx >> 6, kk = idx & 63;
        float c = bh1[t * 64 + kk];
        for (int k = 0; k < 128; k++) c += s2[k] * wh1[t * 8192 + k * 64 + kk];
        hh1[idx] = fmaxf(c, 0.f);
    }
    __syncthreads();
    if (tid < NT) {
        float c = bh2[tid];
        for (int k = 0; k < 64; k++) c += hh1[tid * 64 + k] * wh2[tid * 64 + k];
        out[tid * NGR + g] = c;
    }
}

// ---------------- launch ----------------
extern "C" void kernel_launch(void* const* d_in, const int* in_sizes, int n_in,
                              void* d_out, int out_size) {
    const float* x       = (const float*)d_in[0];
    const int*   ei      = (const int*)d_in[1];
    const int*   batch   = (const int*)d_in[2];
    const float* tda     = (const float*)d_in[3];
    const float* w_in    = (const float*)d_in[4];
    const float* b_in    = (const float*)d_in[5];
    const float* w_gat   = (const float*)d_in[6];
    const float* a_src   = (const float*)d_in[7];
    const float* a_dst   = (const float*)d_in[8];
    const float* b_gat   = (const float*)d_in[9];
    const float* ln_w    = (const float*)d_in[10];
    const float* ln_b    = (const float*)d_in[11];
    const float* w_tda1  = (const float*)d_in[12];
    const float* b_tda1  = (const float*)d_in[13];
    const float* w_tda2  = (const float*)d_in[14];
    const float* b_tda2  = (const float*)d_in[15];
    const float* w_sh1   = (const float*)d_in[16];
    const float* b_sh1   = (const float*)d_in[17];
    const float* w_sh2   = (const float*)d_in[18];
    const float* b_sh2   = (const float*)d_in[19];
    const float* w_h1    = (const float*)d_in[20];
    const float* b_h1    = (const float*)d_in[21];
    const float* w_h2    = (const float*)d_in[22];
    const float* b_h2    = (const float*)d_in[23];
    float* out = (float*)d_out;

    const int ROWS64_GRID = (NN + 63) / 64;   // 313
    const int ALPHA_GRID  = (NN + 1) / 2;     // 10000

    k_pre<<<PRE_TOTAL_BLOCKS, 256>>>(x, w_in, b_in, w_gat, a_src, a_dst, batch);  // 0
    k_count<<<(ETOT + 255) / 256, 256>>>(ei);                                     // 1
    k_scan<<<1, 1024>>>();                                                        // 2
    k_alpha<<<ALPHA_GRID, 256>>>(0);                                              // 3 (profiled)
    k_scatter<<<(ETOT + 255) / 256, 256>>>(ei);                                   // 4

    for (int l = 0; l < NL; l++) {
        k_agg<<<NN, 128>>>();
        k_gemm2<<<ROWS64_GRID, 256>>>(l, b_gat + l * 128, ln_w + l * 128, ln_b + l * 128);
        if (l + 1 < NL) k_alpha<<<ALPHA_GRID, 256>>>(l + 1);
    }

    k_head<<<NGR, 256>>>(tda, w_tda1, b_tda1, w_tda2, b_tda2,
                         w_sh1, b_sh1, w_sh2, b_sh2, w_h1, b_h1, w_h2, b_h2, out);
}

// round 13
// speedup vs baseline: 1.1844x; 1.0916x over previous
#include <cuda_runtime.h>
#include <cuda_bf16.h>
#include <math.h>

#define NN   20000        // nodes
#define NE   320000       // edges (without self loops)
#define ETOT (NE + NN)    // edges + self loops
#define NGR  256          // graphs
#define FD   11           // node feature dim
#define FT   30           // tda feature dim
#define DH   128          // hidden
#define NH   4            // heads
#define NL   3            // layers
#define NT   6            // tasks

#define APAD 40           // A smem row length (32 k + 8 pad) in bf16
#define BPAD 136          // B smem row length (128 n + 8 pad) in bf16

// ---------------- device scratch (static, no allocations) ----------------
// Referenced ONLY inside kernels — never passed as kernel arguments.
__device__ float         g_h[NN * DH];            // node features (in-place updated)
__device__ __nv_bfloat16 g_agg_hi[NN * 512];      // aggregated features bf16 hi [N, 4*128]
__device__ __nv_bfloat16 g_agg_lo[NN * 512];      // aggregated features bf16 lo
__device__ __nv_bfloat16 g_wstk_hi[NL * 512 * DH];// stacked (W_h/4) bf16 hi [l][h*128+kd][d]
__device__ __nv_bfloat16 g_wstk_lo[NL * 512 * DH];
__device__ float         g_vs[NL * NH * DH];      // projected a_src vectors [l][h][k]
__device__ float         g_vd[NL * NH * DH];      // projected a_dst vectors
__device__ float         g_as[NN * NH];           // alpha_src per node/head
__device__ float         g_ad[NN * NH];           // alpha_dst per node/head
__device__ int           g_rowptr[NN + 1];
__device__ int           g_cnt[NN];               // counts, then scatter cursor
__device__ int           g_esrc[ETOT];            // src ids sorted by dst
__device__ int           g_gstart[NGR + 1];

// ---------------- bf16 mma helpers ----------------
__device__ __forceinline__ void mma_bf16(float c[4], const unsigned a[4], const unsigned* b) {
    asm volatile(
        "mma.sync.aligned.m16n8k16.row.col.f32.bf16.bf16.f32 "
        "{%0,%1,%2,%3}, {%4,%5,%6,%7}, {%8,%9}, {%0,%1,%2,%3};\n"
        : "+f"(c[0]), "+f"(c[1]), "+f"(c[2]), "+f"(c[3])
        : "r"(a[0]), "r"(a[1]), "r"(a[2]), "r"(a[3]), "r"(b[0]), "r"(b[1]));
}

__device__ __forceinline__ void ldsm_x4(unsigned r[4], unsigned saddr) {
    asm volatile("ldmatrix.sync.aligned.m8n8.x4.shared.b16 {%0,%1,%2,%3}, [%4];"
        : "=r"(r[0]), "=r"(r[1]), "=r"(r[2]), "=r"(r[3]) : "r"(saddr));
}

__device__ __forceinline__ void ldsm_x4_t(unsigned r[4], unsigned saddr) {
    asm volatile("ldmatrix.sync.aligned.m8n8.x4.trans.shared.b16 {%0,%1,%2,%3}, [%4];"
        : "=r"(r[0]), "=r"(r[1]), "=r"(r[2]), "=r"(r[3]) : "r"(saddr));
}

// ---------------- fused pre-pass ----------------
// segments: inproj (2 nodes/block) | Wstack split | v-projection (warp per output) | CSR prep
#define PRE_INPROJ_BLOCKS (NN / 2)                        // 10000
#define PRE_WSTK_BLOCKS   ((NL * 512 * DH + 255) / 256)   // 768
#define PRE_V_BLOCKS      ((NL * 2 * NH * DH) / 8)        // 384 (8 warps/block, warp per output)
#define PRE_PREP_BLOCKS   ((NN + 256) / 256)              // 79
#define PRE_TOTAL_BLOCKS  (PRE_INPROJ_BLOCKS + PRE_WSTK_BLOCKS + PRE_V_BLOCKS + PRE_PREP_BLOCKS)

__global__ __launch_bounds__(256) void k_pre(const float* __restrict__ x,
                                             const float* __restrict__ w,
                                             const float* __restrict__ b,
                                             const float* __restrict__ wg,
                                             const float* __restrict__ a_src,
                                             const float* __restrict__ a_dst,
                                             const int* __restrict__ batch) {
    int bid = blockIdx.x;
    if (bid < PRE_INPROJ_BLOCKS) {
        int local = threadIdx.x >> 7;     // 0/1
        int d = threadIdx.x & 127;
        int n = bid * 2 + local;
        __shared__ float xs[2][FD];
        if (d < FD) xs[local][d] = x[n * FD + d];
        __syncthreads();
        float a = b[d];
#pragma unroll
        for (int k = 0; k < FD; k++) a += xs[local][k] * w[k * DH + d];
        g_h[n * DH + d] = fmaxf(a, 0.f);
    } else if (bid < PRE_INPROJ_BLOCKS + PRE_WSTK_BLOCKS) {
        int i = (bid - PRE_INPROJ_BLOCKS) * 256 + threadIdx.x;
        if (i < NL * 512 * DH) {
            int l = i >> 16;             // 512*128 = 65536
            int r = (i >> 7) & 511;      // stacked row = h*128 + kd
            int d = i & 127;
            int h = r >> 7, kd = r & 127;
            float v = 0.25f * wg[l * 65536 + kd * 512 + h * 128 + d];
            __nv_bfloat16 hi = __float2bfloat16_rn(v);
            g_wstk_hi[i] = hi;
            g_wstk_lo[i] = __float2bfloat16_rn(v - __bfloat162float(hi));
        }
    } else if (bid < PRE_INPROJ_BLOCKS + PRE_WSTK_BLOCKS + PRE_V_BLOCKS) {
        // warp per output: j over NL*2*NH*DH = 3072; lane = one float4 of the 128-dot
        int bl = bid - PRE_INPROJ_BLOCKS - PRE_WSTK_BLOCKS;
        int wid = threadIdx.x >> 5, lane = threadIdx.x & 31;
        int j = bl * 8 + wid;            // [0, 3072)
        int l    = j >> 10;              // 1024 outputs per layer (2 halves x 512)
        int rem  = j & 1023;
        int half = rem >> 9;
        int hk   = rem & 511;
        int h = hk >> 7, k = hk & 127;
        const float* av = half ? a_dst : a_src;
        float4 w4 = *(const float4*)&wg[l * 65536 + k * 512 + h * 128 + lane * 4];
        float4 a4 = *(const float4*)&av[l * 512 + h * 128 + lane * 4];
        float s = w4.x * a4.x + w4.y * a4.y + w4.z * a4.z + w4.w * a4.w;
#pragma unroll
        for (int off = 16; off > 0; off >>= 1) s += __shfl_xor_sync(0xffffffffu, s, off);
        if (lane == 0) {
            if (half) g_vd[l * 512 + hk] = s;
            else      g_vs[l * 512 + hk] = s;
        }
    } else {
        int i = (bid - PRE_INPROJ_BLOCKS - PRE_WSTK_BLOCKS - PRE_V_BLOCKS) * 256 + threadIdx.x;
        if (i < NN) g_cnt[i] = 0;
        if (i <= NN) {
            int bb = (i < NN) ? batch[i] : NGR;
            int bp = (i > 0) ? batch[i - 1] : -1;
            for (int g = bp + 1; g <= bb && g <= NGR; g++) g_gstart[g] = i;
        }
    }
}

// ---------------- CSR build ----------------
__global__ void k_count(const int* __restrict__ ei) {
    int i = blockIdx.x * blockDim.x + threadIdx.x;
    if (i >= ETOT) return;
    int dst = (i < NE) ? ei[NE + i] : (i - NE);
    atomicAdd(&g_cnt[dst], 1);
}

__global__ void k_scan() {   // single block, 1024 threads, chunk=20; also writes cursor
    __shared__ int ssum[1024];
    const int CH = 20;
    int tid = threadIdx.x;
    int base = tid * CH;
    int s = 0;
    for (int j = 0; j < CH; j++) {
        int idx = base + j;
        if (idx < NN) s += g_cnt[idx];
    }
    ssum[tid] = s;
    __syncthreads();
    for (int off = 1; off < 1024; off <<= 1) {
        int v = 0;
        if (tid >= off) v = ssum[tid - off];
        __syncthreads();
        ssum[tid] += v;
        __syncthreads();
    }
    int run = tid ? ssum[tid - 1] : 0;
    for (int j = 0; j < CH; j++) {
        int idx = base + j;
        if (idx < NN) {
            int c = g_cnt[idx];
            g_rowptr[idx] = run;
            g_cnt[idx]    = run;   // scatter cursor
            run += c;
        }
    }
    if (tid == 1023) g_rowptr[NN] = ssum[1023];
}

__global__ void k_scatter(const int* __restrict__ ei) {
    int i = blockIdx.x * blockDim.x + threadIdx.x;
    if (i >= ETOT) return;
    int src, dst;
    if (i < NE) { src = ei[i]; dst = ei[NE + i]; }
    else        { src = i - NE; dst = i - NE; }
    int pos = atomicAdd(&g_cnt[dst], 1);
    g_esrc[pos] = src;
}

// ---------------- alpha logits for layer 0 only ----------------
// grid 10000 x 256: 2 nodes/block, thread = (node, dim). 1 LDG + 8 broadcast LDS + reduce.
__global__ __launch_bounds__(256) void k_alpha(int layer) {
    __shared__ float sv[1024];        // [0:512) = vs, [512:1024) = vd
    __shared__ float red[8][8];       // [warp][p-index]
    int tid = threadIdx.x;
    {
        float4 v4;
        if (tid < 128) v4 = *(const float4*)&g_vs[layer * 512 + tid * 4];
        else           v4 = *(const float4*)&g_vd[layer * 512 + (tid - 128) * 4];
        *(float4*)&sv[tid * 4] = v4;
    }
    __syncthreads();
    int local = tid >> 7;             // 0/1
    int d = tid & 127;
    int n = blockIdx.x * 2 + local;
    float hv = (n < NN) ? g_h[n * DH + d] : 0.f;
    float p[8];
#pragma unroll
    for (int h = 0; h < 4; h++) {
        p[h]     = hv * sv[h * 128 + d];
        p[4 + h] = hv * sv[512 + h * 128 + d];
    }
#pragma unroll
    for (int off = 16; off > 0; off >>= 1)
#pragma unroll
        for (int i = 0; i < 8; i++) p[i] += __shfl_xor_sync(0xffffffffu, p[i], off);
    int wid = tid >> 5, lane = tid & 31;
    if (lane == 0) {
#pragma unroll
        for (int i = 0; i < 8; i++) red[wid][i] = p[i];
    }
    __syncthreads();
    if (tid < 16) {
        int ln = tid >> 3, i = tid & 7;
        float s = red[ln * 4 + 0][i] + red[ln * 4 + 1][i] + red[ln * 4 + 2][i] + red[ln * 4 + 3][i];
        int nn = blockIdx.x * 2 + ln;
        if (nn < NN) {
            if (i < 4) g_as[nn * 4 + i] = s;
            else       g_ad[nn * 4 + (i - 4)] = s;
        }
    }
}

// ---------------- GAT aggregation in input space ----------------
// block per node, 128 threads; thread = dim; 4 head accumulators over h[src].
__global__ __launch_bounds__(128) void k_agg() {
    int node = blockIdx.x, tid = threadIdx.x;
    int h = tid >> 5, lane = tid & 31;
    __shared__ float sm[4], ss[4], sad[4];
    __shared__ int   ssrc[32];
    __shared__ alignas(16) float swt[32][4];
    if (tid < 4) sad[tid] = g_ad[node * 4 + tid];
    int beg = g_rowptr[node], end = g_rowptr[node + 1];
    __syncthreads();

    // pass 1: per-head online softmax stats (warp per head)
    float adh = sad[h];
    float m = -1e30f, s = 0.f;
    for (int e = beg + lane; e < end; e += 32) {
        int src = g_esrc[e];
        float x = g_as[src * 4 + h] + adh;
        x = x > 0.f ? x : 0.2f * x;
        float nm = fmaxf(m, x);
        s = s * __expf(m - nm) + __expf(x - nm);
        m = nm;
    }
#pragma unroll
    for (int off = 16; off > 0; off >>= 1) {
        float mo = __shfl_xor_sync(0xffffffffu, m, off);
        float so = __shfl_xor_sync(0xffffffffu, s, off);
        float nm = fmaxf(m, mo);
        s = s * __expf(m - nm) + so * __expf(mo - nm);
        m = nm;
    }
    if (lane == 0) { sm[h] = m; ss[h] = 1.f / s; }
    __syncthreads();

    // pass 2: gather h[src] once per edge, 4 head-weighted accumulators
    float a0 = 0.f, a1 = 0.f, a2 = 0.f, a3 = 0.f;
    for (int base = beg; base < end; base += 32) {
        int cnt = end - base; if (cnt > 32) cnt = 32;
        if (tid < cnt * 4) {
            int e  = base + (tid >> 2);
            int hd = tid & 3;
            int src = g_esrc[e];
            float x = g_as[src * 4 + hd] + sad[hd];
            x = x > 0.f ? x : 0.2f * x;
            swt[tid >> 2][hd] = __expf(x - sm[hd]) * ss[hd];
            if (hd == 0) ssrc[tid >> 2] = src;
        }
        __syncthreads();
        for (int j = 0; j < cnt; j++) {
            float4 wv = *(const float4*)swt[j];
            float hv = g_h[ssrc[j] * DH + tid];
            a0 += wv.x * hv;
            a1 += wv.y * hv;
            a2 += wv.z * hv;
            a3 += wv.w * hv;
        }
        __syncthreads();
    }

    // store bf16 split of agg [node][h*128 + d]
    int ob = node * 512 + tid;
#pragma unroll
    for (int hh = 0; hh < 4; hh++) {
        float v = (hh == 0) ? a0 : (hh == 1) ? a1 : (hh == 2) ? a2 : a3;
        __nv_bfloat16 hi = __float2bfloat16_rn(v);
        g_agg_hi[ob + hh * 128] = hi;
        g_agg_lo[ob + hh * 128] = __float2bfloat16_rn(v - __bfloat162float(hi));
    }
}

// ---------------- post-GEMM: h_new = relu(LN(agg @ Wstack + bias)) + h_old ----------------
// M-tile 64, grid 313, 256 threads = 8 warps (4 warp_m x 16 rows, 2 warp_n x 64 cols).
// If next_layer < NL, also computes next layer's alpha logits from the fresh h values.
__global__ __launch_bounds__(256, 3) void k_gemm2(int layer, int next_layer,
                                                  const float* __restrict__ bg,
                                                  const float* __restrict__ lnw,
                                                  const float* __restrict__ lnb) {
    __shared__ alignas(16) __nv_bfloat16 As_h[64][APAD], As_l[64][APAD];     // [m][k]
    __shared__ alignas(16) __nv_bfloat16 Bs_h[32][BPAD],  Bs_l[32][BPAD];    // [k][n]
    __shared__ float rsum[2][64], rsq[2][64];
    __shared__ float s_bg[128], s_lnw[128], s_lnb[128];
    __shared__ float sv[1024];          // next layer's vs|vd (staged iff next_layer < NL)
    __shared__ float ared[2][64][8];    // alpha partials [warp_n][row][out]

    int tid = threadIdx.x;
    int wid = tid >> 5, lane = tid & 31;
    int warp_m = wid & 3, warp_n = wid >> 2;
    int m0 = blockIdx.x * 64;
    int g  = lane >> 2, t = lane & 3;
    bool do_alpha = (next_layer < NL);
    const __nv_bfloat16* Bh = g_wstk_hi + layer * 512 * DH;
    const __nv_bfloat16* Bl = g_wstk_lo + layer * 512 * DH;

    if (tid < 128) { s_bg[tid] = bg[tid]; s_lnw[tid] = lnw[tid]; s_lnb[tid] = lnb[tid]; }
    if (do_alpha) {
        for (int i = tid; i < 512; i += 256) {
            sv[i]       = g_vs[next_layer * 512 + i];
            sv[512 + i] = g_vd[next_layer * 512 + i];
        }
    }

    float c[8][4];
#pragma unroll
    for (int nt = 0; nt < 8; nt++)
#pragma unroll
        for (int i = 0; i < 4; i++) c[nt][i] = 0.f;

    int ar  = tid >> 2, akg = (tid & 3) * 8;     // A: 64 rows, 8 bf16 (1 uint4) per thread
    int bkr = tid >> 3, bcg = (tid & 7) * 16;    // B: 32 rows, 16 bf16 (2 uint4) per thread

    int lrow = (lane & 7) + ((lane >> 3) & 1) * 8;
    int lcol = (lane >> 4) * 8;
    unsigned sAh = (unsigned)__cvta_generic_to_shared(As_h);
    unsigned sAl = (unsigned)__cvta_generic_to_shared(As_l);
    unsigned sBh = (unsigned)__cvta_generic_to_shared(Bs_h);
    unsigned sBl = (unsigned)__cvta_generic_to_shared(Bs_l);

    for (int kc = 0; kc < 512; kc += 32) {
        __syncthreads();
        {
            bool ok = (m0 + ar < NN);
            uint4 z = make_uint4(0u, 0u, 0u, 0u);
            const uint4* ph = (const uint4*)&g_agg_hi[(m0 + ar) * 512 + kc + akg];
            const uint4* pl = (const uint4*)&g_agg_lo[(m0 + ar) * 512 + kc + akg];
            *(uint4*)&As_h[ar][akg] = ok ? ph[0] : z;
            *(uint4*)&As_l[ar][akg] = ok ? pl[0] : z;
        }
        {
            const uint4* ph = (const uint4*)&Bh[(kc + bkr) * 128 + bcg];
            const uint4* pl = (const uint4*)&Bl[(kc + bkr) * 128 + bcg];
            uint4 h0 = ph[0], h1 = ph[1];
            uint4 l0 = pl[0], l1 = pl[1];
            *(uint4*)&Bs_h[bkr][bcg]     = h0;
            *(uint4*)&Bs_h[bkr][bcg + 8] = h1;
            *(uint4*)&Bs_l[bkr][bcg]     = l0;
            *(uint4*)&Bs_l[bkr][bcg + 8] = l1;
        }
        __syncthreads();

#pragma unroll
        for (int kk = 0; kk < 32; kk += 16) {
            unsigned ah[4], al[4];
            unsigned off = (unsigned)(((warp_m * 16 + lrow) * APAD + kk + lcol) * 2);
            ldsm_x4(ah, sAh + off);
            ldsm_x4(al, sAl + off);
#pragma unroll
            for (int p = 0; p < 4; p++) {
                unsigned boff = (unsigned)(((kk + lrow) * BPAD + warp_n * 64 + p * 16 + lcol) * 2);
                unsigned bh[4], bl[4];
                ldsm_x4_t(bh, sBh + boff);
                ldsm_x4_t(bl, sBl + boff);
#pragma unroll
                for (int q = 0; q < 2; q++) {
                    float* cc = c[p * 2 + q];
                    mma_bf16(cc, ah, &bh[q * 2]);
                    mma_bf16(cc, ah, &bl[q * 2]);
                    mma_bf16(cc, al, &bh[q * 2]);
                }
            }
        }
    }
    __syncthreads();

    // epilogue: bias, per-row LN stats, normalize, relu, residual, write g_h (+ fused alpha)
#pragma unroll
    for (int nt = 0; nt < 8; nt++) {
        int col = warp_n * 64 + nt * 8 + t * 2;
        c[nt][0] += s_bg[col];
        c[nt][1] += s_bg[col + 1];
        c[nt][2] += s_bg[col];
        c[nt][3] += s_bg[col + 1];
    }
    float sum[2] = {0.f, 0.f}, sq[2] = {0.f, 0.f};
#pragma unroll
    for (int nt = 0; nt < 8; nt++) {
        float c0 = c[nt][0], c1 = c[nt][1], c2 = c[nt][2], c3 = c[nt][3];
        sum[0] += c0 + c1;  sq[0] += c0 * c0 + c1 * c1;
        sum[1] += c2 + c3;  sq[1] += c2 * c2 + c3 * c3;
    }
#pragma unroll
    for (int off = 1; off <= 2; off <<= 1)
#pragma unroll
        for (int i = 0; i < 2; i++) {
            sum[i] += __shfl_xor_sync(0xffffffffu, sum[i], off);
            sq[i]  += __shfl_xor_sync(0xffffffffu, sq[i],  off);
        }
    if (t == 0) {
#pragma unroll
        for (int hf = 0; hf < 2; hf++) {
            int row = warp_m * 16 + hf * 8 + g;
            rsum[warp_n][row] = sum[hf];
            rsq[warp_n][row]  = sq[hf];
        }
    }
    __syncthreads();

    float pa[2][4] = {{0.f,0.f,0.f,0.f},{0.f,0.f,0.f,0.f}};   // alpha_src partials per hf
    float pb[2][4] = {{0.f,0.f,0.f,0.f},{0.f,0.f,0.f,0.f}};   // alpha_dst partials per hf

#pragma unroll
    for (int hf = 0; hf < 2; hf++) {
        int row = warp_m * 16 + hf * 8 + g;
        int grow = m0 + row;
        if (grow >= NN) continue;
        float S = rsum[0][row] + rsum[1][row];
        float Q = rsq[0][row] + rsq[1][row];
        float mu  = S * (1.f / 128.f);
        float var = Q * (1.f / 128.f) - mu * mu;
        float rstd = rsqrtf(var + 1e-5f);
#pragma unroll
        for (int nt = 0; nt < 8; nt++) {
            int col = warp_n * 64 + nt * 8 + t * 2;
            float c0 = c[nt][hf * 2 + 0];
            float c1 = c[nt][hf * 2 + 1];
            float2 hold = *(const float2*)&g_h[grow * DH + col];
            float v0 = (c0 - mu) * rstd * s_lnw[col]     + s_lnb[col];
            float v1 = (c1 - mu) * rstd * s_lnw[col + 1] + s_lnb[col + 1];
            float nv0 = fmaxf(v0, 0.f) + hold.x;
            float nv1 = fmaxf(v1, 0.f) + hold.y;
            *(float2*)&g_h[grow * DH + col] = make_float2(nv0, nv1);
            if (do_alpha) {
#pragma unroll
                for (int h = 0; h < 4; h++) {
                    pa[hf][h] += nv0 * sv[h * 128 + col]       + nv1 * sv[h * 128 + col + 1];
                    pb[hf][h] += nv0 * sv[512 + h * 128 + col] + nv1 * sv[512 + h * 128 + col + 1];
                }
            }
        }
    }

    if (do_alpha) {
#pragma unroll
        for (int off = 1; off <= 2; off <<= 1)
#pragma unroll
            for (int hf = 0; hf < 2; hf++)
#pragma unroll
                for (int h = 0; h < 4; h++) {
                    pa[hf][h] += __shfl_xor_sync(0xffffffffu, pa[hf][h], off);
                    pb[hf][h] += __shfl_xor_sync(0xffffffffu, pb[hf][h], off);
                }
        if (t == 0) {
#pragma unroll
            for (int hf = 0; hf < 2; hf++) {
                int row = warp_m * 16 + hf * 8 + g;
#pragma unroll
                for (int h = 0; h < 4; h++) {
                    ared[warp_n][row][h]     = pa[hf][h];
                    ared[warp_n][row][4 + h] = pb[hf][h];
                }
            }
        }
        __syncthreads();
        for (int idx = tid; idx < 512; idx += 256) {
            int row = idx >> 3, o = idx & 7;
            int grow = m0 + row;
            if (grow < NN) {
                float s = ared[0][row][o] + ared[1][row][o];
                if (o < 4) g_as[grow * 4 + o] = s;
                else       g_ad[grow * 4 + (o - 4)] = s;
            }
        }
    }
}

// ---------------- pooling + TDA + trunk + task heads (fully fused) ----------------
__global__ __launch_bounds__(256) void k_head(const float* __restrict__ tda,
                                              const float* __restrict__ wt1, const float* __restrict__ bt1,
                                              const float* __restrict__ wt2, const float* __restrict__ bt2,
                                              const float* __restrict__ wsh1, const float* __restrict__ bsh1,
                                              const float* __restrict__ wsh2, const float* __restrict__ bsh2,
                                              const float* __restrict__ wh1,  const float* __restrict__ bh1,
                                              const float* __restrict__ wh2,  const float* __restrict__ bh2,
                                              float* __restrict__ out) {
    int g = blockIdx.x, tid = threadIdx.x;
    __shared__ float comb[320], s1[256], s2[128], hh1[NT * 64], th1[64];

    int beg = g_gstart[g], end = g_gstart[g + 1];
    int cntn = end - beg;
    {
        int d = tid & 127;
        if (tid < 128) {
            float s = 0.f;
            for (int i = beg; i < end; i++) s += g_h[i * DH + d];
            comb[d] = s / (float)(cntn > 0 ? cntn : 1);
        } else {
            float mx = -1e30f;
            for (int i = beg; i < end; i++) mx = fmaxf(mx, g_h[i * DH + d]);
            comb[128 + d] = (cntn > 0) ? mx : 0.f;
        }
    }
    __syncthreads();
    if (tid < 64) {
        float a = bt1[tid];
#pragma unroll
        for (int k = 0; k < FT; k++) a += tda[g * FT + k] * wt1[k * 64 + tid];
        th1[tid] = fmaxf(a, 0.f);
    }
    __syncthreads();
    if (tid < 64) {
        float c = bt2[tid];
#pragma unroll
        for (int k = 0; k < 64; k++) c += th1[k] * wt2[k * 64 + tid];
        comb[256 + tid] = fmaxf(c, 0.f);
    }
    __syncthreads();
    float a = bsh1[tid];
    for (int k = 0; k < 320; k++) a += comb[k] * wsh1[k * 256 + tid];
    s1[tid] = fmaxf(a, 0.f);
    __syncthreads();
    if (tid < 128) {
        float c = bsh2[tid];
        for (int k = 0; k < 256; k++) c += s1[k] * wsh2[k * 128 + tid];
        s2[tid] = fmaxf(c, 0.f);
    }
    __syncthreads();
    for (int idx = tid; idx < NT * 64; idx += 256) {
        int t = idx >> 6, kk = idx & 63;
        float c = bh1[t * 64 + kk];
        for (int k = 0; k < 128; k++) c += s2[k] * wh1[t * 8192 + k * 64 + kk];
        hh1[idx] = fmaxf(c, 0.f);
    }
    __syncthreads();
    if (tid < NT) {
        float c = bh2[tid];
        for (int k = 0; k < 64; k++) c += hh1[tid * 64 + k] * wh2[tid * 64 + k];
        out[tid * NGR + g] = c;
    }
}

// ---------------- launch ----------------
extern "C" void kernel_launch(void* const* d_in, const int* in_sizes, int n_in,
                              void* d_out, int out_size) {
    const float* x       = (const float*)d_in[0];
    const int*   ei      = (const int*)d_in[1];
    const int*   batch   = (const int*)d_in[2];
    const float* tda     = (const float*)d_in[3];
    const float* w_in    = (const float*)d_in[4];
    const float* b_in    = (const float*)d_in[5];
    const float* w_gat   = (const float*)d_in[6];
    const float* a_src   = (const float*)d_in[7];
    const float* a_dst   = (const float*)d_in[8];
    const float* b_gat   = (const float*)d_in[9];
    const float* ln_w    = (const float*)d_in[10];
    const float* ln_b    = (const float*)d_in[11];
    const float* w_tda1  = (const float*)d_in[12];
    const float* b_tda1  = (const float*)d_in[13];
    const float* w_tda2  = (const float*)d_in[14];
    const float* b_tda2  = (const float*)d_in[15];
    const float* w_sh1   = (const float*)d_in[16];
    const float* b_sh1   = (const float*)d_in[17];
    const float* w_sh2   = (const float*)d_in[18];
    const float* b_sh2   = (const float*)d_in[19];
    const float* w_h1    = (const float*)d_in[20];
    const float* b_h1    = (const float*)d_in[21];
    const float* w_h2    = (const float*)d_in[22];
    const float* b_h2    = (const float*)d_in[23];
    float* out = (float*)d_out;

    const int ROWS64_GRID = (NN + 63) / 64;   // 313
    const int ALPHA_GRID  = (NN + 1) / 2;     // 10000

    k_pre<<<PRE_TOTAL_BLOCKS, 256>>>(x, w_in, b_in, w_gat, a_src, a_dst, batch);  // 0
    k_count<<<(ETOT + 255) / 256, 256>>>(ei);                                     // 1
    k_scan<<<1, 1024>>>();                                                        // 2
    k_alpha<<<ALPHA_GRID, 256>>>(0);                                              // 3 (profiled)
    k_scatter<<<(ETOT + 255) / 256, 256>>>(ei);                                   // 4

    for (int l = 0; l < NL; l++) {
        k_agg<<<NN, 128>>>();
        k_gemm2<<<ROWS64_GRID, 256>>>(l, l + 1,
                                      b_gat + l * 128, ln_w + l * 128, ln_b + l * 128);
    }

    k_head<<<NGR, 256>>>(tda, w_tda1, b_tda1, w_tda2, b_tda2,
                         w_sh1, b_sh1, w_sh2, b_sh2, w_h1, b_h1, w_h2, b_h2, out);
}

// round 15
// speedup vs baseline: 1.2661x; 1.0689x over previous
#include <cuda_runtime.h>
#include <cuda_bf16.h>
#include <math.h>

#define NN   20000        // nodes
#define NE   320000       // edges (without self loops)
#define ETOT (NE + NN)    // edges + self loops
#define NGR  256          // graphs
#define FD   11           // node feature dim
#define FT   30           // tda feature dim
#define DH   128          // hidden
#define NH   4            // heads
#define NL   3            // layers
#define NT   6            // tasks

#define APAD 40           // A smem row length (32 k + 8 pad) in bf16
#define BPAD 136          // B smem row length (128 n + 8 pad) in bf16

// ---------------- device scratch (static, no allocations) ----------------
// Referenced ONLY inside kernels — never passed as kernel arguments.
// alignas(16): several arrays are accessed via float4/uint4 — device globals
// only guarantee type alignment, so force 16B explicitly.
__device__ alignas(16) float         g_h[NN * DH];            // node features (in-place updated)
__device__ alignas(16) __nv_bfloat16 g_agg_hi[NN * 512];      // aggregated features bf16 hi
__device__ alignas(16) __nv_bfloat16 g_agg_lo[NN * 512];      // aggregated features bf16 lo
__device__ alignas(16) __nv_bfloat16 g_wstk_hi[NL * 512 * DH];// stacked (W_h/4) bf16 hi
__device__ alignas(16) __nv_bfloat16 g_wstk_lo[NL * 512 * DH];
__device__ alignas(16) float         g_vs[NL * NH * DH];      // projected a_src vectors
__device__ alignas(16) float         g_vd[NL * NH * DH];      // projected a_dst vectors
__device__ alignas(16) float         g_as[NN * NH];           // alpha_src per node/head
__device__ alignas(16) float         g_ad[NN * NH];           // alpha_dst per node/head
__device__ int           g_rowptr[NN + 1];
__device__ int           g_cnt[NN];               // counts, then scatter cursor
__device__ int           g_esrc[ETOT];            // src ids sorted by dst
__device__ int           g_gstart[NGR + 1];

// ---------------- bf16 mma helpers ----------------
__device__ __forceinline__ void mma_bf16(float c[4], const unsigned a[4], const unsigned* b) {
    asm volatile(
        "mma.sync.aligned.m16n8k16.row.col.f32.bf16.bf16.f32 "
        "{%0,%1,%2,%3}, {%4,%5,%6,%7}, {%8,%9}, {%0,%1,%2,%3};\n"
        : "+f"(c[0]), "+f"(c[1]), "+f"(c[2]), "+f"(c[3])
        : "r"(a[0]), "r"(a[1]), "r"(a[2]), "r"(a[3]), "r"(b[0]), "r"(b[1]));
}

__device__ __forceinline__ void ldsm_x4(unsigned r[4], unsigned saddr) {
    asm volatile("ldmatrix.sync.aligned.m8n8.x4.shared.b16 {%0,%1,%2,%3}, [%4];"
        : "=r"(r[0]), "=r"(r[1]), "=r"(r[2]), "=r"(r[3]) : "r"(saddr));
}

__device__ __forceinline__ void ldsm_x4_t(unsigned r[4], unsigned saddr) {
    asm volatile("ldmatrix.sync.aligned.m8n8.x4.trans.shared.b16 {%0,%1,%2,%3}, [%4];"
        : "=r"(r[0]), "=r"(r[1]), "=r"(r[2]), "=r"(r[3]) : "r"(saddr));
}

// ---------------- fused pre-pass ----------------
// segments: Wstack split | v-projection (warp per output) | CSR prep
#define PRE_WSTK_BLOCKS   ((NL * 512 * DH + 255) / 256)   // 768
#define PRE_V_BLOCKS      ((NL * 2 * NH * DH) / 8)        // 384 (8 warps/block, warp per output)
#define PRE_PREP_BLOCKS   ((NN + 256) / 256)              // 79
#define PRE_TOTAL_BLOCKS  (PRE_WSTK_BLOCKS + PRE_V_BLOCKS + PRE_PREP_BLOCKS)

__global__ __launch_bounds__(256) void k_pre(const float* __restrict__ wg,
                                             const float* __restrict__ a_src,
                                             const float* __restrict__ a_dst,
                                             const int* __restrict__ batch) {
    int bid = blockIdx.x;
    if (bid < PRE_WSTK_BLOCKS) {
        int i = bid * 256 + threadIdx.x;
        if (i < NL * 512 * DH) {
            int l = i >> 16;             // 512*128 = 65536
            int r = (i >> 7) & 511;      // stacked row = h*128 + kd
            int d = i & 127;
            int h = r >> 7, kd = r & 127;
            float v = 0.25f * wg[l * 65536 + kd * 512 + h * 128 + d];
            __nv_bfloat16 hi = __float2bfloat16_rn(v);
            g_wstk_hi[i] = hi;
            g_wstk_lo[i] = __float2bfloat16_rn(v - __bfloat162float(hi));
        }
    } else if (bid < PRE_WSTK_BLOCKS + PRE_V_BLOCKS) {
        // warp per output: j over NL*2*NH*DH = 3072; lane = one float4 of the 128-dot
        int bl = bid - PRE_WSTK_BLOCKS;
        int wid = threadIdx.x >> 5, lane = threadIdx.x & 31;
        int j = bl * 8 + wid;            // [0, 3072)
        int l    = j >> 10;              // 1024 outputs per layer (2 halves x 512)
        int rem  = j & 1023;
        int half = rem >> 9;
        int hk   = rem & 511;
        int h = hk >> 7, k = hk & 127;
        const float* av = half ? a_dst : a_src;
        float4 w4 = *(const float4*)&wg[l * 65536 + k * 512 + h * 128 + lane * 4];
        float4 a4 = *(const float4*)&av[l * 512 + h * 128 + lane * 4];
        float s = w4.x * a4.x + w4.y * a4.y + w4.z * a4.z + w4.w * a4.w;
#pragma unroll
        for (int off = 16; off > 0; off >>= 1) s += __shfl_xor_sync(0xffffffffu, s, off);
        if (lane == 0) {
            if (half) g_vd[l * 512 + hk] = s;
            else      g_vs[l * 512 + hk] = s;
        }
    } else {
        int i = (bid - PRE_WSTK_BLOCKS - PRE_V_BLOCKS) * 256 + threadIdx.x;
        if (i < NN) g_cnt[i] = 0;
        if (i <= NN) {
            int bb = (i < NN) ? batch[i] : NGR;
            int bp = (i > 0) ? batch[i - 1] : -1;
            for (int g = bp + 1; g <= bb && g <= NGR; g++) g_gstart[g] = i;
        }
    }
}

// ---------------- CSR build ----------------
__global__ void k_count(const int* __restrict__ ei) {
    int i = blockIdx.x * blockDim.x + threadIdx.x;
    if (i >= ETOT) return;
    int dst = (i < NE) ? ei[NE + i] : (i - NE);
    atomicAdd(&g_cnt[dst], 1);
}

__global__ void k_scan() {   // single block, 1024 threads, chunk=20; also writes cursor
    __shared__ int ssum[1024];
    const int CH = 20;
    int tid = threadIdx.x;
    int base = tid * CH;
    int s = 0;
    for (int j = 0; j < CH; j++) {
        int idx = base + j;
        if (idx < NN) s += g_cnt[idx];
    }
    ssum[tid] = s;
    __syncthreads();
    for (int off = 1; off < 1024; off <<= 1) {
        int v = 0;
        if (tid >= off) v = ssum[tid - off];
        __syncthreads();
        ssum[tid] += v;
        __syncthreads();
    }
    int run = tid ? ssum[tid - 1] : 0;
    for (int j = 0; j < CH; j++) {
        int idx = base + j;
        if (idx < NN) {
            int c = g_cnt[idx];
            g_rowptr[idx] = run;
            g_cnt[idx]    = run;   // scatter cursor
            run += c;
        }
    }
    if (tid == 1023) g_rowptr[NN] = ssum[1023];
}

__global__ void k_scatter(const int* __restrict__ ei) {
    int i = blockIdx.x * blockDim.x + threadIdx.x;
    if (i >= ETOT) return;
    int src, dst;
    if (i < NE) { src = ei[i]; dst = ei[NE + i]; }
    else        { src = i - NE; dst = i - NE; }
    int pos = atomicAdd(&g_cnt[dst], 1);
    g_esrc[pos] = src;
}

// ---------------- input projection + layer-0 alpha logits (fused) ----------------
// grid 10000, 256 threads: 2 nodes/block, thread = (node, dim). Requires g_vs/g_vd[0] ready.
__global__ __launch_bounds__(256) void k_inproj(const float* __restrict__ x,
                                                const float* __restrict__ w,
                                                const float* __restrict__ b) {
    __shared__ float xs[2][FD];
    __shared__ alignas(16) float sv[1024];  // [0:512) = vs(layer0), [512:1024) = vd(layer0)
    __shared__ float red[8][8];             // [warp][p-index]
    int tid = threadIdx.x;
    int local = tid >> 7;             // 0/1
    int d = tid & 127;
    int n = blockIdx.x * 2 + local;   // always < NN (grid exact)
    {
        float4 v4;
        if (tid < 128) v4 = *(const float4*)&g_vs[tid * 4];
        else           v4 = *(const float4*)&g_vd[(tid - 128) * 4];
        *(float4*)&sv[tid * 4] = v4;
    }
    if (d < FD) xs[local][d] = x[n * FD + d];
    __syncthreads();
    float a = b[d];
#pragma unroll
    for (int k = 0; k < FD; k++) a += xs[local][k] * w[k * DH + d];
    float hv = fmaxf(a, 0.f);
    g_h[n * DH + d] = hv;

    // layer-0 alpha logits from the fresh h value
    float p[8];
#pragma unroll
    for (int h = 0; h < 4; h++) {
        p[h]     = hv * sv[h * 128 + d];
        p[4 + h] = hv * sv[512 + h * 128 + d];
    }
#pragma unroll
    for (int off = 16; off > 0; off >>= 1)
#pragma unroll
        for (int i = 0; i < 8; i++) p[i] += __shfl_xor_sync(0xffffffffu, p[i], off);
    int wid = tid >> 5, lane = tid & 31;
    if (lane == 0) {
#pragma unroll
        for (int i = 0; i < 8; i++) red[wid][i] = p[i];
    }
    __syncthreads();
    if (tid < 16) {
        int ln = tid >> 3, i = tid & 7;
        float s = red[ln * 4 + 0][i] + red[ln * 4 + 1][i] + red[ln * 4 + 2][i] + red[ln * 4 + 3][i];
        int nn = blockIdx.x * 2 + ln;
        if (i < 4) g_as[nn * 4 + i] = s;
        else       g_ad[nn * 4 + (i - 4)] = s;
    }
}

// ---------------- GAT aggregation in input space — warp per node ----------------
// 4 nodes/block (grid exactly 5000), no block barriers. Lane = float4 of dims.
__global__ __launch_bounds__(128) void k_agg() {
    int tid = threadIdx.x;
    int wid = tid >> 5, lane = tid & 31;
    int node = blockIdx.x * 4 + wid;   // < NN always (20000/4 = 5000 exact)
    int beg = g_rowptr[node], end = g_rowptr[node + 1];
    float4 ad4 = *(const float4*)&g_ad[node * 4];

    // pass 1: online softmax for 4 heads, lane-strided edges
    float m0 = -1e30f, m1 = -1e30f, m2 = -1e30f, m3 = -1e30f;
    float s0 = 0.f, s1 = 0.f, s2 = 0.f, s3 = 0.f;
    for (int e = beg + lane; e < end; e += 32) {
        int src = g_esrc[e];
        float4 as4 = *(const float4*)&g_as[src * 4];
        float x0 = as4.x + ad4.x; x0 = x0 > 0.f ? x0 : 0.2f * x0;
        float x1 = as4.y + ad4.y; x1 = x1 > 0.f ? x1 : 0.2f * x1;
        float x2 = as4.z + ad4.z; x2 = x2 > 0.f ? x2 : 0.2f * x2;
        float x3 = as4.w + ad4.w; x3 = x3 > 0.f ? x3 : 0.2f * x3;
        float nm;
        nm = fmaxf(m0, x0); s0 = s0 * __expf(m0 - nm) + __expf(x0 - nm); m0 = nm;
        nm = fmaxf(m1, x1); s1 = s1 * __expf(m1 - nm) + __expf(x1 - nm); m1 = nm;
        nm = fmaxf(m2, x2); s2 = s2 * __expf(m2 - nm) + __expf(x2 - nm); m2 = nm;
        nm = fmaxf(m3, x3); s3 = s3 * __expf(m3 - nm) + __expf(x3 - nm); m3 = nm;
    }
#pragma unroll
    for (int off = 16; off > 0; off >>= 1) {
        float mo, so, nm;
        mo = __shfl_xor_sync(0xffffffffu, m0, off); so = __shfl_xor_sync(0xffffffffu, s0, off);
        nm = fmaxf(m0, mo); s0 = s0 * __expf(m0 - nm) + so * __expf(mo - nm); m0 = nm;
        mo = __shfl_xor_sync(0xffffffffu, m1, off); so = __shfl_xor_sync(0xffffffffu, s1, off);
        nm = fmaxf(m1, mo); s1 = s1 * __expf(m1 - nm) + so * __expf(mo - nm); m1 = nm;
        mo = __shfl_xor_sync(0xffffffffu, m2, off); so = __shfl_xor_sync(0xffffffffu, s2, off);
        nm = fmaxf(m2, mo); s2 = s2 * __expf(m2 - nm) + so * __expf(mo - nm); m2 = nm;
        mo = __shfl_xor_sync(0xffffffffu, m3, off); so = __shfl_xor_sync(0xffffffffu, s3, off);
        nm = fmaxf(m3, mo); s3 = s3 * __expf(m3 - nm) + so * __expf(mo - nm); m3 = nm;
    }
    float i0 = 1.f / s0, i1 = 1.f / s1, i2 = 1.f / s2, i3 = 1.f / s3;

    // pass 2: chunked; lane loads (src, w4) for edge base+lane, shfl-broadcast per edge.
    float4 acc0 = {0.f,0.f,0.f,0.f}, acc1 = acc0, acc2 = acc0, acc3 = acc0;
    int dimoff = lane * 4;
    for (int base = beg; base < end; base += 32) {
        int cnt = end - base; if (cnt > 32) cnt = 32;
        int src = 0; float4 w4 = {0.f,0.f,0.f,0.f};
        if (lane < cnt) {
            src = g_esrc[base + lane];
            float4 as4 = *(const float4*)&g_as[src * 4];
            float x0 = as4.x + ad4.x; x0 = x0 > 0.f ? x0 : 0.2f * x0;
            float x1 = as4.y + ad4.y; x1 = x1 > 0.f ? x1 : 0.2f * x1;
            float x2 = as4.z + ad4.z; x2 = x2 > 0.f ? x2 : 0.2f * x2;
            float x3 = as4.w + ad4.w; x3 = x3 > 0.f ? x3 : 0.2f * x3;
            w4.x = __expf(x0 - m0) * i0;
            w4.y = __expf(x1 - m1) * i1;
            w4.z = __expf(x2 - m2) * i2;
            w4.w = __expf(x3 - m3) * i3;
        }
        for (int j = 0; j < cnt; j++) {
            int  sj = __shfl_sync(0xffffffffu, src, j);
            float wx = __shfl_sync(0xffffffffu, w4.x, j);
            float wy = __shfl_sync(0xffffffffu, w4.y, j);
            float wz = __shfl_sync(0xffffffffu, w4.z, j);
            float ww = __shfl_sync(0xffffffffu, w4.w, j);
            float4 hv = *(const float4*)&g_h[sj * DH + dimoff];
            acc0.x += wx * hv.x; acc0.y += wx * hv.y; acc0.z += wx * hv.z; acc0.w += wx * hv.w;
            acc1.x += wy * hv.x; acc1.y += wy * hv.y; acc1.z += wy * hv.z; acc1.w += wy * hv.w;
            acc2.x += wz * hv.x; acc2.y += wz * hv.y; acc2.z += wz * hv.z; acc2.w += wz * hv.w;
            acc3.x += ww * hv.x; acc3.y += ww * hv.y; acc3.z += ww * hv.z; acc3.w += ww * hv.w;
        }
    }

    // store bf16 split: head hh at [node*512 + hh*128 + lane*4], 4 bf16 = 8 bytes
#pragma unroll
    for (int hh = 0; hh < 4; hh++) {
        float4 v = (hh == 0) ? acc0 : (hh == 1) ? acc1 : (hh == 2) ? acc2 : acc3;
        __nv_bfloat162 hA, hB, lA, lB;
        hA.x = __float2bfloat16_rn(v.x); hA.y = __float2bfloat16_rn(v.y);
        hB.x = __float2bfloat16_rn(v.z); hB.y = __float2bfloat16_rn(v.w);
        lA.x = __float2bfloat16_rn(v.x - __bfloat162float(hA.x));
        lA.y = __float2bfloat16_rn(v.y - __bfloat162float(hA.y));
        lB.x = __float2bfloat16_rn(v.z - __bfloat162float(hB.x));
        lB.y = __float2bfloat16_rn(v.w - __bfloat162float(hB.y));
        int ob = node * 512 + hh * 128 + dimoff;
        *(__nv_bfloat162*)&g_agg_hi[ob]     = hA;
        *(__nv_bfloat162*)&g_agg_hi[ob + 2] = hB;
        *(__nv_bfloat162*)&g_agg_lo[ob]     = lA;
        *(__nv_bfloat162*)&g_agg_lo[ob + 2] = lB;
    }
}

// ---------------- post-GEMM: h_new = relu(LN(agg @ Wstack + bias)) + h_old ----------------
// M-tile 64, grid 313, 256 threads = 8 warps (4 warp_m x 16 rows, 2 warp_n x 64 cols).
// If next_layer < NL, also computes next layer's alpha logits from the fresh h values.
__global__ __launch_bounds__(256, 3) void k_gemm2(int layer, int next_layer,
                                                  const float* __restrict__ bg,
                                                  const float* __restrict__ lnw,
                                                  const float* __restrict__ lnb) {
    __shared__ alignas(16) __nv_bfloat16 As_h[64][APAD], As_l[64][APAD];     // [m][k]
    __shared__ alignas(16) __nv_bfloat16 Bs_h[32][BPAD],  Bs_l[32][BPAD];    // [k][n]
    __shared__ float rsum[2][64], rsq[2][64];
    __shared__ float s_bg[128], s_lnw[128], s_lnb[128];
    __shared__ float sv[1024];          // next layer's vs|vd (staged iff next_layer < NL)
    __shared__ float ared[2][64][8];    // alpha partials [warp_n][row][out]

    int tid = threadIdx.x;
    int wid = tid >> 5, lane = tid & 31;
    int warp_m = wid & 3, warp_n = wid >> 2;
    int m0 = blockIdx.x * 64;
    int g  = lane >> 2, t = lane & 3;
    bool do_alpha = (next_layer < NL);
    const __nv_bfloat16* Bh = g_wstk_hi + layer * 512 * DH;
    const __nv_bfloat16* Bl = g_wstk_lo + layer * 512 * DH;

    if (tid < 128) { s_bg[tid] = bg[tid]; s_lnw[tid] = lnw[tid]; s_lnb[tid] = lnb[tid]; }
    if (do_alpha) {
        for (int i = tid; i < 512; i += 256) {
            sv[i]       = g_vs[next_layer * 512 + i];
            sv[512 + i] = g_vd[next_layer * 512 + i];
        }
    }

    float c[8][4];
#pragma unroll
    for (int nt = 0; nt < 8; nt++)
#pragma unroll
        for (int i = 0; i < 4; i++) c[nt][i] = 0.f;

    int ar  = tid >> 2, akg = (tid & 3) * 8;     // A: 64 rows, 8 bf16 (1 uint4) per thread
    int bkr = tid >> 3, bcg = (tid & 7) * 16;    // B: 32 rows, 16 bf16 (2 uint4) per thread

    int lrow = (lane & 7) + ((lane >> 3) & 1) * 8;
    int lcol = (lane >> 4) * 8;
    unsigned sAh = (unsigned)__cvta_generic_to_shared(As_h);
    unsigned sAl = (unsigned)__cvta_generic_to_shared(As_l);
    unsigned sBh = (unsigned)__cvta_generic_to_shared(Bs_h);
    unsigned sBl = (unsigned)__cvta_generic_to_shared(Bs_l);

    for (int kc = 0; kc < 512; kc += 32) {
        __syncthreads();
        {
            bool ok = (m0 + ar < NN);
            uint4 z = make_uint4(0u, 0u, 0u, 0u);
            const uint4* ph = (const uint4*)&g_agg_hi[(m0 + ar) * 512 + kc + akg];
            const uint4* pl = (const uint4*)&g_agg_lo[(m0 + ar) * 512 + kc + akg];
            *(uint4*)&As_h[ar][akg] = ok ? ph[0] : z;
            *(uint4*)&As_l[ar][akg] = ok ? pl[0] : z;
        }
        {
            const uint4* ph = (const uint4*)&Bh[(kc + bkr) * 128 + bcg];
            const uint4* pl = (const uint4*)&Bl[(kc + bkr) * 128 + bcg];
            uint4 h0 = ph[0], h1 = ph[1];
            uint4 l0 = pl[0], l1 = pl[1];
            *(uint4*)&Bs_h[bkr][bcg]     = h0;
            *(uint4*)&Bs_h[bkr][bcg + 8] = h1;
            *(uint4*)&Bs_l[bkr][bcg]     = l0;
            *(uint4*)&Bs_l[bkr][bcg + 8] = l1;
        }
        __syncthreads();

#pragma unroll
        for (int kk = 0; kk < 32; kk += 16) {
            unsigned ah[4], al[4];
            unsigned off = (unsigned)(((warp_m * 16 + lrow) * APAD + kk + lcol) * 2);
            ldsm_x4(ah, sAh + off);
            ldsm_x4(al, sAl + off);
#pragma unroll
            for (int p = 0; p < 4; p++) {
                unsigned boff = (unsigned)(((kk + lrow) * BPAD + warp_n * 64 + p * 16 + lcol) * 2);
                unsigned bh[4], bl[4];
                ldsm_x4_t(bh, sBh + boff);
                ldsm_x4_t(bl, sBl + boff);
#pragma unroll
                for (int q = 0; q < 2; q++) {
                    float* cc = c[p * 2 + q];
                    mma_bf16(cc, ah, &bh[q * 2]);
                    mma_bf16(cc, ah, &bl[q * 2]);
                    mma_bf16(cc, al, &bh[q * 2]);
                }
            }
        }
    }
    __syncthreads();

    // epilogue: bias, per-row LN stats, normalize, relu, residual, write g_h (+ fused alpha)
#pragma unroll
    for (int nt = 0; nt < 8; nt++) {
        int col = warp_n * 64 + nt * 8 + t * 2;
        c[nt][0] += s_bg[col];
        c[nt][1] += s_bg[col + 1];
        c[nt][2] += s_bg[col];
        c[nt][3] += s_bg[col + 1];
    }
    float sum[2] = {0.f, 0.f}, sq[2] = {0.f, 0.f};
#pragma unroll
    for (int nt = 0; nt < 8; nt++) {
        float c0 = c[nt][0], c1 = c[nt][1], c2 = c[nt][2], c3 = c[nt][3];
        sum[0] += c0 + c1;  sq[0] += c0 * c0 + c1 * c1;
        sum[1] += c2 + c3;  sq[1] += c2 * c2 + c3 * c3;
    }
#pragma unroll
    for (int off = 1; off <= 2; off <<= 1)
#pragma unroll
        for (int i = 0; i < 2; i++) {
            sum[i] += __shfl_xor_sync(0xffffffffu, sum[i], off);
            sq[i]  += __shfl_xor_sync(0xffffffffu, sq[i],  off);
        }
    if (t == 0) {
#pragma unroll
        for (int hf = 0; hf < 2; hf++) {
            int row = warp_m * 16 + hf * 8 + g;
            rsum[warp_n][row] = sum[hf];
            rsq[warp_n][row]  = sq[hf];
        }
    }
    __syncthreads();

    float pa[2][4] = {{0.f,0.f,0.f,0.f},{0.f,0.f,0.f,0.f}};   // alpha_src partials per hf
    float pb[2][4] = {{0.f,0.f,0.f,0.f},{0.f,0.f,0.f,0.f}};   // alpha_dst partials per hf

#pragma unroll
    for (int hf = 0; hf < 2; hf++) {
        int row = warp_m * 16 + hf * 8 + g;
        int grow = m0 + row;
        if (grow >= NN) continue;
        float S = rsum[0][row] + rsum[1][row];
        float Q = rsq[0][row] + rsq[1][row];
        float mu  = S * (1.f / 128.f);
        float var = Q * (1.f / 128.f) - mu * mu;
        float rstd = rsqrtf(var + 1e-5f);
#pragma unroll
        for (int nt = 0; nt < 8; nt++) {
            int col = warp_n * 64 + nt * 8 + t * 2;
            float c0 = c[nt][hf * 2 + 0];
            float c1 = c[nt][hf * 2 + 1];
            float2 hold = *(const float2*)&g_h[grow * DH + col];
            float v0 = (c0 - mu) * rstd * s_lnw[col]     + s_lnb[col];
            float v1 = (c1 - mu) * rstd * s_lnw[col + 1] + s_lnb[col + 1];
            float nv0 = fmaxf(v0, 0.f) + hold.x;
            float nv1 = fmaxf(v1, 0.f) + hold.y;
            *(float2*)&g_h[grow * DH + col] = make_float2(nv0, nv1);
            if (do_alpha) {
#pragma unroll
                for (int h = 0; h < 4; h++) {
                    pa[hf][h] += nv0 * sv[h * 128 + col]       + nv1 * sv[h * 128 + col + 1];
                    pb[hf][h] += nv0 * sv[512 + h * 128 + col] + nv1 * sv[512 + h * 128 + col + 1];
                }
            }
        }
    }

    if (do_alpha) {
#pragma unroll
        for (int off = 1; off <= 2; off <<= 1)
#pragma unroll
            for (int hf = 0; hf < 2; hf++)
#pragma unroll
                for (int h = 0; h < 4; h++) {
                    pa[hf][h] += __shfl_xor_sync(0xffffffffu, pa[hf][h], off);
                    pb[hf][h] += __shfl_xor_sync(0xffffffffu, pb[hf][h], off);
                }
        if (t == 0) {
#pragma unroll
            for (int hf = 0; hf < 2; hf++) {
                int row = warp_m * 16 + hf * 8 + g;
#pragma unroll
                for (int h = 0; h < 4; h++) {
                    ared[warp_n][row][h]     = pa[hf][h];
                    ared[warp_n][row][4 + h] = pb[hf][h];
                }
            }
        }
        __syncthreads();
        for (int idx = tid; idx < 512; idx += 256) {
            int row = idx >> 3, o = idx & 7;
            int grow = m0 + row;
            if (grow < NN) {
                float s = ared[0][row][o] + ared[1][row][o];
                if (o < 4) g_as[grow * 4 + o] = s;
                else       g_ad[grow * 4 + (o - 4)] = s;
            }
        }
    }
}

// ---------------- pooling + TDA + trunk + task heads (fully fused) ----------------
__global__ __launch_bounds__(256) void k_head(const float* __restrict__ tda,
                                              const float* __restrict__ wt1, const float* __restrict__ bt1,
                                              const float* __restrict__ wt2, const float* __restrict__ bt2,
                                              const float* __restrict__ wsh1, const float* __restrict__ bsh1,
                                              const float* __restrict__ wsh2, const float* __restrict__ bsh2,
                                              const float* __restrict__ wh1,  const float* __restrict__ bh1,
                                              const float* __restrict__ wh2,  const float* __restrict__ bh2,
                                              float* __restrict__ out) {
    int g = blockIdx.x, tid = threadIdx.x;
    __shared__ float comb[320], s1[256], s2[128], hh1[NT * 64], th1[64];

    int beg = g_gstart[g], end = g_gstart[g + 1];
    int cntn = end - beg;
    {
        int d = tid & 127;
        if (tid < 128) {
            float s = 0.f;
            for (int i = beg; i < end; i++) s += g_h[i * DH + d];
            comb[d] = s / (float)(cntn > 0 ? cntn : 1);
        } else {
            float mx = -1e30f;
            for (int i = beg; i < end; i++) mx = fmaxf(mx, g_h[i * DH + d]);
            comb[128 + d] = (cntn > 0) ? mx : 0.f;
        }
    }
    __syncthreads();
    if (tid < 64) {
        float a = bt1[tid];
#pragma unroll
        for (int k = 0; k < FT; k++) a += tda[g * FT + k] * wt1[k * 64 + tid];
        th1[tid] = fmaxf(a, 0.f);
    }
    __syncthreads();
    if (tid < 64) {
        float c = bt2[tid];
#pragma unroll
        for (int k = 0; k < 64; k++) c += th1[k] * wt2[k * 64 + tid];
        comb[256 + tid] = fmaxf(c, 0.f);
    }
    __syncthreads();
    float a = bsh1[tid];
    for (int k = 0; k < 320; k++) a += comb[k] * wsh1[k * 256 + tid];
    s1[tid] = fmaxf(a, 0.f);
    __syncthreads();
    if (tid < 128) {
        float c = bsh2[tid];
        for (int k = 0; k < 256; k++) c += s1[k] * wsh2[k * 128 + tid];
        s2[tid] = fmaxf(c, 0.f);
    }
    __syncthreads();
    for (int idx = tid; idx < NT * 64; idx += 256) {
        int t = idx >> 6, kk = idx & 63;
        float c = bh1[t * 64 + kk];
        for (int k = 0; k < 128; k++) c += s2[k] * wh1[t * 8192 + k * 64 + kk];
        hh1[idx] = fmaxf(c, 0.f);
    }
    __syncthreads();
    if (tid < NT) {
        float c = bh2[tid];
        for (int k = 0; k < 64; k++) c += hh1[tid * 64 + k] * wh2[tid * 64 + k];
        out[tid * NGR + g] = c;
    }
}

// ---------------- launch ----------------
extern "C" void kernel_launch(void* const* d_in, const int* in_sizes, int n_in,
                              void* d_out, int out_size) {
    const float* x       = (const float*)d_in[0];
    const int*   ei      = (const int*)d_in[1];
    const int*   batch   = (const int*)d_in[2];
    const float* tda     = (const float*)d_in[3];
    const float* w_in    = (const float*)d_in[4];
    const float* b_in    = (const float*)d_in[5];
    const float* w_gat   = (const float*)d_in[6];
    const float* a_src   = (const float*)d_in[7];
    const float* a_dst   = (const float*)d_in[8];
    const float* b_gat   = (const float*)d_in[9];
    const float* ln_w    = (const float*)d_in[10];
    const float* ln_b    = (const float*)d_in[11];
    const float* w_tda1  = (const float*)d_in[12];
    const float* b_tda1  = (const float*)d_in[13];
    const float* w_tda2  = (const float*)d_in[14];
    const float* b_tda2  = (const float*)d_in[15];
    const float* w_sh1   = (const float*)d_in[16];
    const float* b_sh1   = (const float*)d_in[17];
    const float* w_sh2   = (const float*)d_in[18];
    const float* b_sh2   = (const float*)d_in[19];
    const float* w_h1    = (const float*)d_in[20];
    const float* b_h1    = (const float*)d_in[21];
    const float* w_h2    = (const float*)d_in[22];
    const float* b_h2    = (const float*)d_in[23];
    float* out = (float*)d_out;

    const int ROWS64_GRID = (NN + 63) / 64;   // 313

    k_pre<<<PRE_TOTAL_BLOCKS, 256>>>(w_gat, a_src, a_dst, batch);   // 0
    k_count<<<(ETOT + 255) / 256, 256>>>(ei);                        // 1
    k_scan<<<1, 1024>>>();                                           // 2
    k_inproj<<<NN / 2, 256>>>(x, w_in, b_in);                        // 3 (profiled; needs g_vs/g_vd from 0)
    k_scatter<<<(ETOT + 255) / 256, 256>>>(ei);                      // 4

    for (int l = 0; l < NL; l++) {
        k_agg<<<NN / 4, 128>>>();
        k_gemm2<<<ROWS64_GRID, 256>>>(l, l + 1,
                                      b_gat + l * 128, ln_w + l * 128, ln_b + l * 128);
    }

    k_head<<<NGR, 256>>>(tda, w_tda1, b_tda1, w_tda2, b_tda2,
                         w_sh1, b_sh1, w_sh2, b_sh2, w_h1, b_h1, w_h2, b_h2, out);
}

// round 16
// speedup vs baseline: 1.2745x; 1.0066x over previous
#include <cuda_runtime.h>
#include <cuda_bf16.h>
#include <math.h>

#define NN   20000        // nodes
#define NE   320000       // edges (without self loops)
#define ETOT (NE + NN)    // edges + self loops
#define NGR  256          // graphs
#define FD   11           // node feature dim
#define FT   30           // tda feature dim
#define DH   128          // hidden
#define NH   4            // heads
#define NL   3            // layers
#define NT   6            // tasks

#define APAD 40           // A smem row length (32 k + 8 pad) in bf16
#define BPAD 136          // B smem row length (128 n + 8 pad) in bf16

// ---------------- device scratch (static, no allocations) ----------------
// Referenced ONLY inside kernels — never passed as kernel arguments.
__device__ alignas(16) float         g_h[NN * DH];            // node features (in-place updated)
__device__ alignas(16) __nv_bfloat16 g_agg_hi[NN * 512];      // aggregated features bf16 hi
__device__ alignas(16) __nv_bfloat16 g_agg_lo[NN * 512];      // aggregated features bf16 lo
__device__ alignas(16) __nv_bfloat16 g_wstk_hi[NL * 512 * DH];// stacked (W_h/4) bf16 hi
__device__ alignas(16) __nv_bfloat16 g_wstk_lo[NL * 512 * DH];
__device__ alignas(16) float         g_vs[NL * NH * DH];      // projected a_src vectors
__device__ alignas(16) float         g_vd[NL * NH * DH];      // projected a_dst vectors
__device__ alignas(16) float         g_as[NN * NH];           // alpha_src per node/head
__device__ alignas(16) float         g_ad[NN * NH];           // alpha_dst per node/head
__device__ int           g_rowptr[NN + 1];
__device__ int           g_cnt[NN];               // counts, then scatter cursor
__device__ int           g_esrc[ETOT];            // src ids sorted by dst
__device__ int           g_gstart[NGR + 1];

// ---------------- bf16 mma helpers ----------------
__device__ __forceinline__ void mma_bf16(float c[4], const unsigned a[4], const unsigned* b) {
    asm volatile(
        "mma.sync.aligned.m16n8k16.row.col.f32.bf16.bf16.f32 "
        "{%0,%1,%2,%3}, {%4,%5,%6,%7}, {%8,%9}, {%0,%1,%2,%3};\n"
        : "+f"(c[0]), "+f"(c[1]), "+f"(c[2]), "+f"(c[3])
        : "r"(a[0]), "r"(a[1]), "r"(a[2]), "r"(a[3]), "r"(b[0]), "r"(b[1]));
}

__device__ __forceinline__ void ldsm_x4(unsigned r[4], unsigned saddr) {
    asm volatile("ldmatrix.sync.aligned.m8n8.x4.shared.b16 {%0,%1,%2,%3}, [%4];"
        : "=r"(r[0]), "=r"(r[1]), "=r"(r[2]), "=r"(r[3]) : "r"(saddr));
}

__device__ __forceinline__ void ldsm_x4_t(unsigned r[4], unsigned saddr) {
    asm volatile("ldmatrix.sync.aligned.m8n8.x4.trans.shared.b16 {%0,%1,%2,%3}, [%4];"
        : "=r"(r[0]), "=r"(r[1]), "=r"(r[2]), "=r"(r[3]) : "r"(saddr));
}

// ---------------- fused pre-pass ----------------
// segments: Wstack split | v-projection (warp per output) | CSR prep
#define PRE_WSTK_BLOCKS   ((NL * 512 * DH + 255) / 256)   // 768
#define PRE_V_BLOCKS      ((NL * 2 * NH * DH) / 8)        // 384 (8 warps/block, warp per output)
#define PRE_PREP_BLOCKS   ((NN + 256) / 256)              // 79
#define PRE_TOTAL_BLOCKS  (PRE_WSTK_BLOCKS + PRE_V_BLOCKS + PRE_PREP_BLOCKS)

__global__ __launch_bounds__(256) void k_pre(const float* __restrict__ wg,
                                             const float* __restrict__ a_src,
                                             const float* __restrict__ a_dst,
                                             const int* __restrict__ batch) {
    int bid = blockIdx.x;
    if (bid < PRE_WSTK_BLOCKS) {
        int i = bid * 256 + threadIdx.x;
        if (i < NL * 512 * DH) {
            int l = i >> 16;             // 512*128 = 65536
            int r = (i >> 7) & 511;      // stacked row = h*128 + kd
            int d = i & 127;
            int h = r >> 7, kd = r & 127;
            float v = 0.25f * wg[l * 65536 + kd * 512 + h * 128 + d];
            __nv_bfloat16 hi = __float2bfloat16_rn(v);
            g_wstk_hi[i] = hi;
            g_wstk_lo[i] = __float2bfloat16_rn(v - __bfloat162float(hi));
        }
    } else if (bid < PRE_WSTK_BLOCKS + PRE_V_BLOCKS) {
        int bl = bid - PRE_WSTK_BLOCKS;
        int wid = threadIdx.x >> 5, lane = threadIdx.x & 31;
        int j = bl * 8 + wid;            // [0, 3072)
        int l    = j >> 10;
        int rem  = j & 1023;
        int half = rem >> 9;
        int hk   = rem & 511;
        int h = hk >> 7, k = hk & 127;
        const float* av = half ? a_dst : a_src;
        float4 w4 = *(const float4*)&wg[l * 65536 + k * 512 + h * 128 + lane * 4];
        float4 a4 = *(const float4*)&av[l * 512 + h * 128 + lane * 4];
        float s = w4.x * a4.x + w4.y * a4.y + w4.z * a4.z + w4.w * a4.w;
#pragma unroll
        for (int off = 16; off > 0; off >>= 1) s += __shfl_xor_sync(0xffffffffu, s, off);
        if (lane == 0) {
            if (half) g_vd[l * 512 + hk] = s;
            else      g_vs[l * 512 + hk] = s;
        }
    } else {
        int i = (bid - PRE_WSTK_BLOCKS - PRE_V_BLOCKS) * 256 + threadIdx.x;
        if (i < NN) g_cnt[i] = 0;
        if (i <= NN) {
            int bb = (i < NN) ? batch[i] : NGR;
            int bp = (i > 0) ? batch[i - 1] : -1;
            for (int g = bp + 1; g <= bb && g <= NGR; g++) g_gstart[g] = i;
        }
    }
}

// ---------------- CSR build ----------------
__global__ void k_count(const int* __restrict__ ei) {
    int i = blockIdx.x * blockDim.x + threadIdx.x;
    if (i >= ETOT) return;
    int dst = (i < NE) ? ei[NE + i] : (i - NE);
    atomicAdd(&g_cnt[dst], 1);
}

__global__ void k_scan() {   // single block, 1024 threads, chunk=20; also writes cursor
    __shared__ int ssum[1024];
    const int CH = 20;
    int tid = threadIdx.x;
    int base = tid * CH;
    int s = 0;
    for (int j = 0; j < CH; j++) {
        int idx = base + j;
        if (idx < NN) s += g_cnt[idx];
    }
    ssum[tid] = s;
    __syncthreads();
    for (int off = 1; off < 1024; off <<= 1) {
        int v = 0;
        if (tid >= off) v = ssum[tid - off];
        __syncthreads();
        ssum[tid] += v;
        __syncthreads();
    }
    int run = tid ? ssum[tid - 1] : 0;
    for (int j = 0; j < CH; j++) {
        int idx = base + j;
        if (idx < NN) {
            int c = g_cnt[idx];
            g_rowptr[idx] = run;
            g_cnt[idx]    = run;   // scatter cursor
            run += c;
        }
    }
    if (tid == 1023) g_rowptr[NN] = ssum[1023];
}

__global__ void k_scatter(const int* __restrict__ ei) {
    int i = blockIdx.x * blockDim.x + threadIdx.x;
    if (i >= ETOT) return;
    int src, dst;
    if (i < NE) { src = ei[i]; dst = ei[NE + i]; }
    else        { src = i - NE; dst = i - NE; }
    int pos = atomicAdd(&g_cnt[dst], 1);
    g_esrc[pos] = src;
}

// ---------------- input projection + layer-0 alpha logits (warp per node) ----------------
// grid 2500, 256 threads = 8 warps = 8 nodes/block. Lane = float4 of dims.
__global__ __launch_bounds__(256) void k_inproj(const float* __restrict__ x,
                                                const float* __restrict__ w,
                                                const float* __restrict__ b) {
    __shared__ alignas(16) float sw[FD * DH];   // 1408 floats
    __shared__ alignas(16) float sv[1024];      // vs(layer0) | vd(layer0)
    int tid = threadIdx.x;
    for (int i = tid; i < FD * DH; i += 256) sw[i] = w[i];
    {
        float4 v4;
        if (tid < 128) v4 = *(const float4*)&g_vs[tid * 4];
        else           v4 = *(const float4*)&g_vd[(tid - 128) * 4];
        *(float4*)&sv[tid * 4] = v4;
    }
    __syncthreads();

    int wid = tid >> 5, lane = tid & 31;
    int n = blockIdx.x * 8 + wid;        // exact: 2500*8 = 20000
    float xv = (lane < FD) ? x[n * FD + lane] : 0.f;
    int d = lane * 4;
    float4 hv = *(const float4*)&b[d];
#pragma unroll
    for (int k = 0; k < FD; k++) {
        float xk = __shfl_sync(0xffffffffu, xv, k);
        float4 w4 = *(const float4*)&sw[k * DH + d];
        hv.x += xk * w4.x; hv.y += xk * w4.y; hv.z += xk * w4.z; hv.w += xk * w4.w;
    }
    hv.x = fmaxf(hv.x, 0.f); hv.y = fmaxf(hv.y, 0.f);
    hv.z = fmaxf(hv.z, 0.f); hv.w = fmaxf(hv.w, 0.f);
    *(float4*)&g_h[n * DH + d] = hv;

    float p[8];
#pragma unroll
    for (int h = 0; h < 4; h++) {
        float4 a4 = *(const float4*)&sv[h * 128 + d];
        float4 b4 = *(const float4*)&sv[512 + h * 128 + d];
        p[h]     = hv.x * a4.x + hv.y * a4.y + hv.z * a4.z + hv.w * a4.w;
        p[4 + h] = hv.x * b4.x + hv.y * b4.y + hv.z * b4.z + hv.w * b4.w;
    }
#pragma unroll
    for (int off = 16; off > 0; off >>= 1)
#pragma unroll
        for (int i = 0; i < 8; i++) p[i] += __shfl_xor_sync(0xffffffffu, p[i], off);
    if (lane == 0) {
        *(float4*)&g_as[n * 4] = make_float4(p[0], p[1], p[2], p[3]);
        *(float4*)&g_ad[n * 4] = make_float4(p[4], p[5], p[6], p[7]);
    }
}

// ---------------- GAT aggregation in input space — warp per node ----------------
// 4 nodes/block (grid exactly 5000), no block barriers. Lane = float4 of dims.
__global__ __launch_bounds__(128) void k_agg() {
    int tid = threadIdx.x;
    int wid = tid >> 5, lane = tid & 31;
    int node = blockIdx.x * 4 + wid;   // < NN always
    int beg = g_rowptr[node], end = g_rowptr[node + 1];
    float4 ad4 = *(const float4*)&g_ad[node * 4];

    // pass 1: online softmax for 4 heads, lane-strided edges
    float m0 = -1e30f, m1 = -1e30f, m2 = -1e30f, m3 = -1e30f;
    float s0 = 0.f, s1 = 0.f, s2 = 0.f, s3 = 0.f;
    for (int e = beg + lane; e < end; e += 32) {
        int src = g_esrc[e];
        float4 as4 = *(const float4*)&g_as[src * 4];
        float x0 = as4.x + ad4.x; x0 = x0 > 0.f ? x0 : 0.2f * x0;
        float x1 = as4.y + ad4.y; x1 = x1 > 0.f ? x1 : 0.2f * x1;
        float x2 = as4.z + ad4.z; x2 = x2 > 0.f ? x2 : 0.2f * x2;
        float x3 = as4.w + ad4.w; x3 = x3 > 0.f ? x3 : 0.2f * x3;
        float nm;
        nm = fmaxf(m0, x0); s0 = s0 * __expf(m0 - nm) + __expf(x0 - nm); m0 = nm;
        nm = fmaxf(m1, x1); s1 = s1 * __expf(m1 - nm) + __expf(x1 - nm); m1 = nm;
        nm = fmaxf(m2, x2); s2 = s2 * __expf(m2 - nm) + __expf(x2 - nm); m2 = nm;
        nm = fmaxf(m3, x3); s3 = s3 * __expf(m3 - nm) + __expf(x3 - nm); m3 = nm;
    }
#pragma unroll
    for (int off = 16; off > 0; off >>= 1) {
        float mo, so, nm;
        mo = __shfl_xor_sync(0xffffffffu, m0, off); so = __shfl_xor_sync(0xffffffffu, s0, off);
        nm = fmaxf(m0, mo); s0 = s0 * __expf(m0 - nm) + so * __expf(mo - nm); m0 = nm;
        mo = __shfl_xor_sync(0xffffffffu, m1, off); so = __shfl_xor_sync(0xffffffffu, s1, off);
        nm = fmaxf(m1, mo); s1 = s1 * __expf(m1 - nm) + so * __expf(mo - nm); m1 = nm;
        mo = __shfl_xor_sync(0xffffffffu, m2, off); so = __shfl_xor_sync(0xffffffffu, s2, off);
        nm = fmaxf(m2, mo); s2 = s2 * __expf(m2 - nm) + so * __expf(mo - nm); m2 = nm;
        mo = __shfl_xor_sync(0xffffffffu, m3, off); so = __shfl_xor_sync(0xffffffffu, s3, off);
        nm = fmaxf(m3, mo); s3 = s3 * __expf(m3 - nm) + so * __expf(mo - nm); m3 = nm;
    }
    float i0 = 1.f / s0, i1 = 1.f / s1, i2 = 1.f / s2, i3 = 1.f / s3;

    // pass 2: chunked; lane loads (src, w4) for edge base+lane, shfl-broadcast per edge.
    float4 acc0 = {0.f,0.f,0.f,0.f}, acc1 = acc0, acc2 = acc0, acc3 = acc0;
    int dimoff = lane * 4;
    for (int base = beg; base < end; base += 32) {
        int cnt = end - base; if (cnt > 32) cnt = 32;
        int src = 0; float4 w4 = {0.f,0.f,0.f,0.f};
        if (lane < cnt) {
            src = g_esrc[base + lane];
            float4 as4 = *(const float4*)&g_as[src * 4];
            float x0 = as4.x + ad4.x; x0 = x0 > 0.f ? x0 : 0.2f * x0;
            float x1 = as4.y + ad4.y; x1 = x1 > 0.f ? x1 : 0.2f * x1;
            float x2 = as4.z + ad4.z; x2 = x2 > 0.f ? x2 : 0.2f * x2;
            float x3 = as4.w + ad4.w; x3 = x3 > 0.f ? x3 : 0.2f * x3;
            w4.x = __expf(x0 - m0) * i0;
            w4.y = __expf(x1 - m1) * i1;
            w4.z = __expf(x2 - m2) * i2;
            w4.w = __expf(x3 - m3) * i3;
        }
        for (int j = 0; j < cnt; j++) {
            int  sj = __shfl_sync(0xffffffffu, src, j);
            float wx = __shfl_sync(0xffffffffu, w4.x, j);
            float wy = __shfl_sync(0xffffffffu, w4.y, j);
            float wz = __shfl_sync(0xffffffffu, w4.z, j);
            float ww = __shfl_sync(0xffffffffu, w4.w, j);
            float4 hv = *(const float4*)&g_h[sj * DH + dimoff];
            acc0.x += wx * hv.x; acc0.y += wx * hv.y; acc0.z += wx * hv.z; acc0.w += wx * hv.w;
            acc1.x += wy * hv.x; acc1.y += wy * hv.y; acc1.z += wy * hv.z; acc1.w += wy * hv.w;
            acc2.x += wz * hv.x; acc2.y += wz * hv.y; acc2.z += wz * hv.z; acc2.w += wz * hv.w;
            acc3.x += ww * hv.x; acc3.y += ww * hv.y; acc3.z += ww * hv.z; acc3.w += ww * hv.w;
        }
    }

    // store bf16 split: head hh at [node*512 + hh*128 + lane*4]
#pragma unroll
    for (int hh = 0; hh < 4; hh++) {
        float4 v = (hh == 0) ? acc0 : (hh == 1) ? acc1 : (hh == 2) ? acc2 : acc3;
        __nv_bfloat162 hA, hB, lA, lB;
        hA.x = __float2bfloat16_rn(v.x); hA.y = __float2bfloat16_rn(v.y);
        hB.x = __float2bfloat16_rn(v.z); hB.y = __float2bfloat16_rn(v.w);
        lA.x = __float2bfloat16_rn(v.x - __bfloat162float(hA.x));
        lA.y = __float2bfloat16_rn(v.y - __bfloat162float(hA.y));
        lB.x = __float2bfloat16_rn(v.z - __bfloat162float(hB.x));
        lB.y = __float2bfloat16_rn(v.w - __bfloat162float(hB.y));
        int ob = node * 512 + hh * 128 + dimoff;
        *(__nv_bfloat162*)&g_agg_hi[ob]     = hA;
        *(__nv_bfloat162*)&g_agg_hi[ob + 2] = hB;
        *(__nv_bfloat162*)&g_agg_lo[ob]     = lA;
        *(__nv_bfloat162*)&g_agg_lo[ob + 2] = lB;
    }
}

// ---------------- post-GEMM: h_new = relu(LN(agg @ Wstack + bias)) + h_old ----------------
// M-tile 64, grid 313, 256 threads. Register-prefetch software pipeline on the k-loop.
// If next_layer < NL, also computes next layer's alpha logits from the fresh h values.
__global__ __launch_bounds__(256, 3) void k_gemm2(int layer, int next_layer,
                                                  const float* __restrict__ bg,
                                                  const float* __restrict__ lnw,
                                                  const float* __restrict__ lnb) {
    __shared__ alignas(16) __nv_bfloat16 As_h[64][APAD], As_l[64][APAD];     // [m][k]
    __shared__ alignas(16) __nv_bfloat16 Bs_h[32][BPAD],  Bs_l[32][BPAD];    // [k][n]
    __shared__ float rsum[2][64], rsq[2][64];
    __shared__ float s_bg[128], s_lnw[128], s_lnb[128];
    __shared__ float sv[1024];
    __shared__ float ared[2][64][8];

    int tid = threadIdx.x;
    int wid = tid >> 5, lane = tid & 31;
    int warp_m = wid & 3, warp_n = wid >> 2;
    int m0 = blockIdx.x * 64;
    int g  = lane >> 2, t = lane & 3;
    bool do_alpha = (next_layer < NL);
    const __nv_bfloat16* Bh = g_wstk_hi + layer * 512 * DH;
    const __nv_bfloat16* Bl = g_wstk_lo + layer * 512 * DH;

    if (tid < 128) { s_bg[tid] = bg[tid]; s_lnw[tid] = lnw[tid]; s_lnb[tid] = lnb[tid]; }
    if (do_alpha) {
        for (int i = tid; i < 512; i += 256) {
            sv[i]       = g_vs[next_layer * 512 + i];
            sv[512 + i] = g_vd[next_layer * 512 + i];
        }
    }

    float c[8][4];
#pragma unroll
    for (int nt = 0; nt < 8; nt++)
#pragma unroll
        for (int i = 0; i < 4; i++) c[nt][i] = 0.f;

    int ar  = tid >> 2, akg = (tid & 3) * 8;     // A: 64 rows, 8 bf16 (1 uint4) per thread
    int bkr = tid >> 3, bcg = (tid & 7) * 16;    // B: 32 rows, 16 bf16 (2 uint4) per thread

    int lrow = (lane & 7) + ((lane >> 3) & 1) * 8;
    int lcol = (lane >> 4) * 8;
    unsigned sAh = (unsigned)__cvta_generic_to_shared(As_h);
    unsigned sAl = (unsigned)__cvta_generic_to_shared(As_l);
    unsigned sBh = (unsigned)__cvta_generic_to_shared(Bs_h);
    unsigned sBl = (unsigned)__cvta_generic_to_shared(Bs_l);

    // register prefetch pipeline
    bool okA = (m0 + ar < NN);
    uint4 z = make_uint4(0u, 0u, 0u, 0u);
    const uint4* gAh = (const uint4*)&g_agg_hi[(m0 + ar) * 512 + akg];
    const uint4* gAl = (const uint4*)&g_agg_lo[(m0 + ar) * 512 + akg];
    uint4 rAh = okA ? gAh[0] : z;
    uint4 rAl = okA ? gAl[0] : z;
    const uint4* pBh = (const uint4*)&Bh[bkr * 128 + bcg];
    const uint4* pBl = (const uint4*)&Bl[bkr * 128 + bcg];
    uint4 rBh0 = pBh[0], rBh1 = pBh[1];
    uint4 rBl0 = pBl[0], rBl1 = pBl[1];

    for (int kc = 0; kc < 512; kc += 32) {
        __syncthreads();
        *(uint4*)&As_h[ar][akg] = rAh;
        *(uint4*)&As_l[ar][akg] = rAl;
        *(uint4*)&Bs_h[bkr][bcg]     = rBh0;
        *(uint4*)&Bs_h[bkr][bcg + 8] = rBh1;
        *(uint4*)&Bs_l[bkr][bcg]     = rBl0;
        *(uint4*)&Bs_l[bkr][bcg + 8] = rBl1;
        __syncthreads();

        if (kc + 32 < 512) {
            int kn = kc + 32;
            const uint4* nAh = (const uint4*)&g_agg_hi[(m0 + ar) * 512 + kn + akg];
            const uint4* nAl = (const uint4*)&g_agg_lo[(m0 + ar) * 512 + kn + akg];
            rAh = okA ? nAh[0] : z;
            rAl = okA ? nAl[0] : z;
            const uint4* nBh = (const uint4*)&Bh[(kn + bkr) * 128 + bcg];
            const uint4* nBl = (const uint4*)&Bl[(kn + bkr) * 128 + bcg];
            rBh0 = nBh[0]; rBh1 = nBh[1];
            rBl0 = nBl[0]; rBl1 = nBl[1];
        }

#pragma unroll
        for (int kk = 0; kk < 32; kk += 16) {
            unsigned ah[4], al[4];
            unsigned off = (unsigned)(((warp_m * 16 + lrow) * APAD + kk + lcol) * 2);
            ldsm_x4(ah, sAh + off);
            ldsm_x4(al, sAl + off);
#pragma unroll
            for (int p = 0; p < 4; p++) {
                unsigned boff = (unsigned)(((kk + lrow) * BPAD + warp_n * 64 + p * 16 + lcol) * 2);
                unsigned bh[4], bl[4];
                ldsm_x4_t(bh, sBh + boff);
                ldsm_x4_t(bl, sBl + boff);
#pragma unroll
                for (int q = 0; q < 2; q++) {
                    float* cc = c[p * 2 + q];
                    mma_bf16(cc, ah, &bh[q * 2]);
                    mma_bf16(cc, ah, &bl[q * 2]);
                    mma_bf16(cc, al, &bh[q * 2]);
                }
            }
        }
    }
    __syncthreads();

    // epilogue: bias, per-row LN stats, normalize, relu, residual, write g_h (+ fused alpha)
#pragma unroll
    for (int nt = 0; nt < 8; nt++) {
        int col = warp_n * 64 + nt * 8 + t * 2;
        c[nt][0] += s_bg[col];
        c[nt][1] += s_bg[col + 1];
        c[nt][2] += s_bg[col];
        c[nt][3] += s_bg[col + 1];
    }
    float sum[2] = {0.f, 0.f}, sq[2] = {0.f, 0.f};
#pragma unroll
    for (int nt = 0; nt < 8; nt++) {
        float c0 = c[nt][0], c1 = c[nt][1], c2 = c[nt][2], c3 = c[nt][3];
        sum[0] += c0 + c1;  sq[0] += c0 * c0 + c1 * c1;
        sum[1] += c2 + c3;  sq[1] += c2 * c2 + c3 * c3;
    }
#pragma unroll
    for (int off = 1; off <= 2; off <<= 1)
#pragma unroll
        for (int i = 0; i < 2; i++) {
            sum[i] += __shfl_xor_sync(0xffffffffu, sum[i], off);
            sq[i]  += __shfl_xor_sync(0xffffffffu, sq[i],  off);
        }
    if (t == 0) {
#pragma unroll
        for (int hf = 0; hf < 2; hf++) {
            int row = warp_m * 16 + hf * 8 + g;
            rsum[warp_n][row] = sum[hf];
            rsq[warp_n][row]  = sq[hf];
        }
    }
    __syncthreads();

    float pa[2][4] = {{0.f,0.f,0.f,0.f},{0.f,0.f,0.f,0.f}};
    float pb[2][4] = {{0.f,0.f,0.f,0.f},{0.f,0.f,0.f,0.f}};

#pragma unroll
    for (int hf = 0; hf < 2; hf++) {
        int row = warp_m * 16 + hf * 8 + g;
        int grow = m0 + row;
        if (grow >= NN) continue;
        float S = rsum[0][row] + rsum[1][row];
        float Q = rsq[0][row] + rsq[1][row];
        float mu  = S * (1.f / 128.f);
        float var = Q * (1.f / 128.f) - mu * mu;
        float rstd = rsqrtf(var + 1e-5f);
#pragma unroll
        for (int nt = 0; nt < 8; nt++) {
            int col = warp_n * 64 + nt * 8 + t * 2;
            float c0 = c[nt][hf * 2 + 0];
            float c1 = c[nt][hf * 2 + 1];
            float2 hold = *(const float2*)&g_h[grow * DH + col];
            float v0 = (c0 - mu) * rstd * s_lnw[col]     + s_lnb[col];
            float v1 = (c1 - mu) * rstd * s_lnw[col + 1] + s_lnb[col + 1];
            float nv0 = fmaxf(v0, 0.f) + hold.x;
            float nv1 = fmaxf(v1, 0.f) + hold.y;
            *(float2*)&g_h[grow * DH + col] = make_float2(nv0, nv1);
            if (do_alpha) {
#pragma unroll
                for (int h = 0; h < 4; h++) {
                    pa[hf][h] += nv0 * sv[h * 128 + col]       + nv1 * sv[h * 128 + col + 1];
                    pb[hf][h] += nv0 * sv[512 + h * 128 + col] + nv1 * sv[512 + h * 128 + col + 1];
                }
            }
        }
    }

    if (do_alpha) {
#pragma unroll
        for (int off = 1; off <= 2; off <<= 1)
#pragma unroll
            for (int hf = 0; hf < 2; hf++)
#pragma unroll
                for (int h = 0; h < 4; h++) {
                    pa[hf][h] += __shfl_xor_sync(0xffffffffu, pa[hf][h], off);
                    pb[hf][h] += __shfl_xor_sync(0xffffffffu, pb[hf][h], off);
                }
        if (t == 0) {
#pragma unroll
            for (int hf = 0; hf < 2; hf++) {
                int row = warp_m * 16 + hf * 8 + g;
#pragma unroll
                for (int h = 0; h < 4; h++) {
                    ared[warp_n][row][h]     = pa[hf][h];
                    ared[warp_n][row][4 + h] = pb[hf][h];
                }
            }
        }
        __syncthreads();
        for (int idx = tid; idx < 512; idx += 256) {
            int row = idx >> 3, o = idx & 7;
            int grow = m0 + row;
            if (grow < NN) {
                float s = ared[0][row][o] + ared[1][row][o];
                if (o < 4) g_as[grow * 4 + o] = s;
                else       g_ad[grow * 4 + (o - 4)] = s;
            }
        }
    }
}

// ---------------- pooling + TDA + trunk + task heads (fully fused) ----------------
__global__ __launch_bounds__(256) void k_head(const float* __restrict__ tda,
                                              const float* __restrict__ wt1, const float* __restrict__ bt1,
                                              const float* __restrict__ wt2, const float* __restrict__ bt2,
                                              const float* __restrict__ wsh1, const float* __restrict__ bsh1,
                                              const float* __restrict__ wsh2, const float* __restrict__ bsh2,
                                              const float* __restrict__ wh1,  const float* __restrict__ bh1,
                                              const float* __restrict__ wh2,  const float* __restrict__ bh2,
                                              float* __restrict__ out) {
    int g = blockIdx.x, tid = threadIdx.x;
    __shared__ float comb[320], s1[256], s2[128], hh1[NT * 64], th1[64];

    int beg = g_gstart[g], end = g_gstart[g + 1];
    int cntn = end - beg;
    {
        int d = tid & 127;
        if (tid < 128) {
            float s = 0.f;
            for (int i = beg; i < end; i++) s += g_h[i * DH + d];
            comb[d] = s / (float)(cntn > 0 ? cntn : 1);
        } else {
            float mx = -1e30f;
            for (int i = beg; i < end; i++) mx = fmaxf(mx, g_h[i * DH + d]);
            comb[128 + d] = (cntn > 0) ? mx : 0.f;
        }
    }
    __syncthreads();
    if (tid < 64) {
        float a = bt1[tid];
#pragma unroll
        for (int k = 0; k < FT; k++) a += tda[g * FT + k] * wt1[k * 64 + tid];
        th1[tid] = fmaxf(a, 0.f);
    }
    __syncthreads();
    if (tid < 64) {
        float c = bt2[tid];
#pragma unroll
        for (int k = 0; k < 64; k++) c += th1[k] * wt2[k * 64 + tid];
        comb[256 + tid] = fmaxf(c, 0.f);
    }
    __syncthreads();
    float a = bsh1[tid];
    for (int k = 0; k < 320; k++) a += comb[k] * wsh1[k * 256 + tid];
    s1[tid] = fmaxf(a, 0.f);
    __syncthreads();
    if (tid < 128) {
        float c = bsh2[tid];
        for (int k = 0; k < 256; k++) c += s1[k] * wsh2[k * 128 + tid];
        s2[tid] = fmaxf(c, 0.f);
    }
    __syncthreads();
    for (int idx = tid; idx < NT * 64; idx += 256) {
        int t = idx >> 6, kk = idx & 63;
        float c = bh1[t * 64 + kk];
        for (int k = 0; k < 128; k++) c += s2[k] * wh1[t * 8192 + k * 64 + kk];
        hh1[idx] = fmaxf(c, 0.f);
    }
    __syncthreads();
    if (tid < NT) {
        float c = bh2[tid];
        for (int k = 0; k < 64; k++) c += hh1[tid * 64 + k] * wh2[tid * 64 + k];
        out[tid * NGR + g] = c;
    }
}

// ---------------- launch ----------------
extern "C" void kernel_launch(void* const* d_in, const int* in_sizes, int n_in,
                              void* d_out, int out_size) {
    const float* x       = (const float*)d_in[0];
    const int*   ei      = (const int*)d_in[1];
    const int*   batch   = (const int*)d_in[2];
    const float* tda     = (const float*)d_in[3];
    const float* w_in    = (const float*)d_in[4];
    const float* b_in    = (const float*)d_in[5];
    const float* w_gat   = (const float*)d_in[6];
    const float* a_src   = (const float*)d_in[7];
    const float* a_dst   = (const float*)d_in[8];
    const float* b_gat   = (const float*)d_in[9];
    const float* ln_w    = (const float*)d_in[10];
    const float* ln_b    = (const float*)d_in[11];
    const float* w_tda1  = (const float*)d_in[12];
    const float* b_tda1  = (const float*)d_in[13];
    const float* w_tda2  = (const float*)d_in[14];
    const float* b_tda2  = (const float*)d_in[15];
    const float* w_sh1   = (const float*)d_in[16];
    const float* b_sh1   = (const float*)d_in[17];
    const float* w_sh2   = (const float*)d_in[18];
    const float* b_sh2   = (const float*)d_in[19];
    const float* w_h1    = (const float*)d_in[20];
    const float* b_h1    = (const float*)d_in[21];
    const float* w_h2    = (const float*)d_in[22];
    const float* b_h2    = (const float*)d_in[23];
    float* out = (float*)d_out;

    const int ROWS64_GRID = (NN + 63) / 64;   // 313

    k_pre<<<PRE_TOTAL_BLOCKS, 256>>>(w_gat, a_src, a_dst, batch);   // 0
    k_count<<<(ETOT + 255) / 256, 256>>>(ei);                        // 1
    k_scan<<<1, 1024>>>();                                           // 2
    k_inproj<<<NN / 8, 256>>>(x, w_in, b_in);                        // 3 (profiled)
    k_scatter<<<(ETOT + 255) / 256, 256>>>(ei);                      // 4

    for (int l = 0; l < NL; l++) {
        k_agg<<<NN / 4, 128>>>();
        k_gemm2<<<ROWS64_GRID, 256>>>(l, l + 1,
                                      b_gat + l * 128, ln_w + l * 128, ln_b + l * 128);
    }

    k_head<<<NGR, 256>>>(tda, w_tda1, b_tda1, w_tda2, b_tda2,
                         w_sh1, b_sh1, w_sh2, b_sh2, w_h1, b_h1, w_h2, b_h2, out);
}

// round 17
// speedup vs baseline: 1.3225x; 1.0377x over previous
#include <cuda_runtime.h>
#include <cuda_bf16.h>
#include <math.h>

#define NN   20000        // nodes
#define NE   320000       // edges (without self loops)
#define ETOT (NE + NN)    // edges + self loops
#define NGR  256          // graphs
#define FD   11           // node feature dim
#define FT   30           // tda feature dim
#define DH   128          // hidden
#define NH   4            // heads
#define NL   3            // layers
#define NT   6            // tasks

#define APAD 40           // A smem row length (32 k + 8 pad) in bf16
#define BPAD 136          // B smem row length (128 n + 8 pad) in bf16

// ---------------- device scratch (static, no allocations) ----------------
// Referenced ONLY inside kernels — never passed as kernel arguments.
__device__ alignas(16) float         g_h[NN * DH];            // node features (in-place updated)
__device__ alignas(16) __nv_bfloat16 g_agg_hi[NN * 512];      // aggregated features bf16 hi
__device__ alignas(16) __nv_bfloat16 g_agg_lo[NN * 512];      // aggregated features bf16 lo
__device__ alignas(16) __nv_bfloat16 g_wstk_hi[NL * 512 * DH];// stacked (W_h/4) bf16 hi
__device__ alignas(16) __nv_bfloat16 g_wstk_lo[NL * 512 * DH];
__device__ alignas(16) float         g_vs[NL * NH * DH];      // projected a_src vectors
__device__ alignas(16) float         g_vd[NL * NH * DH];      // projected a_dst vectors
__device__ alignas(16) float         g_as[NN * NH];           // alpha_src per node/head
__device__ alignas(16) float         g_ad[NN * NH];           // alpha_dst per node/head
__device__ int           g_rowptr[NN + 1];
__device__ int           g_cnt[NN];               // counts, then scatter cursor
__device__ int           g_esrc[ETOT];            // src ids sorted by dst
__device__ int           g_gstart[NGR + 1];

// ---------------- bf16 mma helpers ----------------
__device__ __forceinline__ void mma_bf16(float c[4], const unsigned a[4], const unsigned* b) {
    asm volatile(
        "mma.sync.aligned.m16n8k16.row.col.f32.bf16.bf16.f32 "
        "{%0,%1,%2,%3}, {%4,%5,%6,%7}, {%8,%9}, {%0,%1,%2,%3};\n"
        : "+f"(c[0]), "+f"(c[1]), "+f"(c[2]), "+f"(c[3])
        : "r"(a[0]), "r"(a[1]), "r"(a[2]), "r"(a[3]), "r"(b[0]), "r"(b[1]));
}

__device__ __forceinline__ void ldsm_x4(unsigned r[4], unsigned saddr) {
    asm volatile("ldmatrix.sync.aligned.m8n8.x4.shared.b16 {%0,%1,%2,%3}, [%4];"
        : "=r"(r[0]), "=r"(r[1]), "=r"(r[2]), "=r"(r[3]) : "r"(saddr));
}

__device__ __forceinline__ void ldsm_x4_t(unsigned r[4], unsigned saddr) {
    asm volatile("ldmatrix.sync.aligned.m8n8.x4.trans.shared.b16 {%0,%1,%2,%3}, [%4];"
        : "=r"(r[0]), "=r"(r[1]), "=r"(r[2]), "=r"(r[3]) : "r"(saddr));
}

// ---------------- fused pre-pass ----------------
// segments: Wstack split | v-projection (warp per output) | CSR prep
#define PRE_WSTK_BLOCKS   ((NL * 512 * DH + 255) / 256)   // 768
#define PRE_V_BLOCKS      ((NL * 2 * NH * DH) / 8)        // 384 (8 warps/block, warp per output)
#define PRE_PREP_BLOCKS   ((NN + 256) / 256)              // 79
#define PRE_TOTAL_BLOCKS  (PRE_WSTK_BLOCKS + PRE_V_BLOCKS + PRE_PREP_BLOCKS)

__global__ __launch_bounds__(256) void k_pre(const float* __restrict__ wg,
                                             const float* __restrict__ a_src,
                                             const float* __restrict__ a_dst,
                                             const int* __restrict__ batch) {
    int bid = blockIdx.x;
    if (bid < PRE_WSTK_BLOCKS) {
        int i = bid * 256 + threadIdx.x;
        if (i < NL * 512 * DH) {
            int l = i >> 16;             // 512*128 = 65536
            int r = (i >> 7) & 511;      // stacked row = h*128 + kd
            int d = i & 127;
            int h = r >> 7, kd = r & 127;
            float v = 0.25f * wg[l * 65536 + kd * 512 + h * 128 + d];
            __nv_bfloat16 hi = __float2bfloat16_rn(v);
            g_wstk_hi[i] = hi;
            g_wstk_lo[i] = __float2bfloat16_rn(v - __bfloat162float(hi));
        }
    } else if (bid < PRE_WSTK_BLOCKS + PRE_V_BLOCKS) {
        int bl = bid - PRE_WSTK_BLOCKS;
        int wid = threadIdx.x >> 5, lane = threadIdx.x & 31;
        int j = bl * 8 + wid;            // [0, 3072)
        int l    = j >> 10;
        int rem  = j & 1023;
        int half = rem >> 9;
        int hk   = rem & 511;
        int h = hk >> 7, k = hk & 127;
        const float* av = half ? a_dst : a_src;
        float4 w4 = *(const float4*)&wg[l * 65536 + k * 512 + h * 128 + lane * 4];
        float4 a4 = *(const float4*)&av[l * 512 + h * 128 + lane * 4];
        float s = w4.x * a4.x + w4.y * a4.y + w4.z * a4.z + w4.w * a4.w;
#pragma unroll
        for (int off = 16; off > 0; off >>= 1) s += __shfl_xor_sync(0xffffffffu, s, off);
        if (lane == 0) {
            if (half) g_vd[l * 512 + hk] = s;
            else      g_vs[l * 512 + hk] = s;
        }
    } else {
        int i = (bid - PRE_WSTK_BLOCKS - PRE_V_BLOCKS) * 256 + threadIdx.x;
        if (i < NN) g_cnt[i] = 0;
        if (i <= NN) {
            int bb = (i < NN) ? batch[i] : NGR;
            int bp = (i > 0) ? batch[i - 1] : -1;
            for (int g = bp + 1; g <= bb && g <= NGR; g++) g_gstart[g] = i;
        }
    }
}

// ---------------- CSR build ----------------
__global__ void k_count(const int* __restrict__ ei) {
    int i = blockIdx.x * blockDim.x + threadIdx.x;
    if (i >= ETOT) return;
    int dst = (i < NE) ? ei[NE + i] : (i - NE);
    atomicAdd(&g_cnt[dst], 1);
}

__global__ void k_scan() {   // single block, 1024 threads, chunk=20; also writes cursor
    __shared__ int ssum[1024];
    const int CH = 20;
    int tid = threadIdx.x;
    int base = tid * CH;
    int s = 0;
    for (int j = 0; j < CH; j++) {
        int idx = base + j;
        if (idx < NN) s += g_cnt[idx];
    }
    ssum[tid] = s;
    __syncthreads();
    for (int off = 1; off < 1024; off <<= 1) {
        int v = 0;
        if (tid >= off) v = ssum[tid - off];
        __syncthreads();
        ssum[tid] += v;
        __syncthreads();
    }
    int run = tid ? ssum[tid - 1] : 0;
    for (int j = 0; j < CH; j++) {
        int idx = base + j;
        if (idx < NN) {
            int c = g_cnt[idx];
            g_rowptr[idx] = run;
            g_cnt[idx]    = run;   // scatter cursor
            run += c;
        }
    }
    if (tid == 1023) g_rowptr[NN] = ssum[1023];
}

__global__ void k_scatter(const int* __restrict__ ei) {
    int i = blockIdx.x * blockDim.x + threadIdx.x;
    if (i >= ETOT) return;
    int src, dst;
    if (i < NE) { src = ei[i]; dst = ei[NE + i]; }
    else        { src = i - NE; dst = i - NE; }
    int pos = atomicAdd(&g_cnt[dst], 1);
    g_esrc[pos] = src;
}

// ---------------- input projection + layer-0 alpha logits (warp per node) ----------------
// grid 2500, 256 threads = 8 warps = 8 nodes/block. Lane = float4 of dims.
__global__ __launch_bounds__(256) void k_inproj(const float* __restrict__ x,
                                                const float* __restrict__ w,
                                                const float* __restrict__ b) {
    __shared__ alignas(16) float sw[FD * DH];   // 1408 floats
    __shared__ alignas(16) float sv[1024];      // vs(layer0) | vd(layer0)
    int tid = threadIdx.x;
    for (int i = tid; i < FD * DH; i += 256) sw[i] = w[i];
    {
        float4 v4;
        if (tid < 128) v4 = *(const float4*)&g_vs[tid * 4];
        else           v4 = *(const float4*)&g_vd[(tid - 128) * 4];
        *(float4*)&sv[tid * 4] = v4;
    }
    __syncthreads();

    int wid = tid >> 5, lane = tid & 31;
    int n = blockIdx.x * 8 + wid;        // exact: 2500*8 = 20000
    float xv = (lane < FD) ? x[n * FD + lane] : 0.f;
    int d = lane * 4;
    float4 hv = *(const float4*)&b[d];
#pragma unroll
    for (int k = 0; k < FD; k++) {
        float xk = __shfl_sync(0xffffffffu, xv, k);
        float4 w4 = *(const float4*)&sw[k * DH + d];
        hv.x += xk * w4.x; hv.y += xk * w4.y; hv.z += xk * w4.z; hv.w += xk * w4.w;
    }
    hv.x = fmaxf(hv.x, 0.f); hv.y = fmaxf(hv.y, 0.f);
    hv.z = fmaxf(hv.z, 0.f); hv.w = fmaxf(hv.w, 0.f);
    *(float4*)&g_h[n * DH + d] = hv;

    float p[8];
#pragma unroll
    for (int h = 0; h < 4; h++) {
        float4 a4 = *(const float4*)&sv[h * 128 + d];
        float4 b4 = *(const float4*)&sv[512 + h * 128 + d];
        p[h]     = hv.x * a4.x + hv.y * a4.y + hv.z * a4.z + hv.w * a4.w;
        p[4 + h] = hv.x * b4.x + hv.y * b4.y + hv.z * b4.z + hv.w * b4.w;
    }
#pragma unroll
    for (int off = 16; off > 0; off >>= 1)
#pragma unroll
        for (int i = 0; i < 8; i++) p[i] += __shfl_xor_sync(0xffffffffu, p[i], off);
    if (lane == 0) {
        *(float4*)&g_as[n * 4] = make_float4(p[0], p[1], p[2], p[3]);
        *(float4*)&g_ad[n * 4] = make_float4(p[4], p[5], p[6], p[7]);
    }
}

// ---------------- GAT aggregation in input space — warp per node ----------------
// 4 nodes/block (grid exactly 5000), no block barriers. Lane = float4 of dims.
__global__ __launch_bounds__(128) void k_agg() {
    int tid = threadIdx.x;
    int wid = tid >> 5, lane = tid & 31;
    int node = blockIdx.x * 4 + wid;   // < NN always
    int beg = g_rowptr[node], end = g_rowptr[node + 1];
    float4 ad4 = *(const float4*)&g_ad[node * 4];

    // pass 1: online softmax for 4 heads, lane-strided edges
    float m0 = -1e30f, m1 = -1e30f, m2 = -1e30f, m3 = -1e30f;
    float s0 = 0.f, s1 = 0.f, s2 = 0.f, s3 = 0.f;
    for (int e = beg + lane; e < end; e += 32) {
        int src = g_esrc[e];
        float4 as4 = *(const float4*)&g_as[src * 4];
        float x0 = as4.x + ad4.x; x0 = x0 > 0.f ? x0 : 0.2f * x0;
        float x1 = as4.y + ad4.y; x1 = x1 > 0.f ? x1 : 0.2f * x1;
        float x2 = as4.z + ad4.z; x2 = x2 > 0.f ? x2 : 0.2f * x2;
        float x3 = as4.w + ad4.w; x3 = x3 > 0.f ? x3 : 0.2f * x3;
        float nm;
        nm = fmaxf(m0, x0); s0 = s0 * __expf(m0 - nm) + __expf(x0 - nm); m0 = nm;
        nm = fmaxf(m1, x1); s1 = s1 * __expf(m1 - nm) + __expf(x1 - nm); m1 = nm;
        nm = fmaxf(m2, x2); s2 = s2 * __expf(m2 - nm) + __expf(x2 - nm); m2 = nm;
        nm = fmaxf(m3, x3); s3 = s3 * __expf(m3 - nm) + __expf(x3 - nm); m3 = nm;
    }
#pragma unroll
    for (int off = 16; off > 0; off >>= 1) {
        float mo, so, nm;
        mo = __shfl_xor_sync(0xffffffffu, m0, off); so = __shfl_xor_sync(0xffffffffu, s0, off);
        nm = fmaxf(m0, mo); s0 = s0 * __expf(m0 - nm) + so * __expf(mo - nm); m0 = nm;
        mo = __shfl_xor_sync(0xffffffffu, m1, off); so = __shfl_xor_sync(0xffffffffu, s1, off);
        nm = fmaxf(m1, mo); s1 = s1 * __expf(m1 - nm) + so * __expf(mo - nm); m1 = nm;
        mo = __shfl_xor_sync(0xffffffffu, m2, off); so = __shfl_xor_sync(0xffffffffu, s2, off);
        nm = fmaxf(m2, mo); s2 = s2 * __expf(m2 - nm) + so * __expf(mo - nm); m2 = nm;
        mo = __shfl_xor_sync(0xffffffffu, m3, off); so = __shfl_xor_sync(0xffffffffu, s3, off);
        nm = fmaxf(m3, mo); s3 = s3 * __expf(m3 - nm) + so * __expf(mo - nm); m3 = nm;
    }
    float i0 = 1.f / s0, i1 = 1.f / s1, i2 = 1.f / s2, i3 = 1.f / s3;

    // pass 2: chunked; lane loads (src, w4) for edge base+lane, shfl-broadcast per edge.
    float4 acc0 = {0.f,0.f,0.f,0.f}, acc1 = acc0, acc2 = acc0, acc3 = acc0;
    int dimoff = lane * 4;
    for (int base = beg; base < end; base += 32) {
        int cnt = end - base; if (cnt > 32) cnt = 32;
        int src = 0; float4 w4 = {0.f,0.f,0.f,0.f};
        if (lane < cnt) {
            src = g_esrc[base + lane];
            float4 as4 = *(const float4*)&g_as[src * 4];
            float x0 = as4.x + ad4.x; x0 = x0 > 0.f ? x0 : 0.2f * x0;
            float x1 = as4.y + ad4.y; x1 = x1 > 0.f ? x1 : 0.2f * x1;
            float x2 = as4.z + ad4.z; x2 = x2 > 0.f ? x2 : 0.2f * x2;
            float x3 = as4.w + ad4.w; x3 = x3 > 0.f ? x3 : 0.2f * x3;
            w4.x = __expf(x0 - m0) * i0;
            w4.y = __expf(x1 - m1) * i1;
            w4.z = __expf(x2 - m2) * i2;
            w4.w = __expf(x3 - m3) * i3;
        }
        for (int j = 0; j < cnt; j++) {
            int  sj = __shfl_sync(0xffffffffu, src, j);
            float wx = __shfl_sync(0xffffffffu, w4.x, j);
            float wy = __shfl_sync(0xffffffffu, w4.y, j);
            float wz = __shfl_sync(0xffffffffu, w4.z, j);
            float ww = __shfl_sync(0xffffffffu, w4.w, j);
            float4 hv = *(const float4*)&g_h[sj * DH + dimoff];
            acc0.x += wx * hv.x; acc0.y += wx * hv.y; acc0.z += wx * hv.z; acc0.w += wx * hv.w;
            acc1.x += wy * hv.x; acc1.y += wy * hv.y; acc1.z += wy * hv.z; acc1.w += wy * hv.w;
            acc2.x += wz * hv.x; acc2.y += wz * hv.y; acc2.z += wz * hv.z; acc2.w += wz * hv.w;
            acc3.x += ww * hv.x; acc3.y += ww * hv.y; acc3.z += ww * hv.z; acc3.w += ww * hv.w;
        }
    }

    // store bf16 split: head hh at [node*512 + hh*128 + lane*4]
#pragma unroll
    for (int hh = 0; hh < 4; hh++) {
        float4 v = (hh == 0) ? acc0 : (hh == 1) ? acc1 : (hh == 2) ? acc2 : acc3;
        __nv_bfloat162 hA, hB, lA, lB;
        hA.x = __float2bfloat16_rn(v.x); hA.y = __float2bfloat16_rn(v.y);
        hB.x = __float2bfloat16_rn(v.z); hB.y = __float2bfloat16_rn(v.w);
        lA.x = __float2bfloat16_rn(v.x - __bfloat162float(hA.x));
        lA.y = __float2bfloat16_rn(v.y - __bfloat162float(hA.y));
        lB.x = __float2bfloat16_rn(v.z - __bfloat162float(hB.x));
        lB.y = __float2bfloat16_rn(v.w - __bfloat162float(hB.y));
        int ob = node * 512 + hh * 128 + dimoff;
        *(__nv_bfloat162*)&g_agg_hi[ob]     = hA;
        *(__nv_bfloat162*)&g_agg_hi[ob + 2] = hB;
        *(__nv_bfloat162*)&g_agg_lo[ob]     = lA;
        *(__nv_bfloat162*)&g_agg_lo[ob + 2] = lB;
    }
}

// ---------------- post-GEMM: h_new = relu(LN(agg @ Wstack + bias)) + h_old ----------------
// M-tile 64, grid 313, 256 threads = 8 warps (4 warp_m x 16 rows, 2 warp_n x 64 cols).
// If next_layer < NL, also computes next layer's alpha logits from the fresh h values.
// (No register prefetch — measured regression in R16.)
__global__ __launch_bounds__(256, 3) void k_gemm2(int layer, int next_layer,
                                                  const float* __restrict__ bg,
                                                  const float* __restrict__ lnw,
                                                  const float* __restrict__ lnb) {
    __shared__ alignas(16) __nv_bfloat16 As_h[64][APAD], As_l[64][APAD];     // [m][k]
    __shared__ alignas(16) __nv_bfloat16 Bs_h[32][BPAD],  Bs_l[32][BPAD];    // [k][n]
    __shared__ float rsum[2][64], rsq[2][64];
    __shared__ float s_bg[128], s_lnw[128], s_lnb[128];
    __shared__ float sv[1024];          // next layer's vs|vd (staged iff next_layer < NL)
    __shared__ float ared[2][64][8];    // alpha partials [warp_n][row][out]

    int tid = threadIdx.x;
    int wid = tid >> 5, lane = tid & 31;
    int warp_m = wid & 3, warp_n = wid >> 2;
    int m0 = blockIdx.x * 64;
    int g  = lane >> 2, t = lane & 3;
    bool do_alpha = (next_layer < NL);
    const __nv_bfloat16* Bh = g_wstk_hi + layer * 512 * DH;
    const __nv_bfloat16* Bl = g_wstk_lo + layer * 512 * DH;

    if (tid < 128) { s_bg[tid] = bg[tid]; s_lnw[tid] = lnw[tid]; s_lnb[tid] = lnb[tid]; }
    if (do_alpha) {
        for (int i = tid; i < 512; i += 256) {
            sv[i]       = g_vs[next_layer * 512 + i];
            sv[512 + i] = g_vd[next_layer * 512 + i];
        }
    }

    float c[8][4];
#pragma unroll
    for (int nt = 0; nt < 8; nt++)
#pragma unroll
        for (int i = 0; i < 4; i++) c[nt][i] = 0.f;

    int ar  = tid >> 2, akg = (tid & 3) * 8;     // A: 64 rows, 8 bf16 (1 uint4) per thread
    int bkr = tid >> 3, bcg = (tid & 7) * 16;    // B: 32 rows, 16 bf16 (2 uint4) per thread

    int lrow = (lane & 7) + ((lane >> 3) & 1) * 8;
    int lcol = (lane >> 4) * 8;
    unsigned sAh = (unsigned)__cvta_generic_to_shared(As_h);
    unsigned sAl = (unsigned)__cvta_generic_to_shared(As_l);
    unsigned sBh = (unsigned)__cvta_generic_to_shared(Bs_h);
    unsigned sBl = (unsigned)__cvta_generic_to_shared(Bs_l);

    for (int kc = 0; kc < 512; kc += 32) {
        __syncthreads();
        {
            bool ok = (m0 + ar < NN);
            uint4 z = make_uint4(0u, 0u, 0u, 0u);
            const uint4* ph = (const uint4*)&g_agg_hi[(m0 + ar) * 512 + kc + akg];
            const uint4* pl = (const uint4*)&g_agg_lo[(m0 + ar) * 512 + kc + akg];
            *(uint4*)&As_h[ar][akg] = ok ? ph[0] : z;
            *(uint4*)&As_l[ar][akg] = ok ? pl[0] : z;
        }
        {
            const uint4* ph = (const uint4*)&Bh[(kc + bkr) * 128 + bcg];
            const uint4* pl = (const uint4*)&Bl[(kc + bkr) * 128 + bcg];
            uint4 h0 = ph[0], h1 = ph[1];
            uint4 l0 = pl[0], l1 = pl[1];
            *(uint4*)&Bs_h[bkr][bcg]     = h0;
            *(uint4*)&Bs_h[bkr][bcg + 8] = h1;
            *(uint4*)&Bs_l[bkr][bcg]     = l0;
            *(uint4*)&Bs_l[bkr][bcg + 8] = l1;
        }
        __syncthreads();

#pragma unroll
        for (int kk = 0; kk < 32; kk += 16) {
            unsigned ah[4], al[4];
            unsigned off = (unsigned)(((warp_m * 16 + lrow) * APAD + kk + lcol) * 2);
            ldsm_x4(ah, sAh + off);
            ldsm_x4(al, sAl + off);
#pragma unroll
            for (int p = 0; p < 4; p++) {
                unsigned boff = (unsigned)(((kk + lrow) * BPAD + warp_n * 64 + p * 16 + lcol) * 2);
                unsigned bh[4], bl[4];
                ldsm_x4_t(bh, sBh + boff);
                ldsm_x4_t(bl, sBl + boff);
#pragma unroll
                for (int q = 0; q < 2; q++) {
                    float* cc = c[p * 2 + q];
                    mma_bf16(cc, ah, &bh[q * 2]);
                    mma_bf16(cc, ah, &bl[q * 2]);
                    mma_bf16(cc, al, &bh[q * 2]);
                }
            }
        }
    }
    __syncthreads();

    // epilogue: bias, per-row LN stats, normalize, relu, residual, write g_h (+ fused alpha)
#pragma unroll
    for (int nt = 0; nt < 8; nt++) {
        int col = warp_n * 64 + nt * 8 + t * 2;
        c[nt][0] += s_bg[col];
        c[nt][1] += s_bg[col + 1];
        c[nt][2] += s_bg[col];
        c[nt][3] += s_bg[col + 1];
    }
    float sum[2] = {0.f, 0.f}, sq[2] = {0.f, 0.f};
#pragma unroll
    for (int nt = 0; nt < 8; nt++) {
        float c0 = c[nt][0], c1 = c[nt][1], c2 = c[nt][2], c3 = c[nt][3];
        sum[0] += c0 + c1;  sq[0] += c0 * c0 + c1 * c1;
        sum[1] += c2 + c3;  sq[1] += c2 * c2 + c3 * c3;
    }
#pragma unroll
    for (int off = 1; off <= 2; off <<= 1)
#pragma unroll
        for (int i = 0; i < 2; i++) {
            sum[i] += __shfl_xor_sync(0xffffffffu, sum[i], off);
            sq[i]  += __shfl_xor_sync(0xffffffffu, sq[i],  off);
        }
    if (t == 0) {
#pragma unroll
        for (int hf = 0; hf < 2; hf++) {
            int row = warp_m * 16 + hf * 8 + g;
            rsum[warp_n][row] = sum[hf];
            rsq[warp_n][row]  = sq[hf];
        }
    }
    __syncthreads();

    float pa[2][4] = {{0.f,0.f,0.f,0.f},{0.f,0.f,0.f,0.f}};   // alpha_src partials per hf
    float pb[2][4] = {{0.f,0.f,0.f,0.f},{0.f,0.f,0.f,0.f}};   // alpha_dst partials per hf

#pragma unroll
    for (int hf = 0; hf < 2; hf++) {
        int row = warp_m * 16 + hf * 8 + g;
        int grow = m0 + row;
        if (grow >= NN) continue;
        float S = rsum[0][row] + rsum[1][row];
        float Q = rsq[0][row] + rsq[1][row];
        float mu  = S * (1.f / 128.f);
        float var = Q * (1.f / 128.f) - mu * mu;
        float rstd = rsqrtf(var + 1e-5f);
#pragma unroll
        for (int nt = 0; nt < 8; nt++) {
            int col = warp_n * 64 + nt * 8 + t * 2;
            float c0 = c[nt][hf * 2 + 0];
            float c1 = c[nt][hf * 2 + 1];
            float2 hold = *(const float2*)&g_h[grow * DH + col];
            float v0 = (c0 - mu) * rstd * s_lnw[col]     + s_lnb[col];
            float v1 = (c1 - mu) * rstd * s_lnw[col + 1] + s_lnb[col + 1];
            float nv0 = fmaxf(v0, 0.f) + hold.x;
            float nv1 = fmaxf(v1, 0.f) + hold.y;
            *(float2*)&g_h[grow * DH + col] = make_float2(nv0, nv1);
            if (do_alpha) {
#pragma unroll
                for (int h = 0; h < 4; h++) {
                    pa[hf][h] += nv0 * sv[h * 128 + col]       + nv1 * sv[h * 128 + col + 1];
                    pb[hf][h] += nv0 * sv[512 + h * 128 + col] + nv1 * sv[512 + h * 128 + col + 1];
                }
            }
        }
    }

    if (do_alpha) {
#pragma unroll
        for (int off = 1; off <= 2; off <<= 1)
#pragma unroll
            for (int hf = 0; hf < 2; hf++)
#pragma unroll
                for (int h = 0; h < 4; h++) {
                    pa[hf][h] += __shfl_xor_sync(0xffffffffu, pa[hf][h], off);
                    pb[hf][h] += __shfl_xor_sync(0xffffffffu, pb[hf][h], off);
                }
        if (t == 0) {
#pragma unroll
            for (int hf = 0; hf < 2; hf++) {
                int row = warp_m * 16 + hf * 8 + g;
#pragma unroll
                for (int h = 0; h < 4; h++) {
                    ared[warp_n][row][h]     = pa[hf][h];
                    ared[warp_n][row][4 + h] = pb[hf][h];
                }
            }
        }
        __syncthreads();
        for (int idx = tid; idx < 512; idx += 256) {
            int row = idx >> 3, o = idx & 7;
            int grow = m0 + row;
            if (grow < NN) {
                float s = ared[0][row][o] + ared[1][row][o];
                if (o < 4) g_as[grow * 4 + o] = s;
                else       g_ad[grow * 4 + (o - 4)] = s;
            }
        }
    }
}

// ---------------- pooling + TDA + trunk + task heads (fully fused) ----------------
__global__ __launch_bounds__(256) void k_head(const float* __restrict__ tda,
                                              const float* __restrict__ wt1, const float* __restrict__ bt1,
                                              const float* __restrict__ wt2, const float* __restrict__ bt2,
                                              const float* __restrict__ wsh1, const float* __restrict__ bsh1,
                                              const float* __restrict__ wsh2, const float* __restrict__ bsh2,
                                              const float* __restrict__ wh1,  const float* __restrict__ bh1,
                                              const float* __restrict__ wh2,  const float* __restrict__ bh2,
                                              float* __restrict__ out) {
    int g = blockIdx.x, tid = threadIdx.x;
    __shared__ float comb[320], s1[256], s2[128], hh1[NT * 64], th1[64];

    int beg = g_gstart[g], end = g_gstart[g + 1];
    int cntn = end - beg;
    {
        int d = tid & 127;
        if (tid < 128) {
            float s = 0.f;
            for (int i = beg; i < end; i++) s += g_h[i * DH + d];
            comb[d] = s / (float)(cntn > 0 ? cntn : 1);
        } else {
            float mx = -1e30f;
            for (int i = beg; i < end; i++) mx = fmaxf(mx, g_h[i * DH + d]);
            comb[128 + d] = (cntn > 0) ? mx : 0.f;
        }
    }
    __syncthreads();
    if (tid < 64) {
        float a = bt1[tid];
#pragma unroll
        for (int k = 0; k < FT; k++) a += tda[g * FT + k] * wt1[k * 64 + tid];
        th1[tid] = fmaxf(a, 0.f);
    }
    __syncthreads();
    if (tid < 64) {
        float c = bt2[tid];
#pragma unroll
        for (int k = 0; k < 64; k++) c += th1[k] * wt2[k * 64 + tid];
        comb[256 + tid] = fmaxf(c, 0.f);
    }
    __syncthreads();
    float a = bsh1[tid];
    for (int k = 0; k < 320; k++) a += comb[k] * wsh1[k * 256 + tid];
    s1[tid] = fmaxf(a, 0.f);
    __syncthreads();
    if (tid < 128) {
        float c = bsh2[tid];
        for (int k = 0; k < 256; k++) c += s1[k] * wsh2[k * 128 + tid];
        s2[tid] = fmaxf(c, 0.f);
    }
    __syncthreads();
    for (int idx = tid; idx < NT * 64; idx += 256) {
        int t = idx >> 6, kk = idx & 63;
        float c = bh1[t * 64 + kk];
        for (int k = 0; k < 128; k++) c += s2[k] * wh1[t * 8192 + k * 64 + kk];
        hh1[idx] = fmaxf(c, 0.f);
    }
    __syncthreads();
    if (tid < NT) {
        float c = bh2[tid];
        for (int k = 0; k < 64; k++) c += hh1[tid * 64 + k] * wh2[tid * 64 + k];
        out[tid * NGR + g] = c;
    }
}

// ---------------- launch ----------------
extern "C" void kernel_launch(void* const* d_in, const int* in_sizes, int n_in,
                              void* d_out, int out_size) {
    const float* x       = (const float*)d_in[0];
    const int*   ei      = (const int*)d_in[1];
    const int*   batch   = (const int*)d_in[2];
    const float* tda     = (const float*)d_in[3];
    const float* w_in    = (const float*)d_in[4];
    const float* b_in    = (const float*)d_in[5];
    const float* w_gat   = (const float*)d_in[6];
    const float* a_src   = (const float*)d_in[7];
    const float* a_dst   = (const float*)d_in[8];
    const float* b_gat   = (const float*)d_in[9];
    const float* ln_w    = (const float*)d_in[10];
    const float* ln_b    = (const float*)d_in[11];
    const float* w_tda1  = (const float*)d_in[12];
    const float* b_tda1  = (const float*)d_in[13];
    const float* w_tda2  = (const float*)d_in[14];
    const float* b_tda2  = (const float*)d_in[15];
    const float* w_sh1   = (const float*)d_in[16];
    const float* b_sh1   = (const float*)d_in[17];
    const float* w_sh2   = (const float*)d_in[18];
    const float* b_sh2   = (const float*)d_in[19];
    const float* w_h1    = (const float*)d_in[20];
    const float* b_h1    = (const float*)d_in[21];
    const float* w_h2    = (const float*)d_in[22];
    const float* b_h2    = (const float*)d_in[23];
    float* out = (float*)d_out;

    const int ROWS64_GRID = (NN + 63) / 64;   // 313

    k_pre<<<PRE_TOTAL_BLOCKS, 256>>>(w_gat, a_src, a_dst, batch);   // 0
    k_count<<<(ETOT + 255) / 256, 256>>>(ei);                        // 1
    k_scan<<<1, 1024>>>();                                           // 2
    k_inproj<<<NN / 8, 256>>>(x, w_in, b_in);                        // 3 (profiled)
    k_scatter<<<(ETOT + 255) / 256, 256>>>(ei);                      // 4

    for (int l = 0; l < NL; l++) {
        k_agg<<<NN / 4, 128>>>();
        k_gemm2<<<ROWS64_GRID, 256>>>(l, l + 1,
                                      b_gat + l * 128, ln_w + l * 128, ln_b + l * 128);
    }

    k_head<<<NGR, 256>>>(tda, w_tda1, b_tda1, w_tda2, b_tda2,
                         w_sh1, b_sh1, w_sh2, b_sh2, w_h1, b_h1, w_h2, b_h2, out);
}